// round 10
// baseline (speedup 1.0000x reference)
#include <cuda_runtime.h>
#include <cuda_bf16.h>
#include <math.h>
#include <stdint.h>

// Problem constants
#define DIMN     5120
#define NHEADS   40
#define HDIM     128
#define BATCH    2
#define SEQ      1024
#define TOKENS   (BATCH * SEQ)        // 2048
#define QKV_COLS (3 * DIMN)           // 15360
#define EPSV     1e-6f
#define SCALEV   0.08838834764831845f // 128^-0.5

// GEMM tiling: CTA 128x128, 16 warps of 32x32, BK=32, 2 stages, 2 CTAs/SM
#define GBM 128
#define GBN 128
#define GBK 32
#define AROW 40                               // (32+8) bf16 per row
#define AROWB (AROW * 2)                      // 80 bytes
#define A_PLANE (GBM * AROWB)                 // 10240 B
#define B_PLANE (GBN * AROWB)                 // 10240 B
#define STAGE_B (2 * A_PLANE + 2 * B_PLANE)   // 40960
#define GSMEM (2 * STAGE_B)                   // 81920 (2 CTAs/SM)
#define NCHUNK (DIMN / GBK)                   // 160

// Flash tiling: Br=128 (8 warps x m16), Bc=64, D=128, 2-stage cp.async K/V
#define FBR 128
#define FBC 64
#define FROWB 272
#define FQPL (FBR * FROWB)
#define FKPL (FBC * FROWB)
#define FSTG (4 * FKPL)
#define FSMEM (2 * FQPL + 2 * FSTG)           // 208896

// Scratch (no allocations allowed)
__device__ float          g_qkv[(size_t)TOKENS * QKV_COLS];
__device__ __nv_bfloat16  g_xhi[(size_t)TOKENS * DIMN];
__device__ __nv_bfloat16  g_xlo[(size_t)TOKENS * DIMN];
__device__ __nv_bfloat16  g_ahi[(size_t)TOKENS * DIMN];
__device__ __nv_bfloat16  g_alo[(size_t)TOKENS * DIMN];
__device__ __nv_bfloat16  g_wqhi[(size_t)QKV_COLS * DIMN];
__device__ __nv_bfloat16  g_wqlo[(size_t)QKV_COLS * DIMN];
__device__ __nv_bfloat16  g_wohi[(size_t)DIMN * DIMN];
__device__ __nv_bfloat16  g_wolo[(size_t)DIMN * DIMN];
__device__ __nv_bfloat16  g_qh[(size_t)TOKENS * DIMN];
__device__ __nv_bfloat16  g_ql[(size_t)TOKENS * DIMN];
__device__ __nv_bfloat16  g_kh[(size_t)TOKENS * DIMN];
__device__ __nv_bfloat16  g_kl[(size_t)TOKENS * DIMN];
__device__ __nv_bfloat16  g_vh[(size_t)TOKENS * DIMN];
__device__ __nv_bfloat16  g_vl[(size_t)TOKENS * DIMN];

// ---------------------------------------------------------------------------
__device__ __forceinline__ uint32_t smem_u32(const void* p) {
    uint32_t a;
    asm("{ .reg .u64 t; cvta.to.shared.u64 t, %1; cvt.u32.u64 %0, t; }" : "=r"(a) : "l"(p));
    return a;
}
__device__ __forceinline__ void cp16(uint32_t s, const void* g) {
    asm volatile("cp.async.cg.shared.global [%0], [%1], 16;" :: "r"(s), "l"(g));
}
__device__ __forceinline__ void cp_commit() {
    asm volatile("cp.async.commit_group;" ::: "memory");
}
__device__ __forceinline__ void cp_wait1() {
    asm volatile("cp.async.wait_group 1;" ::: "memory");
}
__device__ __forceinline__ void cp_wait0() {
    asm volatile("cp.async.wait_group 0;" ::: "memory");
}
__device__ __forceinline__ void mma_bf16(float* c, const uint32_t* a, const uint32_t* b) {
    asm volatile("mma.sync.aligned.m16n8k16.row.col.f32.bf16.bf16.f32 "
        "{%0,%1,%2,%3}, {%4,%5,%6,%7}, {%8,%9}, {%0,%1,%2,%3};"
        : "+f"(c[0]), "+f"(c[1]), "+f"(c[2]), "+f"(c[3])
        : "r"(a[0]), "r"(a[1]), "r"(a[2]), "r"(a[3]), "r"(b[0]), "r"(b[1]));
}
__device__ __forceinline__ void ldsm_x4(uint32_t* r, uint32_t a) {
    asm volatile("ldmatrix.sync.aligned.m8n8.x4.shared.b16 {%0,%1,%2,%3}, [%4];"
        : "=r"(r[0]), "=r"(r[1]), "=r"(r[2]), "=r"(r[3]) : "r"(a));
}
__device__ __forceinline__ void ldsm_x2(uint32_t* r, uint32_t a) {
    asm volatile("ldmatrix.sync.aligned.m8n8.x2.shared.b16 {%0,%1}, [%2];"
        : "=r"(r[0]), "=r"(r[1]) : "r"(a));
}
__device__ __forceinline__ void ldsm_x2t(uint32_t* r, uint32_t a) {
    asm volatile("ldmatrix.sync.aligned.m8n8.x2.trans.shared.b16 {%0,%1}, [%2];"
        : "=r"(r[0]), "=r"(r[1]) : "r"(a));
}
__device__ __forceinline__ void bsplit2(float x, float y, uint32_t& hi, uint32_t& lo) {
    __nv_bfloat16 hx = __float2bfloat16_rn(x), hy = __float2bfloat16_rn(y);
    __nv_bfloat16 lx = __float2bfloat16_rn(x - __bfloat162float(hx));
    __nv_bfloat16 ly = __float2bfloat16_rn(y - __bfloat162float(hy));
    hi = ((uint32_t)__bfloat16_as_ushort(hy) << 16) | __bfloat16_as_ushort(hx);
    lo = ((uint32_t)__bfloat16_as_ushort(ly) << 16) | __bfloat16_as_ushort(lx);
}

// ---------------------------------------------------------------------------
// GEMM: C[M, Ntot] = A @ B^T + bias, 3-pass split bf16 (hh + hl + lh).
// 512 threads, warptile 32x32, register double-buffered fragments,
// ONE __syncthreads per chunk. 2 CTAs/SM.
// ---------------------------------------------------------------------------
struct Frag {
    uint32_t ah[2][4], al[2][4];
    uint32_t bh[4][2], bl[4][2];
};

__global__ __launch_bounds__(512, 2) void gemm_bf16x3(
    const __nv_bfloat16* __restrict__ Ahi, const __nv_bfloat16* __restrict__ Alo,
    const __nv_bfloat16* __restrict__ Bhi, const __nv_bfloat16* __restrict__ Blo,
    const float* __restrict__ bias, float* __restrict__ C, int Ntot)
{
    extern __shared__ char gsm[];
    const uint32_t sbase = smem_u32(gsm);
    const int tid = threadIdx.x;
    const int m0  = blockIdx.x * GBM;
    const int n0  = blockIdx.y * GBN;
    const int K   = DIMN;

    const int wid  = tid >> 5, lane = tid & 31;
    const int wm   = wid & 3;        // 4 groups of 32 rows
    const int wn   = wid >> 2;       // 4 groups of 32 cols
    const int gid  = lane >> 2;
    const int tig  = lane & 3;
    const int l15  = lane & 15;

    const uint32_t a_row  = (uint32_t)(wm * 32 + l15);
    const uint32_t a_colh = (uint32_t)((lane >> 4) << 4);
    const uint32_t b_row  = (uint32_t)(wn * 32 + (lane & 7));
    const uint32_t b_colh = (uint32_t)(((lane >> 3) & 1) << 4);

    float acc[2][4][4];
#pragma unroll
    for (int a = 0; a < 2; ++a)
#pragma unroll
        for (int b = 0; b < 4; ++b)
#pragma unroll
            for (int c = 0; c < 4; ++c) acc[a][b][c] = 0.0f;

    auto issue = [&](int s, int k0) {
        const uint32_t st = sbase + s * STAGE_B;
#pragma unroll
        for (int i = 0; i < 2; ++i) {
            const int idx = tid + 512 * i;        // 0..1023
            const int p   = idx >> 9;
            const int r   = (idx >> 2) & 127;
            const int ch  = idx & 3;
            const __nv_bfloat16* src = (p ? Alo : Ahi) + (size_t)(m0 + r) * K + k0 + ch * 8;
            cp16(st + p * A_PLANE + r * AROWB + ch * 16, src);
        }
#pragma unroll
        for (int i = 0; i < 2; ++i) {
            const int idx = tid + 512 * i;
            const int p   = idx >> 9;
            const int r   = (idx >> 2) & 127;
            const int ch  = idx & 3;
            const __nv_bfloat16* src = (p ? Blo : Bhi) + (size_t)(n0 + r) * K + k0 + ch * 8;
            cp16(st + 2 * A_PLANE + p * B_PLANE + r * AROWB + ch * 16, src);
        }
        cp_commit();
    };

    auto loadfrag = [&](Frag& F, uint32_t ss, uint32_t kofs) {
#pragma unroll
        for (int mt = 0; mt < 2; ++mt) {
            const uint32_t aaddr = ss + (a_row + mt * 16) * AROWB + kofs + a_colh;
            ldsm_x4(F.ah[mt], aaddr);
            ldsm_x4(F.al[mt], aaddr + A_PLANE);
        }
#pragma unroll
        for (int nt = 0; nt < 4; ++nt) {
            const uint32_t baddr =
                ss + 2 * A_PLANE + (b_row + nt * 8) * AROWB + kofs + b_colh;
            ldsm_x2(F.bh[nt], baddr);
            ldsm_x2(F.bl[nt], baddr + B_PLANE);
        }
    };

    auto runmma = [&](const Frag& F) {
        // pass-major: consecutive MMAs hit different accumulators
#pragma unroll
        for (int mt = 0; mt < 2; ++mt)
#pragma unroll
            for (int nt = 0; nt < 4; ++nt)
                mma_bf16(acc[mt][nt], F.ah[mt], F.bh[nt]);
#pragma unroll
        for (int mt = 0; mt < 2; ++mt)
#pragma unroll
            for (int nt = 0; nt < 4; ++nt)
                mma_bf16(acc[mt][nt], F.ah[mt], F.bl[nt]);
#pragma unroll
        for (int mt = 0; mt < 2; ++mt)
#pragma unroll
            for (int nt = 0; nt < 4; ++nt)
                mma_bf16(acc[mt][nt], F.al[mt], F.bh[nt]);
    };

    issue(0, 0);
    issue(1, GBK);
    cp_wait1();          // chunk 0 resident
    __syncthreads();

    Frag F0, F1;
    loadfrag(F0, sbase, 0);

#pragma unroll 2
    for (int it = 0; it < NCHUNK; ++it) {
        const int s = it & 1;
        const uint32_t ss = sbase + s * STAGE_B;

        loadfrag(F1, ss, 32);          // ks=1 of current chunk
        runmma(F0);                    // ks=0 MMAs (overlap F1 loads)
        __syncthreads();               // all warps done reading stage s

        if (it + 2 < NCHUNK) {
            issue(s, (it + 2) * GBK);  // refill stage s
            cp_wait1();                // chunk it+1 resident
        } else if (it + 1 < NCHUNK) {
            cp_wait0();                // last refill already issued; drain
        }
        if (it + 1 < NCHUNK)
            loadfrag(F0, sbase + ((it + 1) & 1) * STAGE_B, 0);  // next ks=0
        runmma(F1);                    // ks=1 MMAs (overlap F0 loads)
    }

#pragma unroll
    for (int mt = 0; mt < 2; ++mt) {
#pragma unroll
        for (int nt = 0; nt < 4; ++nt) {
            const int row = m0 + wm * 32 + mt * 16 + gid;
            const int col = n0 + wn * 32 + nt * 8 + tig * 2;
            const float b0 = bias[col], b1 = bias[col + 1];
            float2 v0 = {acc[mt][nt][0] + b0, acc[mt][nt][1] + b1};
            float2 v1 = {acc[mt][nt][2] + b0, acc[mt][nt][3] + b1};
            *(float2*)(C + (size_t)row * Ntot + col)       = v0;
            *(float2*)(C + (size_t)(row + 8) * Ntot + col) = v1;
        }
    }
}

// ---------------------------------------------------------------------------
__global__ __launch_bounds__(256) void split_bf16(
    const float4* __restrict__ in, uint2* __restrict__ hi, uint2* __restrict__ lo, int n4)
{
    const int i = blockIdx.x * 256 + threadIdx.x;
    if (i >= n4) return;
    float4 v = in[i];
    uint32_t H0, L0, H1, L1;
    bsplit2(v.x, v.y, H0, L0);
    bsplit2(v.z, v.w, H1, L1);
    hi[i] = make_uint2(H0, H1);
    lo[i] = make_uint2(L0, L1);
}

__global__ __launch_bounds__(256) void transpose_split(
    const float* __restrict__ W,
    __nv_bfloat16* __restrict__ Whi, __nv_bfloat16* __restrict__ Wlo, int K, int N)
{
    __shared__ float t[32][33];
    const int n0 = blockIdx.x * 32, k0 = blockIdx.y * 32;
    const int tx = threadIdx.x, ty = threadIdx.y;
#pragma unroll
    for (int i = 0; i < 32; i += 8)
        t[ty + i][tx] = W[(size_t)(k0 + ty + i) * N + n0 + tx];
    __syncthreads();
#pragma unroll
    for (int i = 0; i < 32; i += 8) {
        float x = t[tx][ty + i];
        __nv_bfloat16 h = __float2bfloat16_rn(x);
        __nv_bfloat16 l = __float2bfloat16_rn(x - __bfloat162float(h));
        const size_t idx = (size_t)(n0 + ty + i) * K + k0 + tx;
        Whi[idx] = h;
        Wlo[idx] = l;
    }
}

// ---------------------------------------------------------------------------
// RMSNorm + rotary; emits split-bf16 q (pre-scaled), k, and v planes.
// ---------------------------------------------------------------------------
__global__ __launch_bounds__(256) void rms_rope_split(
    const float* __restrict__ qkv,
    const float* __restrict__ gq, const float* __restrict__ gk,
    const float* __restrict__ fcos, const float* __restrict__ fsin,
    __nv_bfloat16* __restrict__ qh, __nv_bfloat16* __restrict__ ql,
    __nv_bfloat16* __restrict__ kh, __nv_bfloat16* __restrict__ kl,
    __nv_bfloat16* __restrict__ vh, __nv_bfloat16* __restrict__ vl)
{
    const int t   = blockIdx.x;
    const int l   = t & (SEQ - 1);
    const int tid = threadIdx.x;

    const float* qrow = qkv + (size_t)t * QKV_COLS;
    const float* krow = qrow + DIMN;
    const float* vrow = qrow + 2 * DIMN;

    float sq = 0.0f, sk = 0.0f;
    for (int i = tid; i < DIMN; i += 256) {
        float a = qrow[i]; sq = fmaf(a, a, sq);
        float b = krow[i]; sk = fmaf(b, b, sk);
    }
#pragma unroll
    for (int off = 16; off; off >>= 1) {
        sq += __shfl_xor_sync(0xffffffffu, sq, off);
        sk += __shfl_xor_sync(0xffffffffu, sk, off);
    }
    __shared__ float redq[8], redk[8];
    __shared__ float bq, bk;
    const int warp = tid >> 5, lane = tid & 31;
    if (lane == 0) { redq[warp] = sq; redk[warp] = sk; }
    __syncthreads();
    if (tid == 0) {
        float a = 0.0f, b = 0.0f;
#pragma unroll
        for (int w = 0; w < 8; ++w) { a += redq[w]; b += redk[w]; }
        bq = a; bk = b;
    }
    __syncthreads();
    const float rq = rsqrtf(bq * (1.0f / DIMN) + EPSV);
    const float rk = rsqrtf(bk * (1.0f / DIMN) + EPSV);

    const size_t ob = (size_t)t * DIMN;
    for (int p = tid; p < DIMN / 2; p += 256) {
        const int head = p >> 6;
        const int i2   = (p & 63) * 2;
        const int ce   = head * HDIM + i2;
        const int co   = ce + 1;
        const float ccos = fcos[l * HDIM + i2];
        const float csin = fsin[l * HDIM + i2 + 1];

        float xe = qrow[ce] * rq * gq[ce];
        float xo = qrow[co] * rq * gq[co];
        float qe = (xe * ccos - xo * csin) * SCALEV;
        float qo = (xe * csin + xo * ccos) * SCALEV;
        uint32_t H, L;
        bsplit2(qe, qo, H, L);
        *(uint32_t*)(qh + ob + ce) = H;
        *(uint32_t*)(ql + ob + ce) = L;

        xe = krow[ce] * rk * gk[ce];
        xo = krow[co] * rk * gk[co];
        float ke = xe * ccos - xo * csin;
        float ko = xe * csin + xo * ccos;
        bsplit2(ke, ko, H, L);
        *(uint32_t*)(kh + ob + ce) = H;
        *(uint32_t*)(kl + ob + ce) = L;

        float v0 = vrow[ce], v1 = vrow[co];
        bsplit2(v0, v1, H, L);
        *(uint32_t*)(vh + ob + ce) = H;
        *(uint32_t*)(vl + ob + ce) = L;
    }
}

// ---------------------------------------------------------------------------
// Tensor-core flash attention. Br=128, Bc=64, D=128.
// ---------------------------------------------------------------------------
__global__ __launch_bounds__(256, 1) void flash_mma(
    const __nv_bfloat16* __restrict__ qhp, const __nv_bfloat16* __restrict__ qlp,
    const __nv_bfloat16* __restrict__ khp, const __nv_bfloat16* __restrict__ klp,
    const __nv_bfloat16* __restrict__ vhp, const __nv_bfloat16* __restrict__ vlp,
    __nv_bfloat16* __restrict__ ohi, __nv_bfloat16* __restrict__ olo)
{
    extern __shared__ char fsm[];
    const uint32_t sb = smem_u32(fsm);

    const int qb = blockIdx.x, bh = blockIdx.y;
    const int b  = bh / NHEADS, h = bh % NHEADS;
    const int tid = threadIdx.x, wid = tid >> 5, lane = tid & 31;
    const int gid = lane >> 2, tig = lane & 3;
    const int l15 = lane & 15;
    const int hofs = h * HDIM;
    const size_t qrow0 = (size_t)(b * SEQ + qb * FBR);
    const size_t krow0 = (size_t)(b * SEQ);

    for (int i = 0; i < 16; ++i) {
        const int idx = tid + 256 * i;
        const int pl  = idx >> 11;
        const int r   = (idx >> 4) & 127;
        const int c   = idx & 15;
        const __nv_bfloat16* src = (pl ? qlp : qhp) + (qrow0 + r) * DIMN + hofs + c * 8;
        cp16(sb + pl * FQPL + r * FROWB + c * 16, src);
    }
    auto loadkv = [&](int s, int kb) {
        const uint32_t st = sb + 2 * FQPL + s * FSTG;
        const size_t kr = krow0 + (size_t)kb * FBC;
        for (int i = 0; i < 16; ++i) {
            const int idx = tid + 256 * i;
            const int pl  = idx >> 10;
            const int r   = (idx >> 4) & 63;
            const int c   = idx & 15;
            const __nv_bfloat16* base = (pl == 0) ? khp : (pl == 1) ? klp
                                      : (pl == 2) ? vhp : vlp;
            cp16(st + pl * FKPL + r * FROWB + c * 16, base + (kr + r) * DIMN + hofs + c * 8);
        }
        cp_commit();
    };
    loadkv(0, 0);
    loadkv(1, 1);

    float oacc[16][4];
#pragma unroll
    for (int d = 0; d < 16; ++d)
#pragma unroll
        for (int c = 0; c < 4; ++c) oacc[d][c] = 0.0f;
    float mrow[2] = {-1e30f, -1e30f};
    float lrow[2] = {0.0f, 0.0f};

    const int qrow = wid * 16 + l15;
    const uint32_t qcol = ((lane >> 4) & 1) * 16;
    const int krw  = l15 & 7;
    const uint32_t kcadd = ((l15 >> 3) & 1) * 16;

    for (int kb = 0; kb < SEQ / FBC; ++kb) {
        cp_wait1();
        __syncthreads();
        const uint32_t st = sb + 2 * FQPL + (kb & 1) * FSTG;
        const uint32_t kh = st, kl = st + FKPL, vh = st + 2 * FKPL, vl = st + 3 * FKPL;

        float sacc[8][4];
#pragma unroll
        for (int nt = 0; nt < 8; ++nt)
#pragma unroll
            for (int c = 0; c < 4; ++c) sacc[nt][c] = 0.0f;

#pragma unroll
        for (int kc = 0; kc < 8; ++kc) {
            uint32_t aqh[4], aql[4];
            ldsm_x4(aqh, sb + qrow * FROWB + kc * 32 + qcol);
            ldsm_x4(aql, sb + FQPL + qrow * FROWB + kc * 32 + qcol);
            const uint32_t kcol = kc * 32 + kcadd;
#pragma unroll
            for (int nt = 0; nt < 8; ++nt) {
                uint32_t bkh[2], bkl[2];
                ldsm_x2(bkh, kh + (nt * 8 + krw) * FROWB + kcol);
                ldsm_x2(bkl, kl + (nt * 8 + krw) * FROWB + kcol);
                mma_bf16(sacc[nt], aqh, bkh);
                mma_bf16(sacc[nt], aqh, bkl);
                mma_bf16(sacc[nt], aql, bkh);
            }
        }

        float mx0 = sacc[0][0], mx1 = sacc[0][2];
#pragma unroll
        for (int nt = 0; nt < 8; ++nt) {
            mx0 = fmaxf(mx0, fmaxf(sacc[nt][0], sacc[nt][1]));
            mx1 = fmaxf(mx1, fmaxf(sacc[nt][2], sacc[nt][3]));
        }
        mx0 = fmaxf(mx0, __shfl_xor_sync(0xffffffffu, mx0, 1));
        mx0 = fmaxf(mx0, __shfl_xor_sync(0xffffffffu, mx0, 2));
        mx1 = fmaxf(mx1, __shfl_xor_sync(0xffffffffu, mx1, 1));
        mx1 = fmaxf(mx1, __shfl_xor_sync(0xffffffffu, mx1, 2));
        const float mn0 = fmaxf(mrow[0], mx0);
        const float mn1 = fmaxf(mrow[1], mx1);
        const float al0 = __expf(mrow[0] - mn0);
        const float al1 = __expf(mrow[1] - mn1);
        mrow[0] = mn0; mrow[1] = mn1;

        float rs0 = 0.0f, rs1 = 0.0f;
#pragma unroll
        for (int nt = 0; nt < 8; ++nt) {
            sacc[nt][0] = __expf(sacc[nt][0] - mn0);
            sacc[nt][1] = __expf(sacc[nt][1] - mn0);
            sacc[nt][2] = __expf(sacc[nt][2] - mn1);
            sacc[nt][3] = __expf(sacc[nt][3] - mn1);
            rs0 += sacc[nt][0] + sacc[nt][1];
            rs1 += sacc[nt][2] + sacc[nt][3];
        }
        rs0 += __shfl_xor_sync(0xffffffffu, rs0, 1);
        rs0 += __shfl_xor_sync(0xffffffffu, rs0, 2);
        rs1 += __shfl_xor_sync(0xffffffffu, rs1, 1);
        rs1 += __shfl_xor_sync(0xffffffffu, rs1, 2);
        lrow[0] = lrow[0] * al0 + rs0;
        lrow[1] = lrow[1] * al1 + rs1;
#pragma unroll
        for (int d = 0; d < 16; ++d) {
            oacc[d][0] *= al0; oacc[d][1] *= al0;
            oacc[d][2] *= al1; oacc[d][3] *= al1;
        }

#pragma unroll
        for (int kc2 = 0; kc2 < 4; ++kc2) {
            uint32_t aph[4], apl[4];
            bsplit2(sacc[2 * kc2][0],     sacc[2 * kc2][1],     aph[0], apl[0]);
            bsplit2(sacc[2 * kc2][2],     sacc[2 * kc2][3],     aph[1], apl[1]);
            bsplit2(sacc[2 * kc2 + 1][0], sacc[2 * kc2 + 1][1], aph[2], apl[2]);
            bsplit2(sacc[2 * kc2 + 1][2], sacc[2 * kc2 + 1][3], aph[3], apl[3]);
            const uint32_t vr = (kc2 * 16 + l15) * FROWB;
#pragma unroll
            for (int dt = 0; dt < 16; ++dt) {
                uint32_t bvh[2], bvl[2];
                ldsm_x2t(bvh, vh + vr + dt * 16);
                ldsm_x2t(bvl, vl + vr + dt * 16);
                mma_bf16(oacc[dt], aph, bvh);
                mma_bf16(oacc[dt], aph, bvl);
                mma_bf16(oacc[dt], apl, bvh);
            }
        }
        __syncthreads();
        if (kb + 2 < SEQ / FBC) loadkv(kb & 1, kb + 2);
    }

#pragma unroll
    for (int i = 0; i < 2; ++i) {
        const float inv = 1.0f / lrow[i];
        const size_t base =
            (qrow0 + (size_t)(wid * 16 + gid + i * 8)) * DIMN + hofs + tig * 2;
#pragma unroll
        for (int dt = 0; dt < 16; ++dt) {
            uint32_t H, L;
            bsplit2(oacc[dt][2 * i] * inv, oacc[dt][2 * i + 1] * inv, H, L);
            *(uint32_t*)(ohi + base + dt * 8) = H;
            *(uint32_t*)(olo + base + dt * 8) = L;
        }
    }
}

// ---------------------------------------------------------------------------
extern "C" void kernel_launch(void* const* d_in, const int* in_sizes, int n_in,
                              void* d_out, int out_size)
{
    const float* X    = (const float*)d_in[0];
    const float* fcos = (const float*)d_in[1];
    const float* fsin = (const float*)d_in[2];
    const float* Wqkv = (const float*)d_in[3];
    const float* bqkv = (const float*)d_in[4];
    const float* gq   = (const float*)d_in[5];
    const float* gk   = (const float*)d_in[6];
    const float* Wout = (const float*)d_in[7];
    const float* bout = (const float*)d_in[8];
    float* out = (float*)d_out;

    float *qkvbuf;
    __nv_bfloat16 *xhi, *xlo, *ahi, *alo, *wqhi, *wqlo, *wohi, *wolo;
    __nv_bfloat16 *qh, *ql, *kh, *kl, *vh, *vl;
    cudaGetSymbolAddress((void**)&qkvbuf, g_qkv);
    cudaGetSymbolAddress((void**)&xhi, g_xhi);
    cudaGetSymbolAddress((void**)&xlo, g_xlo);
    cudaGetSymbolAddress((void**)&ahi, g_ahi);
    cudaGetSymbolAddress((void**)&alo, g_alo);
    cudaGetSymbolAddress((void**)&wqhi, g_wqhi);
    cudaGetSymbolAddress((void**)&wqlo, g_wqlo);
    cudaGetSymbolAddress((void**)&wohi, g_wohi);
    cudaGetSymbolAddress((void**)&wolo, g_wolo);
    cudaGetSymbolAddress((void**)&qh, g_qh);
    cudaGetSymbolAddress((void**)&ql, g_ql);
    cudaGetSymbolAddress((void**)&kh, g_kh);
    cudaGetSymbolAddress((void**)&kl, g_kl);
    cudaGetSymbolAddress((void**)&vh, g_vh);
    cudaGetSymbolAddress((void**)&vl, g_vl);

    cudaFuncSetAttribute(gemm_bf16x3, cudaFuncAttributeMaxDynamicSharedMemorySize, GSMEM);
    cudaFuncSetAttribute(flash_mma, cudaFuncAttributeMaxDynamicSharedMemorySize, FSMEM);

    // 0) precision-split operands
    split_bf16<<<(TOKENS * DIMN / 4 + 255) / 256, 256>>>(
        (const float4*)X, (uint2*)xhi, (uint2*)xlo, TOKENS * DIMN / 4);
    transpose_split<<<dim3(QKV_COLS / 32, DIMN / 32), dim3(32, 8)>>>(
        Wqkv, wqhi, wqlo, DIMN, QKV_COLS);
    transpose_split<<<dim3(DIMN / 32, DIMN / 32), dim3(32, 8)>>>(
        Wout, wohi, wolo, DIMN, DIMN);

    // 1) qkv = X @ W_qkv + b_qkv
    gemm_bf16x3<<<dim3(TOKENS / GBM, QKV_COLS / GBN), 512, GSMEM>>>(
        xhi, xlo, wqhi, wqlo, bqkv, qkvbuf, QKV_COLS);

    // 2) RMSNorm + RoPE -> split planes
    rms_rope_split<<<TOKENS, 256>>>(qkvbuf, gq, gk, fcos, fsin,
                                    qh, ql, kh, kl, vh, vl);

    // 3) tensor-core flash attention -> bf16 hi/lo planes
    flash_mma<<<dim3(SEQ / FBR, BATCH * NHEADS), 256, FSMEM>>>(
        qh, ql, kh, kl, vh, vl, ahi, alo);

    // 4) out = attn @ W_out + b_out
    gemm_bf16x3<<<dim3(TOKENS / GBM, DIMN / GBN), 512, GSMEM>>>(
        ahi, alo, wohi, wolo, bout, out, DIMN);
}

// round 11
// speedup vs baseline: 3.0805x; 3.0805x over previous
#include <cuda_runtime.h>
#include <cuda_bf16.h>
#include <math.h>
#include <stdint.h>

// Problem constants
#define DIMN     5120
#define NHEADS   40
#define HDIM     128
#define BATCH    2
#define SEQ      1024
#define TOKENS   (BATCH * SEQ)        // 2048
#define QKV_COLS (3 * DIMN)           // 15360
#define EPSV     1e-6f
#define SCALEV   0.08838834764831845f // 128^-0.5

// GEMM tiling: CTA 64x128, 8 warps of 32x32, BK=32, 2 stages, 2 CTAs/SM
#define GBM 64
#define GBN 128
#define GBK 32
#define AROW 40                               // (32+8) bf16 per row
#define AROWB (AROW * 2)                      // 80 bytes
#define A_PLANE (GBM * AROWB)                 // 5120 B
#define B_PLANE (GBN * AROWB)                 // 10240 B
#define STAGE_B (2 * A_PLANE + 2 * B_PLANE)   // 30720
#define GSMEM (2 * STAGE_B)                   // 61440 (2 CTAs/SM easily)
#define NCHUNK (DIMN / GBK)                   // 160

// Flash tiling: Br=128 (8 warps x m16), Bc=64, D=128, 2-stage cp.async K/V
#define FBR 128
#define FBC 64
#define FROWB 272
#define FQPL (FBR * FROWB)
#define FKPL (FBC * FROWB)
#define FSTG (4 * FKPL)
#define FSMEM (2 * FQPL + 2 * FSTG)           // 208896

// Scratch (no allocations allowed)
__device__ float          g_qkv[(size_t)TOKENS * QKV_COLS];
__device__ __nv_bfloat16  g_xhi[(size_t)TOKENS * DIMN];
__device__ __nv_bfloat16  g_xlo[(size_t)TOKENS * DIMN];
__device__ __nv_bfloat16  g_ahi[(size_t)TOKENS * DIMN];
__device__ __nv_bfloat16  g_alo[(size_t)TOKENS * DIMN];
__device__ __nv_bfloat16  g_wqhi[(size_t)QKV_COLS * DIMN];
__device__ __nv_bfloat16  g_wqlo[(size_t)QKV_COLS * DIMN];
__device__ __nv_bfloat16  g_wohi[(size_t)DIMN * DIMN];
__device__ __nv_bfloat16  g_wolo[(size_t)DIMN * DIMN];
__device__ __nv_bfloat16  g_qh[(size_t)TOKENS * DIMN];
__device__ __nv_bfloat16  g_ql[(size_t)TOKENS * DIMN];
__device__ __nv_bfloat16  g_kh[(size_t)TOKENS * DIMN];
__device__ __nv_bfloat16  g_kl[(size_t)TOKENS * DIMN];
__device__ __nv_bfloat16  g_vh[(size_t)TOKENS * DIMN];
__device__ __nv_bfloat16  g_vl[(size_t)TOKENS * DIMN];

// ---------------------------------------------------------------------------
__device__ __forceinline__ uint32_t smem_u32(const void* p) {
    uint32_t a;
    asm("{ .reg .u64 t; cvta.to.shared.u64 t, %1; cvt.u32.u64 %0, t; }" : "=r"(a) : "l"(p));
    return a;
}
__device__ __forceinline__ void cp16(uint32_t s, const void* g) {
    asm volatile("cp.async.cg.shared.global [%0], [%1], 16;" :: "r"(s), "l"(g));
}
__device__ __forceinline__ void cp_commit() {
    asm volatile("cp.async.commit_group;" ::: "memory");
}
__device__ __forceinline__ void cp_wait1() {
    asm volatile("cp.async.wait_group 1;" ::: "memory");
}
__device__ __forceinline__ void cp_wait0() {
    asm volatile("cp.async.wait_group 0;" ::: "memory");
}
__device__ __forceinline__ void mma_bf16(float* c, const uint32_t* a, const uint32_t* b) {
    asm volatile("mma.sync.aligned.m16n8k16.row.col.f32.bf16.bf16.f32 "
        "{%0,%1,%2,%3}, {%4,%5,%6,%7}, {%8,%9}, {%0,%1,%2,%3};"
        : "+f"(c[0]), "+f"(c[1]), "+f"(c[2]), "+f"(c[3])
        : "r"(a[0]), "r"(a[1]), "r"(a[2]), "r"(a[3]), "r"(b[0]), "r"(b[1]));
}
__device__ __forceinline__ void ldsm_x4(uint32_t* r, uint32_t a) {
    asm volatile("ldmatrix.sync.aligned.m8n8.x4.shared.b16 {%0,%1,%2,%3}, [%4];"
        : "=r"(r[0]), "=r"(r[1]), "=r"(r[2]), "=r"(r[3]) : "r"(a));
}
__device__ __forceinline__ void ldsm_x2(uint32_t* r, uint32_t a) {
    asm volatile("ldmatrix.sync.aligned.m8n8.x2.shared.b16 {%0,%1}, [%2];"
        : "=r"(r[0]), "=r"(r[1]) : "r"(a));
}
__device__ __forceinline__ void ldsm_x2t(uint32_t* r, uint32_t a) {
    asm volatile("ldmatrix.sync.aligned.m8n8.x2.trans.shared.b16 {%0,%1}, [%2];"
        : "=r"(r[0]), "=r"(r[1]) : "r"(a));
}
__device__ __forceinline__ void bsplit2(float x, float y, uint32_t& hi, uint32_t& lo) {
    __nv_bfloat16 hx = __float2bfloat16_rn(x), hy = __float2bfloat16_rn(y);
    __nv_bfloat16 lx = __float2bfloat16_rn(x - __bfloat162float(hx));
    __nv_bfloat16 ly = __float2bfloat16_rn(y - __bfloat162float(hy));
    hi = ((uint32_t)__bfloat16_as_ushort(hy) << 16) | __bfloat16_as_ushort(hx);
    lo = ((uint32_t)__bfloat16_as_ushort(ly) << 16) | __bfloat16_as_ushort(lx);
}

// ---------------------------------------------------------------------------
// GEMM: C[M, Ntot] = A @ B^T + bias, 3-pass split bf16 (hh + hl + lh).
// CTA 64x128, warptile 32x32, register double-buffered fragments, 2 CTAs/SM.
// ---------------------------------------------------------------------------
struct Frag {
    uint32_t ah[2][4], al[2][4];   // A hi/lo fragments (2 m-tiles)
    uint32_t bh[4][2], bl[4][2];   // B hi/lo fragments (4 n-tiles)
};

__global__ __launch_bounds__(256, 2) void gemm_bf16x3(
    const __nv_bfloat16* __restrict__ Ahi, const __nv_bfloat16* __restrict__ Alo,
    const __nv_bfloat16* __restrict__ Bhi, const __nv_bfloat16* __restrict__ Blo,
    const float* __restrict__ bias, float* __restrict__ C, int Ntot)
{
    extern __shared__ char gsm[];
    const uint32_t sbase = smem_u32(gsm);
    const int tid = threadIdx.x;
    const int m0  = blockIdx.x * GBM;
    const int n0  = blockIdx.y * GBN;
    const int K   = DIMN;

    const int wid  = tid >> 5, lane = tid & 31;
    const int wm   = wid & 1;        // 2 groups of 32 rows
    const int wn   = wid >> 1;       // 4 groups of 32 cols
    const int gid  = lane >> 2;
    const int tig  = lane & 3;
    const int l15  = lane & 15;

    const uint32_t a_row  = (uint32_t)(wm * 32 + l15);
    const uint32_t a_colh = (uint32_t)((lane >> 4) << 4);
    const uint32_t b_row  = (uint32_t)(wn * 32 + (lane & 7));
    const uint32_t b_colh = (uint32_t)(((lane >> 3) & 1) << 4);

    float acc[2][4][4];
#pragma unroll
    for (int a = 0; a < 2; ++a)
#pragma unroll
        for (int b = 0; b < 4; ++b)
#pragma unroll
            for (int c = 0; c < 4; ++c) acc[a][b][c] = 0.0f;

    auto issue = [&](int s, int k0) {
        const uint32_t st = sbase + s * STAGE_B;
        // A: 2 planes x 256 chunks = 512
#pragma unroll
        for (int i = 0; i < 2; ++i) {
            const int idx = tid + 256 * i;        // 0..511
            const int p   = idx >> 8;
            const int r   = (idx >> 2) & 63;
            const int ch  = idx & 3;
            const __nv_bfloat16* src = (p ? Alo : Ahi) + (size_t)(m0 + r) * K + k0 + ch * 8;
            cp16(st + p * A_PLANE + r * AROWB + ch * 16, src);
        }
        // B: 2 planes x 512 chunks = 1024
#pragma unroll
        for (int i = 0; i < 4; ++i) {
            const int idx = tid + 256 * i;        // 0..1023
            const int p   = idx >> 9;
            const int r   = (idx >> 2) & 127;
            const int ch  = idx & 3;
            const __nv_bfloat16* src = (p ? Blo : Bhi) + (size_t)(n0 + r) * K + k0 + ch * 8;
            cp16(st + 2 * A_PLANE + p * B_PLANE + r * AROWB + ch * 16, src);
        }
        cp_commit();
    };

    auto loadfrag = [&](Frag& F, uint32_t ss, uint32_t kofs) {
#pragma unroll
        for (int mt = 0; mt < 2; ++mt) {
            const uint32_t aaddr = ss + (a_row + mt * 16) * AROWB + kofs + a_colh;
            ldsm_x4(F.ah[mt], aaddr);
            ldsm_x4(F.al[mt], aaddr + A_PLANE);
        }
#pragma unroll
        for (int nt = 0; nt < 4; ++nt) {
            const uint32_t baddr =
                ss + 2 * A_PLANE + (b_row + nt * 8) * AROWB + kofs + b_colh;
            ldsm_x2(F.bh[nt], baddr);
            ldsm_x2(F.bl[nt], baddr + B_PLANE);
        }
    };

    auto runmma = [&](const Frag& F) {
        // pass-major: consecutive MMAs hit different accumulators
#pragma unroll
        for (int mt = 0; mt < 2; ++mt)
#pragma unroll
            for (int nt = 0; nt < 4; ++nt)
                mma_bf16(acc[mt][nt], F.ah[mt], F.bh[nt]);
#pragma unroll
        for (int mt = 0; mt < 2; ++mt)
#pragma unroll
            for (int nt = 0; nt < 4; ++nt)
                mma_bf16(acc[mt][nt], F.ah[mt], F.bl[nt]);
#pragma unroll
        for (int mt = 0; mt < 2; ++mt)
#pragma unroll
            for (int nt = 0; nt < 4; ++nt)
                mma_bf16(acc[mt][nt], F.al[mt], F.bh[nt]);
    };

    issue(0, 0);
    issue(1, GBK);
    cp_wait1();              // chunk 0 resident
    __syncthreads();

    Frag F0, F1;
    loadfrag(F0, sbase, 0);  // chunk 0, ks=0

#pragma unroll 2
    for (int it = 0; it < NCHUNK; ++it) {
        const int s = it & 1;
        const uint32_t ss = sbase + s * STAGE_B;

        loadfrag(F1, ss, 32);              // ks=1 of chunk it (stage s fully consumed)
        __syncthreads();                   // all warps done reading stage s
        if (it + 2 < NCHUNK) issue(s, (it + 2) * GBK);   // refill stage s
        runmma(F0);                        // ks=0 MMAs

        if (it + 1 < NCHUNK) {
            if (it + 2 < NCHUNK) cp_wait1();   // chunk it+1 resident
            else                 cp_wait0();   // tail: drain everything
            __syncthreads();                   // cp.async visibility
            loadfrag(F0, sbase + ((it + 1) & 1) * STAGE_B, 0);  // next chunk ks=0
        }
        runmma(F1);                        // ks=1 MMAs (overlap F0 loads)
    }

#pragma unroll
    for (int mt = 0; mt < 2; ++mt) {
#pragma unroll
        for (int nt = 0; nt < 4; ++nt) {
            const int row = m0 + wm * 32 + mt * 16 + gid;
            const int col = n0 + wn * 32 + nt * 8 + tig * 2;
            const float b0 = bias[col], b1 = bias[col + 1];
            float2 v0 = {acc[mt][nt][0] + b0, acc[mt][nt][1] + b1};
            float2 v1 = {acc[mt][nt][2] + b0, acc[mt][nt][3] + b1};
            *(float2*)(C + (size_t)row * Ntot + col)       = v0;
            *(float2*)(C + (size_t)(row + 8) * Ntot + col) = v1;
        }
    }
}

// ---------------------------------------------------------------------------
__global__ __launch_bounds__(256) void split_bf16(
    const float4* __restrict__ in, uint2* __restrict__ hi, uint2* __restrict__ lo, int n4)
{
    const int i = blockIdx.x * 256 + threadIdx.x;
    if (i >= n4) return;
    float4 v = in[i];
    uint32_t H0, L0, H1, L1;
    bsplit2(v.x, v.y, H0, L0);
    bsplit2(v.z, v.w, H1, L1);
    hi[i] = make_uint2(H0, H1);
    lo[i] = make_uint2(L0, L1);
}

__global__ __launch_bounds__(256) void transpose_split(
    const float* __restrict__ W,
    __nv_bfloat16* __restrict__ Whi, __nv_bfloat16* __restrict__ Wlo, int K, int N)
{
    __shared__ float t[32][33];
    const int n0 = blockIdx.x * 32, k0 = blockIdx.y * 32;
    const int tx = threadIdx.x, ty = threadIdx.y;
#pragma unroll
    for (int i = 0; i < 32; i += 8)
        t[ty + i][tx] = W[(size_t)(k0 + ty + i) * N + n0 + tx];
    __syncthreads();
#pragma unroll
    for (int i = 0; i < 32; i += 8) {
        float x = t[tx][ty + i];
        __nv_bfloat16 h = __float2bfloat16_rn(x);
        __nv_bfloat16 l = __float2bfloat16_rn(x - __bfloat162float(h));
        const size_t idx = (size_t)(n0 + ty + i) * K + k0 + tx;
        Whi[idx] = h;
        Wlo[idx] = l;
    }
}

// ---------------------------------------------------------------------------
// RMSNorm + rotary; emits split-bf16 q (pre-scaled), k, and v planes.
// ---------------------------------------------------------------------------
__global__ __launch_bounds__(256) void rms_rope_split(
    const float* __restrict__ qkv,
    const float* __restrict__ gq, const float* __restrict__ gk,
    const float* __restrict__ fcos, const float* __restrict__ fsin,
    __nv_bfloat16* __restrict__ qh, __nv_bfloat16* __restrict__ ql,
    __nv_bfloat16* __restrict__ kh, __nv_bfloat16* __restrict__ kl,
    __nv_bfloat16* __restrict__ vh, __nv_bfloat16* __restrict__ vl)
{
    const int t   = blockIdx.x;
    const int l   = t & (SEQ - 1);
    const int tid = threadIdx.x;

    const float* qrow = qkv + (size_t)t * QKV_COLS;
    const float* krow = qrow + DIMN;
    const float* vrow = qrow + 2 * DIMN;

    float sq = 0.0f, sk = 0.0f;
    for (int i = tid; i < DIMN; i += 256) {
        float a = qrow[i]; sq = fmaf(a, a, sq);
        float b = krow[i]; sk = fmaf(b, b, sk);
    }
#pragma unroll
    for (int off = 16; off; off >>= 1) {
        sq += __shfl_xor_sync(0xffffffffu, sq, off);
        sk += __shfl_xor_sync(0xffffffffu, sk, off);
    }
    __shared__ float redq[8], redk[8];
    __shared__ float bq, bk;
    const int warp = tid >> 5, lane = tid & 31;
    if (lane == 0) { redq[warp] = sq; redk[warp] = sk; }
    __syncthreads();
    if (tid == 0) {
        float a = 0.0f, b = 0.0f;
#pragma unroll
        for (int w = 0; w < 8; ++w) { a += redq[w]; b += redk[w]; }
        bq = a; bk = b;
    }
    __syncthreads();
    const float rq = rsqrtf(bq * (1.0f / DIMN) + EPSV);
    const float rk = rsqrtf(bk * (1.0f / DIMN) + EPSV);

    const size_t ob = (size_t)t * DIMN;
    for (int p = tid; p < DIMN / 2; p += 256) {
        const int head = p >> 6;
        const int i2   = (p & 63) * 2;
        const int ce   = head * HDIM + i2;
        const int co   = ce + 1;
        const float ccos = fcos[l * HDIM + i2];
        const float csin = fsin[l * HDIM + i2 + 1];

        float xe = qrow[ce] * rq * gq[ce];
        float xo = qrow[co] * rq * gq[co];
        float qe = (xe * ccos - xo * csin) * SCALEV;
        float qo = (xe * csin + xo * ccos) * SCALEV;
        uint32_t H, L;
        bsplit2(qe, qo, H, L);
        *(uint32_t*)(qh + ob + ce) = H;
        *(uint32_t*)(ql + ob + ce) = L;

        xe = krow[ce] * rk * gk[ce];
        xo = krow[co] * rk * gk[co];
        float ke = xe * ccos - xo * csin;
        float ko = xe * csin + xo * ccos;
        bsplit2(ke, ko, H, L);
        *(uint32_t*)(kh + ob + ce) = H;
        *(uint32_t*)(kl + ob + ce) = L;

        float v0 = vrow[ce], v1 = vrow[co];
        bsplit2(v0, v1, H, L);
        *(uint32_t*)(vh + ob + ce) = H;
        *(uint32_t*)(vl + ob + ce) = L;
    }
}

// ---------------------------------------------------------------------------
// Tensor-core flash attention. Br=128, Bc=64, D=128.
// ---------------------------------------------------------------------------
__global__ __launch_bounds__(256, 1) void flash_mma(
    const __nv_bfloat16* __restrict__ qhp, const __nv_bfloat16* __restrict__ qlp,
    const __nv_bfloat16* __restrict__ khp, const __nv_bfloat16* __restrict__ klp,
    const __nv_bfloat16* __restrict__ vhp, const __nv_bfloat16* __restrict__ vlp,
    __nv_bfloat16* __restrict__ ohi, __nv_bfloat16* __restrict__ olo)
{
    extern __shared__ char fsm[];
    const uint32_t sb = smem_u32(fsm);

    const int qb = blockIdx.x, bh = blockIdx.y;
    const int b  = bh / NHEADS, h = bh % NHEADS;
    const int tid = threadIdx.x, wid = tid >> 5, lane = tid & 31;
    const int gid = lane >> 2, tig = lane & 3;
    const int l15 = lane & 15;
    const int hofs = h * HDIM;
    const size_t qrow0 = (size_t)(b * SEQ + qb * FBR);
    const size_t krow0 = (size_t)(b * SEQ);

    for (int i = 0; i < 16; ++i) {
        const int idx = tid + 256 * i;
        const int pl  = idx >> 11;
        const int r   = (idx >> 4) & 127;
        const int c   = idx & 15;
        const __nv_bfloat16* src = (pl ? qlp : qhp) + (qrow0 + r) * DIMN + hofs + c * 8;
        cp16(sb + pl * FQPL + r * FROWB + c * 16, src);
    }
    auto loadkv = [&](int s, int kb) {
        const uint32_t st = sb + 2 * FQPL + s * FSTG;
        const size_t kr = krow0 + (size_t)kb * FBC;
        for (int i = 0; i < 16; ++i) {
            const int idx = tid + 256 * i;
            const int pl  = idx >> 10;
            const int r   = (idx >> 4) & 63;
            const int c   = idx & 15;
            const __nv_bfloat16* base = (pl == 0) ? khp : (pl == 1) ? klp
                                      : (pl == 2) ? vhp : vlp;
            cp16(st + pl * FKPL + r * FROWB + c * 16, base + (kr + r) * DIMN + hofs + c * 8);
        }
        cp_commit();
    };
    loadkv(0, 0);
    loadkv(1, 1);

    float oacc[16][4];
#pragma unroll
    for (int d = 0; d < 16; ++d)
#pragma unroll
        for (int c = 0; c < 4; ++c) oacc[d][c] = 0.0f;
    float mrow[2] = {-1e30f, -1e30f};
    float lrow[2] = {0.0f, 0.0f};

    const int qrow = wid * 16 + l15;
    const uint32_t qcol = ((lane >> 4) & 1) * 16;
    const int krw  = l15 & 7;
    const uint32_t kcadd = ((l15 >> 3) & 1) * 16;

    for (int kb = 0; kb < SEQ / FBC; ++kb) {
        cp_wait1();
        __syncthreads();
        const uint32_t st = sb + 2 * FQPL + (kb & 1) * FSTG;
        const uint32_t kh = st, kl = st + FKPL, vh = st + 2 * FKPL, vl = st + 3 * FKPL;

        float sacc[8][4];
#pragma unroll
        for (int nt = 0; nt < 8; ++nt)
#pragma unroll
            for (int c = 0; c < 4; ++c) sacc[nt][c] = 0.0f;

#pragma unroll
        for (int kc = 0; kc < 8; ++kc) {
            uint32_t aqh[4], aql[4];
            ldsm_x4(aqh, sb + qrow * FROWB + kc * 32 + qcol);
            ldsm_x4(aql, sb + FQPL + qrow * FROWB + kc * 32 + qcol);
            const uint32_t kcol = kc * 32 + kcadd;
#pragma unroll
            for (int nt = 0; nt < 8; ++nt) {
                uint32_t bkh[2], bkl[2];
                ldsm_x2(bkh, kh + (nt * 8 + krw) * FROWB + kcol);
                ldsm_x2(bkl, kl + (nt * 8 + krw) * FROWB + kcol);
                mma_bf16(sacc[nt], aqh, bkh);
                mma_bf16(sacc[nt], aqh, bkl);
                mma_bf16(sacc[nt], aql, bkh);
            }
        }

        float mx0 = sacc[0][0], mx1 = sacc[0][2];
#pragma unroll
        for (int nt = 0; nt < 8; ++nt) {
            mx0 = fmaxf(mx0, fmaxf(sacc[nt][0], sacc[nt][1]));
            mx1 = fmaxf(mx1, fmaxf(sacc[nt][2], sacc[nt][3]));
        }
        mx0 = fmaxf(mx0, __shfl_xor_sync(0xffffffffu, mx0, 1));
        mx0 = fmaxf(mx0, __shfl_xor_sync(0xffffffffu, mx0, 2));
        mx1 = fmaxf(mx1, __shfl_xor_sync(0xffffffffu, mx1, 1));
        mx1 = fmaxf(mx1, __shfl_xor_sync(0xffffffffu, mx1, 2));
        const float mn0 = fmaxf(mrow[0], mx0);
        const float mn1 = fmaxf(mrow[1], mx1);
        const float al0 = __expf(mrow[0] - mn0);
        const float al1 = __expf(mrow[1] - mn1);
        mrow[0] = mn0; mrow[1] = mn1;

        float rs0 = 0.0f, rs1 = 0.0f;
#pragma unroll
        for (int nt = 0; nt < 8; ++nt) {
            sacc[nt][0] = __expf(sacc[nt][0] - mn0);
            sacc[nt][1] = __expf(sacc[nt][1] - mn0);
            sacc[nt][2] = __expf(sacc[nt][2] - mn1);
            sacc[nt][3] = __expf(sacc[nt][3] - mn1);
            rs0 += sacc[nt][0] + sacc[nt][1];
            rs1 += sacc[nt][2] + sacc[nt][3];
        }
        rs0 += __shfl_xor_sync(0xffffffffu, rs0, 1);
        rs0 += __shfl_xor_sync(0xffffffffu, rs0, 2);
        rs1 += __shfl_xor_sync(0xffffffffu, rs1, 1);
        rs1 += __shfl_xor_sync(0xffffffffu, rs1, 2);
        lrow[0] = lrow[0] * al0 + rs0;
        lrow[1] = lrow[1] * al1 + rs1;
#pragma unroll
        for (int d = 0; d < 16; ++d) {
            oacc[d][0] *= al0; oacc[d][1] *= al0;
            oacc[d][2] *= al1; oacc[d][3] *= al1;
        }

#pragma unroll
        for (int kc2 = 0; kc2 < 4; ++kc2) {
            uint32_t aph[4], apl[4];
            bsplit2(sacc[2 * kc2][0],     sacc[2 * kc2][1],     aph[0], apl[0]);
            bsplit2(sacc[2 * kc2][2],     sacc[2 * kc2][3],     aph[1], apl[1]);
            bsplit2(sacc[2 * kc2 + 1][0], sacc[2 * kc2 + 1][1], aph[2], apl[2]);
            bsplit2(sacc[2 * kc2 + 1][2], sacc[2 * kc2 + 1][3], aph[3], apl[3]);
            const uint32_t vr = (kc2 * 16 + l15) * FROWB;
#pragma unroll
            for (int dt = 0; dt < 16; ++dt) {
                uint32_t bvh[2], bvl[2];
                ldsm_x2t(bvh, vh + vr + dt * 16);
                ldsm_x2t(bvl, vl + vr + dt * 16);
                mma_bf16(oacc[dt], aph, bvh);
                mma_bf16(oacc[dt], aph, bvl);
                mma_bf16(oacc[dt], apl, bvh);
            }
        }
        __syncthreads();
        if (kb + 2 < SEQ / FBC) loadkv(kb & 1, kb + 2);
    }

#pragma unroll
    for (int i = 0; i < 2; ++i) {
        const float inv = 1.0f / lrow[i];
        const size_t base =
            (qrow0 + (size_t)(wid * 16 + gid + i * 8)) * DIMN + hofs + tig * 2;
#pragma unroll
        for (int dt = 0; dt < 16; ++dt) {
            uint32_t H, L;
            bsplit2(oacc[dt][2 * i] * inv, oacc[dt][2 * i + 1] * inv, H, L);
            *(uint32_t*)(ohi + base + dt * 8) = H;
            *(uint32_t*)(olo + base + dt * 8) = L;
        }
    }
}

// ---------------------------------------------------------------------------
extern "C" void kernel_launch(void* const* d_in, const int* in_sizes, int n_in,
                              void* d_out, int out_size)
{
    const float* X    = (const float*)d_in[0];
    const float* fcos = (const float*)d_in[1];
    const float* fsin = (const float*)d_in[2];
    const float* Wqkv = (const float*)d_in[3];
    const float* bqkv = (const float*)d_in[4];
    const float* gq   = (const float*)d_in[5];
    const float* gk   = (const float*)d_in[6];
    const float* Wout = (const float*)d_in[7];
    const float* bout = (const float*)d_in[8];
    float* out = (float*)d_out;

    float *qkvbuf;
    __nv_bfloat16 *xhi, *xlo, *ahi, *alo, *wqhi, *wqlo, *wohi, *wolo;
    __nv_bfloat16 *qh, *ql, *kh, *kl, *vh, *vl;
    cudaGetSymbolAddress((void**)&qkvbuf, g_qkv);
    cudaGetSymbolAddress((void**)&xhi, g_xhi);
    cudaGetSymbolAddress((void**)&xlo, g_xlo);
    cudaGetSymbolAddress((void**)&ahi, g_ahi);
    cudaGetSymbolAddress((void**)&alo, g_alo);
    cudaGetSymbolAddress((void**)&wqhi, g_wqhi);
    cudaGetSymbolAddress((void**)&wqlo, g_wqlo);
    cudaGetSymbolAddress((void**)&wohi, g_wohi);
    cudaGetSymbolAddress((void**)&wolo, g_wolo);
    cudaGetSymbolAddress((void**)&qh, g_qh);
    cudaGetSymbolAddress((void**)&ql, g_ql);
    cudaGetSymbolAddress((void**)&kh, g_kh);
    cudaGetSymbolAddress((void**)&kl, g_kl);
    cudaGetSymbolAddress((void**)&vh, g_vh);
    cudaGetSymbolAddress((void**)&vl, g_vl);

    cudaFuncSetAttribute(gemm_bf16x3, cudaFuncAttributeMaxDynamicSharedMemorySize, GSMEM);
    cudaFuncSetAttribute(flash_mma, cudaFuncAttributeMaxDynamicSharedMemorySize, FSMEM);

    // 0) precision-split operands
    split_bf16<<<(TOKENS * DIMN / 4 + 255) / 256, 256>>>(
        (const float4*)X, (uint2*)xhi, (uint2*)xlo, TOKENS * DIMN / 4);
    transpose_split<<<dim3(QKV_COLS / 32, DIMN / 32), dim3(32, 8)>>>(
        Wqkv, wqhi, wqlo, DIMN, QKV_COLS);
    transpose_split<<<dim3(DIMN / 32, DIMN / 32), dim3(32, 8)>>>(
        Wout, wohi, wolo, DIMN, DIMN);

    // 1) qkv = X @ W_qkv + b_qkv
    gemm_bf16x3<<<dim3(TOKENS / GBM, QKV_COLS / GBN), 256, GSMEM>>>(
        xhi, xlo, wqhi, wqlo, bqkv, qkvbuf, QKV_COLS);

    // 2) RMSNorm + RoPE -> split planes
    rms_rope_split<<<TOKENS, 256>>>(qkvbuf, gq, gk, fcos, fsin,
                                    qh, ql, kh, kl, vh, vl);

    // 3) tensor-core flash attention -> bf16 hi/lo planes
    flash_mma<<<dim3(SEQ / FBR, BATCH * NHEADS), 256, FSMEM>>>(
        qh, ql, kh, kl, vh, vl, ahi, alo);

    // 4) out = attn @ W_out + b_out
    gemm_bf16x3<<<dim3(TOKENS / GBM, DIMN / GBN), 256, GSMEM>>>(
        ahi, alo, wohi, wolo, bout, out, DIMN);
}

// round 12
// speedup vs baseline: 4.0971x; 1.3300x over previous
#include <cuda.h>
#include <cuda_runtime.h>
#include <cuda_bf16.h>
#include <math.h>
#include <stdint.h>

// Problem constants
#define DIMN     5120
#define NHEADS   40
#define HDIM     128
#define BATCH    2
#define SEQ      1024
#define TOKENS   (BATCH * SEQ)        // 2048
#define QKV_COLS (3 * DIMN)           // 15360
#define EPSV     1e-6f
#define SCALEV   0.08838834764831845f // 128^-0.5

// GEMM tiling: CTA 64x128, 8 warps of 32x32, BK=64, 2-stage TMA, 2 CTAs/SM
#define GBM 64
#define GBN 128
#define GBK 64
#define A_PL (GBM * GBK * 2)              // 16384... no: 64*64*2 = 8192 B per plane
#define B_PL (GBN * GBK * 2)              // 128*64*2 = 16384 B
#define STB  (2 * A_PL + 2 * B_PL)        // 49152 per stage
#define GSMEM (1024 + 2 * STB)            // ctrl + 2 stages = 99328
#define NCH (DIMN / GBK)                  // 80

// Flash tiling: Br=128 (8 warps x m16), Bc=64, D=128, 2-stage cp.async K/V
#define FBR 128
#define FBC 64
#define FROWB 272
#define FQPL (FBR * FROWB)
#define FKPL (FBC * FROWB)
#define FSTG (4 * FKPL)
#define FSMEM (2 * FQPL + 2 * FSTG)       // 208896

// Scratch (no allocations allowed)
__device__ float          g_qkv[(size_t)TOKENS * QKV_COLS];
__device__ __nv_bfloat16  g_xhi[(size_t)TOKENS * DIMN];
__device__ __nv_bfloat16  g_xlo[(size_t)TOKENS * DIMN];
__device__ __nv_bfloat16  g_ahi[(size_t)TOKENS * DIMN];
__device__ __nv_bfloat16  g_alo[(size_t)TOKENS * DIMN];
__device__ __nv_bfloat16  g_wqhi[(size_t)QKV_COLS * DIMN];
__device__ __nv_bfloat16  g_wqlo[(size_t)QKV_COLS * DIMN];
__device__ __nv_bfloat16  g_wohi[(size_t)DIMN * DIMN];
__device__ __nv_bfloat16  g_wolo[(size_t)DIMN * DIMN];
__device__ __nv_bfloat16  g_qh[(size_t)TOKENS * DIMN];
__device__ __nv_bfloat16  g_ql[(size_t)TOKENS * DIMN];
__device__ __nv_bfloat16  g_kh[(size_t)TOKENS * DIMN];
__device__ __nv_bfloat16  g_kl[(size_t)TOKENS * DIMN];
__device__ __nv_bfloat16  g_vh[(size_t)TOKENS * DIMN];
__device__ __nv_bfloat16  g_vl[(size_t)TOKENS * DIMN];

// ---------------------------------------------------------------------------
__device__ __forceinline__ uint32_t smem_u32(const void* p) {
    uint32_t a;
    asm("{ .reg .u64 t; cvta.to.shared.u64 t, %1; cvt.u32.u64 %0, t; }" : "=r"(a) : "l"(p));
    return a;
}
__device__ __forceinline__ void cp16(uint32_t s, const void* g) {
    asm volatile("cp.async.cg.shared.global [%0], [%1], 16;" :: "r"(s), "l"(g));
}
__device__ __forceinline__ void cp_commit() {
    asm volatile("cp.async.commit_group;" ::: "memory");
}
__device__ __forceinline__ void cp_wait1() {
    asm volatile("cp.async.wait_group 1;" ::: "memory");
}
#define MBARRIER_INIT(addr, cnt) \
    asm volatile("mbarrier.init.shared.b64 [%0], %1;" :: "r"(addr), "r"(cnt) : "memory")
#define MBARRIER_EXPECT_TX(addr, bytes) \
    asm volatile("mbarrier.arrive.expect_tx.shared.b64 _, [%0], %1;" :: "r"(addr), "r"(bytes) : "memory")
#define MBARRIER_WAIT_PARITY(addr, parity) do { \
    uint32_t _m = (addr); uint32_t _p = (parity); uint32_t _d; \
    asm volatile("{\n\t.reg .pred p;\n\t" \
        "mbarrier.try_wait.parity.acquire.cta.shared::cta.b64 p, [%1], %2;\n\t" \
        "selp.b32 %0, 1, 0, p;\n\t}" : "=r"(_d) : "r"(_m), "r"(_p) : "memory"); \
    if (!_d) { \
        asm volatile("{\n\t.reg .pred P1;\n\t" \
            "WL_%=:\n\t" \
            "mbarrier.try_wait.parity.acquire.cta.shared::cta.b64 P1, [%0], %1, 0x989680;\n\t" \
            "@P1 bra.uni WD_%=;\n\t" \
            "bra.uni WL_%=;\n\t" \
            "WD_%=:\n\t}" :: "r"(_m), "r"(_p) : "memory"); \
    } \
} while (0)
#define TMA_LOAD_2D(saddr, tmap, cx, cy, mbar) \
    asm volatile("cp.async.bulk.tensor.2d.shared::cta.global.tile.mbarrier::complete_tx::bytes " \
                 "[%0], [%1, {%2, %3}], [%4];" \
                 :: "r"(saddr), "l"(tmap), "r"(cx), "r"(cy), "r"(mbar) : "memory")

__device__ __forceinline__ void mma_bf16(float* c, const uint32_t* a, const uint32_t* b) {
    asm volatile("mma.sync.aligned.m16n8k16.row.col.f32.bf16.bf16.f32 "
        "{%0,%1,%2,%3}, {%4,%5,%6,%7}, {%8,%9}, {%0,%1,%2,%3};"
        : "+f"(c[0]), "+f"(c[1]), "+f"(c[2]), "+f"(c[3])
        : "r"(a[0]), "r"(a[1]), "r"(a[2]), "r"(a[3]), "r"(b[0]), "r"(b[1]));
}
__device__ __forceinline__ void ldsm_x4(uint32_t* r, uint32_t a) {
    asm volatile("ldmatrix.sync.aligned.m8n8.x4.shared.b16 {%0,%1,%2,%3}, [%4];"
        : "=r"(r[0]), "=r"(r[1]), "=r"(r[2]), "=r"(r[3]) : "r"(a));
}
__device__ __forceinline__ void ldsm_x2(uint32_t* r, uint32_t a) {
    asm volatile("ldmatrix.sync.aligned.m8n8.x2.shared.b16 {%0,%1}, [%2];"
        : "=r"(r[0]), "=r"(r[1]) : "r"(a));
}
__device__ __forceinline__ void ldsm_x2t(uint32_t* r, uint32_t a) {
    asm volatile("ldmatrix.sync.aligned.m8n8.x2.trans.shared.b16 {%0,%1}, [%2];"
        : "=r"(r[0]), "=r"(r[1]) : "r"(a));
}
__device__ __forceinline__ void bsplit2(float x, float y, uint32_t& hi, uint32_t& lo) {
    __nv_bfloat16 hx = __float2bfloat16_rn(x), hy = __float2bfloat16_rn(y);
    __nv_bfloat16 lx = __float2bfloat16_rn(x - __bfloat162float(hx));
    __nv_bfloat16 ly = __float2bfloat16_rn(y - __bfloat162float(hy));
    hi = ((uint32_t)__bfloat16_as_ushort(hy) << 16) | __bfloat16_as_ushort(hx);
    lo = ((uint32_t)__bfloat16_as_ushort(ly) << 16) | __bfloat16_as_ushort(lx);
}

// ---------------------------------------------------------------------------
// GEMM: C[M, Ntot] = A @ B^T + bias, 3-pass split bf16 (hh + hl + lh).
// TMA-loaded tiles (SW128, 128B rows), ldmatrix fragments with per-lane
// swizzled addresses. CTA 64x128, warptile 32x32, 2 CTAs/SM.
// ---------------------------------------------------------------------------
__global__ __launch_bounds__(256, 2) void gemm_tma(
    const __grid_constant__ CUtensorMap tAh, const __grid_constant__ CUtensorMap tAl,
    const __grid_constant__ CUtensorMap tBh, const __grid_constant__ CUtensorMap tBl,
    const float* __restrict__ bias, float* __restrict__ C, int Ntot)
{
    extern __shared__ __align__(1024) char gsm[];
    const uint32_t sb0  = smem_u32(gsm);
    const uint32_t ctrl = sb0;            // barriers in first 1KB
    const uint32_t tile = sb0 + 1024;

    const int tid = threadIdx.x;
    const int m0  = blockIdx.x * GBM;
    const int n0  = blockIdx.y * GBN;

    const int wid  = tid >> 5, lane = tid & 31;
    const int wm   = wid & 1;        // 2 groups of 32 rows
    const int wn   = wid >> 1;       // 4 groups of 32 cols
    const int gid  = lane >> 2;
    const int tig  = lane & 3;
    const int l15  = lane & 15;

    const uint32_t a_row  = (uint32_t)(wm * 32 + l15);
    const uint32_t a_colh = (uint32_t)((lane >> 4) << 4);
    const uint32_t b_row  = (uint32_t)(wn * 32 + (lane & 7));
    const uint32_t b_colh = (uint32_t)(((lane >> 3) & 1) << 4);

    if (tid == 0) { MBARRIER_INIT(ctrl, 1); MBARRIER_INIT(ctrl + 8, 1); }
    __syncthreads();

    auto issue = [&](int s, int k0) {
        const uint32_t st = tile + s * STB;
        MBARRIER_EXPECT_TX(ctrl + s * 8, STB);
        TMA_LOAD_2D(st,                   &tAh, k0, m0, ctrl + s * 8);
        TMA_LOAD_2D(st + A_PL,            &tAl, k0, m0, ctrl + s * 8);
        TMA_LOAD_2D(st + 2 * A_PL,        &tBh, k0, n0, ctrl + s * 8);
        TMA_LOAD_2D(st + 2 * A_PL + B_PL, &tBl, k0, n0, ctrl + s * 8);
    };

    float acc[2][4][4];
#pragma unroll
    for (int a = 0; a < 2; ++a)
#pragma unroll
        for (int b = 0; b < 4; ++b)
#pragma unroll
            for (int c = 0; c < 4; ++c) acc[a][b][c] = 0.0f;

    if (tid == 0) { issue(0, 0); issue(1, GBK); }

    for (int it = 0; it < NCH; ++it) {
        const int s = it & 1;
        MBARRIER_WAIT_PARITY(ctrl + s * 8, (it >> 1) & 1);
        const uint32_t ss = tile + s * STB;

#pragma unroll
        for (int ks = 0; ks < 4; ++ks) {
            const uint32_t kofs = (uint32_t)(ks * 32);

            uint32_t ah[2][4], al[2][4];
#pragma unroll
            for (int mt = 0; mt < 2; ++mt) {
                const uint32_t r  = a_row + mt * 16;
                const uint32_t c  = (kofs + a_colh) ^ ((r & 7) * 16);
                const uint32_t ad = ss + r * 128 + c;
                ldsm_x4(ah[mt], ad);
                ldsm_x4(al[mt], ad + A_PL);
            }
            uint32_t bh[4][2], bl[4][2];
#pragma unroll
            for (int nt = 0; nt < 4; ++nt) {
                const uint32_t r  = b_row + nt * 8;
                const uint32_t c  = (kofs + b_colh) ^ ((r & 7) * 16);
                const uint32_t bd = ss + 2 * A_PL + r * 128 + c;
                ldsm_x2(bh[nt], bd);
                ldsm_x2(bl[nt], bd + B_PL);
            }
            // pass-major: consecutive MMAs hit different accumulators
#pragma unroll
            for (int mt = 0; mt < 2; ++mt)
#pragma unroll
                for (int nt = 0; nt < 4; ++nt)
                    mma_bf16(acc[mt][nt], ah[mt], bh[nt]);
#pragma unroll
            for (int mt = 0; mt < 2; ++mt)
#pragma unroll
                for (int nt = 0; nt < 4; ++nt)
                    mma_bf16(acc[mt][nt], ah[mt], bl[nt]);
#pragma unroll
            for (int mt = 0; mt < 2; ++mt)
#pragma unroll
                for (int nt = 0; nt < 4; ++nt)
                    mma_bf16(acc[mt][nt], al[mt], bh[nt]);
        }
        __syncthreads();                  // all warps done with stage s
        if (tid == 0 && it + 2 < NCH) issue(s, (it + 2) * GBK);
    }

#pragma unroll
    for (int mt = 0; mt < 2; ++mt) {
#pragma unroll
        for (int nt = 0; nt < 4; ++nt) {
            const int row = m0 + wm * 32 + mt * 16 + gid;
            const int col = n0 + wn * 32 + nt * 8 + tig * 2;
            const float b0 = bias[col], b1 = bias[col + 1];
            float2 v0 = {acc[mt][nt][0] + b0, acc[mt][nt][1] + b1};
            float2 v1 = {acc[mt][nt][2] + b0, acc[mt][nt][3] + b1};
            *(float2*)(C + (size_t)row * Ntot + col)       = v0;
            *(float2*)(C + (size_t)(row + 8) * Ntot + col) = v1;
        }
    }
}

// ---------------------------------------------------------------------------
__global__ __launch_bounds__(256) void split_bf16(
    const float4* __restrict__ in, uint2* __restrict__ hi, uint2* __restrict__ lo, int n4)
{
    const int i = blockIdx.x * 256 + threadIdx.x;
    if (i >= n4) return;
    float4 v = in[i];
    uint32_t H0, L0, H1, L1;
    bsplit2(v.x, v.y, H0, L0);
    bsplit2(v.z, v.w, H1, L1);
    hi[i] = make_uint2(H0, H1);
    lo[i] = make_uint2(L0, L1);
}

__global__ __launch_bounds__(256) void transpose_split(
    const float* __restrict__ W,
    __nv_bfloat16* __restrict__ Whi, __nv_bfloat16* __restrict__ Wlo, int K, int N)
{
    __shared__ float t[32][33];
    const int n0 = blockIdx.x * 32, k0 = blockIdx.y * 32;
    const int tx = threadIdx.x, ty = threadIdx.y;
#pragma unroll
    for (int i = 0; i < 32; i += 8)
        t[ty + i][tx] = W[(size_t)(k0 + ty + i) * N + n0 + tx];
    __syncthreads();
#pragma unroll
    for (int i = 0; i < 32; i += 8) {
        float x = t[tx][ty + i];
        __nv_bfloat16 h = __float2bfloat16_rn(x);
        __nv_bfloat16 l = __float2bfloat16_rn(x - __bfloat162float(h));
        const size_t idx = (size_t)(n0 + ty + i) * K + k0 + tx;
        Whi[idx] = h;
        Wlo[idx] = l;
    }
}

// ---------------------------------------------------------------------------
// RMSNorm + rotary; emits split-bf16 q (pre-scaled), k, and v planes.
// ---------------------------------------------------------------------------
__global__ __launch_bounds__(256) void rms_rope_split(
    const float* __restrict__ qkv,
    const float* __restrict__ gq, const float* __restrict__ gk,
    const float* __restrict__ fcos, const float* __restrict__ fsin,
    __nv_bfloat16* __restrict__ qh, __nv_bfloat16* __restrict__ ql,
    __nv_bfloat16* __restrict__ kh, __nv_bfloat16* __restrict__ kl,
    __nv_bfloat16* __restrict__ vh, __nv_bfloat16* __restrict__ vl)
{
    const int t   = blockIdx.x;
    const int l   = t & (SEQ - 1);
    const int tid = threadIdx.x;

    const float* qrow = qkv + (size_t)t * QKV_COLS;
    const float* krow = qrow + DIMN;
    const float* vrow = qrow + 2 * DIMN;

    float sq = 0.0f, sk = 0.0f;
    for (int i = tid; i < DIMN; i += 256) {
        float a = qrow[i]; sq = fmaf(a, a, sq);
        float b = krow[i]; sk = fmaf(b, b, sk);
    }
#pragma unroll
    for (int off = 16; off; off >>= 1) {
        sq += __shfl_xor_sync(0xffffffffu, sq, off);
        sk += __shfl_xor_sync(0xffffffffu, sk, off);
    }
    __shared__ float redq[8], redk[8];
    __shared__ float bq, bk;
    const int warp = tid >> 5, lane = tid & 31;
    if (lane == 0) { redq[warp] = sq; redk[warp] = sk; }
    __syncthreads();
    if (tid == 0) {
        float a = 0.0f, b = 0.0f;
#pragma unroll
        for (int w = 0; w < 8; ++w) { a += redq[w]; b += redk[w]; }
        bq = a; bk = b;
    }
    __syncthreads();
    const float rq = rsqrtf(bq * (1.0f / DIMN) + EPSV);
    const float rk = rsqrtf(bk * (1.0f / DIMN) + EPSV);

    const size_t ob = (size_t)t * DIMN;
    for (int p = tid; p < DIMN / 2; p += 256) {
        const int head = p >> 6;
        const int i2   = (p & 63) * 2;
        const int ce   = head * HDIM + i2;
        const int co   = ce + 1;
        const float ccos = fcos[l * HDIM + i2];
        const float csin = fsin[l * HDIM + i2 + 1];

        float xe = qrow[ce] * rq * gq[ce];
        float xo = qrow[co] * rq * gq[co];
        float qe = (xe * ccos - xo * csin) * SCALEV;
        float qo = (xe * csin + xo * ccos) * SCALEV;
        uint32_t H, L;
        bsplit2(qe, qo, H, L);
        *(uint32_t*)(qh + ob + ce) = H;
        *(uint32_t*)(ql + ob + ce) = L;

        xe = krow[ce] * rk * gk[ce];
        xo = krow[co] * rk * gk[co];
        float ke = xe * ccos - xo * csin;
        float ko = xe * csin + xo * ccos;
        bsplit2(ke, ko, H, L);
        *(uint32_t*)(kh + ob + ce) = H;
        *(uint32_t*)(kl + ob + ce) = L;

        float v0 = vrow[ce], v1 = vrow[co];
        bsplit2(v0, v1, H, L);
        *(uint32_t*)(vh + ob + ce) = H;
        *(uint32_t*)(vl + ob + ce) = L;
    }
}

// ---------------------------------------------------------------------------
// Tensor-core flash attention. Br=128, Bc=64, D=128.
// ---------------------------------------------------------------------------
__global__ __launch_bounds__(256, 1) void flash_mma(
    const __nv_bfloat16* __restrict__ qhp, const __nv_bfloat16* __restrict__ qlp,
    const __nv_bfloat16* __restrict__ khp, const __nv_bfloat16* __restrict__ klp,
    const __nv_bfloat16* __restrict__ vhp, const __nv_bfloat16* __restrict__ vlp,
    __nv_bfloat16* __restrict__ ohi, __nv_bfloat16* __restrict__ olo)
{
    extern __shared__ char fsm[];
    const uint32_t sb = smem_u32(fsm);

    const int qb = blockIdx.x, bh = blockIdx.y;
    const int b  = bh / NHEADS, h = bh % NHEADS;
    const int tid = threadIdx.x, wid = tid >> 5, lane = tid & 31;
    const int gid = lane >> 2, tig = lane & 3;
    const int l15 = lane & 15;
    const int hofs = h * HDIM;
    const size_t qrow0 = (size_t)(b * SEQ + qb * FBR);
    const size_t krow0 = (size_t)(b * SEQ);

    for (int i = 0; i < 16; ++i) {
        const int idx = tid + 256 * i;
        const int pl  = idx >> 11;
        const int r   = (idx >> 4) & 127;
        const int c   = idx & 15;
        const __nv_bfloat16* src = (pl ? qlp : qhp) + (qrow0 + r) * DIMN + hofs + c * 8;
        cp16(sb + pl * FQPL + r * FROWB + c * 16, src);
    }
    auto loadkv = [&](int s, int kb) {
        const uint32_t st = sb + 2 * FQPL + s * FSTG;
        const size_t kr = krow0 + (size_t)kb * FBC;
        for (int i = 0; i < 16; ++i) {
            const int idx = tid + 256 * i;
            const int pl  = idx >> 10;
            const int r   = (idx >> 4) & 63;
            const int c   = idx & 15;
            const __nv_bfloat16* base = (pl == 0) ? khp : (pl == 1) ? klp
                                      : (pl == 2) ? vhp : vlp;
            cp16(st + pl * FKPL + r * FROWB + c * 16, base + (kr + r) * DIMN + hofs + c * 8);
        }
        cp_commit();
    };
    loadkv(0, 0);
    loadkv(1, 1);

    float oacc[16][4];
#pragma unroll
    for (int d = 0; d < 16; ++d)
#pragma unroll
        for (int c = 0; c < 4; ++c) oacc[d][c] = 0.0f;
    float mrow[2] = {-1e30f, -1e30f};
    float lrow[2] = {0.0f, 0.0f};

    const int qrow = wid * 16 + l15;
    const uint32_t qcol = ((lane >> 4) & 1) * 16;
    const int krw  = l15 & 7;
    const uint32_t kcadd = ((l15 >> 3) & 1) * 16;

    for (int kb = 0; kb < SEQ / FBC; ++kb) {
        cp_wait1();
        __syncthreads();
        const uint32_t st = sb + 2 * FQPL + (kb & 1) * FSTG;
        const uint32_t kh = st, kl = st + FKPL, vh = st + 2 * FKPL, vl = st + 3 * FKPL;

        float sacc[8][4];
#pragma unroll
        for (int nt = 0; nt < 8; ++nt)
#pragma unroll
            for (int c = 0; c < 4; ++c) sacc[nt][c] = 0.0f;

#pragma unroll
        for (int kc = 0; kc < 8; ++kc) {
            uint32_t aqh[4], aql[4];
            ldsm_x4(aqh, sb + qrow * FROWB + kc * 32 + qcol);
            ldsm_x4(aql, sb + FQPL + qrow * FROWB + kc * 32 + qcol);
            const uint32_t kcol = kc * 32 + kcadd;
#pragma unroll
            for (int nt = 0; nt < 8; ++nt) {
                uint32_t bkh[2], bkl[2];
                ldsm_x2(bkh, kh + (nt * 8 + krw) * FROWB + kcol);
                ldsm_x2(bkl, kl + (nt * 8 + krw) * FROWB + kcol);
                mma_bf16(sacc[nt], aqh, bkh);
                mma_bf16(sacc[nt], aqh, bkl);
                mma_bf16(sacc[nt], aql, bkh);
            }
        }

        float mx0 = sacc[0][0], mx1 = sacc[0][2];
#pragma unroll
        for (int nt = 0; nt < 8; ++nt) {
            mx0 = fmaxf(mx0, fmaxf(sacc[nt][0], sacc[nt][1]));
            mx1 = fmaxf(mx1, fmaxf(sacc[nt][2], sacc[nt][3]));
        }
        mx0 = fmaxf(mx0, __shfl_xor_sync(0xffffffffu, mx0, 1));
        mx0 = fmaxf(mx0, __shfl_xor_sync(0xffffffffu, mx0, 2));
        mx1 = fmaxf(mx1, __shfl_xor_sync(0xffffffffu, mx1, 1));
        mx1 = fmaxf(mx1, __shfl_xor_sync(0xffffffffu, mx1, 2));
        const float mn0 = fmaxf(mrow[0], mx0);
        const float mn1 = fmaxf(mrow[1], mx1);
        const float al0 = __expf(mrow[0] - mn0);
        const float al1 = __expf(mrow[1] - mn1);
        mrow[0] = mn0; mrow[1] = mn1;

        float rs0 = 0.0f, rs1 = 0.0f;
#pragma unroll
        for (int nt = 0; nt < 8; ++nt) {
            sacc[nt][0] = __expf(sacc[nt][0] - mn0);
            sacc[nt][1] = __expf(sacc[nt][1] - mn0);
            sacc[nt][2] = __expf(sacc[nt][2] - mn1);
            sacc[nt][3] = __expf(sacc[nt][3] - mn1);
            rs0 += sacc[nt][0] + sacc[nt][1];
            rs1 += sacc[nt][2] + sacc[nt][3];
        }
        rs0 += __shfl_xor_sync(0xffffffffu, rs0, 1);
        rs0 += __shfl_xor_sync(0xffffffffu, rs0, 2);
        rs1 += __shfl_xor_sync(0xffffffffu, rs1, 1);
        rs1 += __shfl_xor_sync(0xffffffffu, rs1, 2);
        lrow[0] = lrow[0] * al0 + rs0;
        lrow[1] = lrow[1] * al1 + rs1;
#pragma unroll
        for (int d = 0; d < 16; ++d) {
            oacc[d][0] *= al0; oacc[d][1] *= al0;
            oacc[d][2] *= al1; oacc[d][3] *= al1;
        }

#pragma unroll
        for (int kc2 = 0; kc2 < 4; ++kc2) {
            uint32_t aph[4], apl[4];
            bsplit2(sacc[2 * kc2][0],     sacc[2 * kc2][1],     aph[0], apl[0]);
            bsplit2(sacc[2 * kc2][2],     sacc[2 * kc2][3],     aph[1], apl[1]);
            bsplit2(sacc[2 * kc2 + 1][0], sacc[2 * kc2 + 1][1], aph[2], apl[2]);
            bsplit2(sacc[2 * kc2 + 1][2], sacc[2 * kc2 + 1][3], aph[3], apl[3]);
            const uint32_t vr = (kc2 * 16 + l15) * FROWB;
#pragma unroll
            for (int dt = 0; dt < 16; ++dt) {
                uint32_t bvh[2], bvl[2];
                ldsm_x2t(bvh, vh + vr + dt * 16);
                ldsm_x2t(bvl, vl + vr + dt * 16);
                mma_bf16(oacc[dt], aph, bvh);
                mma_bf16(oacc[dt], aph, bvl);
                mma_bf16(oacc[dt], apl, bvh);
            }
        }
        __syncthreads();
        if (kb + 2 < SEQ / FBC) loadkv(kb & 1, kb + 2);
    }

#pragma unroll
    for (int i = 0; i < 2; ++i) {
        const float inv = 1.0f / lrow[i];
        const size_t base =
            (qrow0 + (size_t)(wid * 16 + gid + i * 8)) * DIMN + hofs + tig * 2;
#pragma unroll
        for (int dt = 0; dt < 16; ++dt) {
            uint32_t H, L;
            bsplit2(oacc[dt][2 * i] * inv, oacc[dt][2 * i + 1] * inv, H, L);
            *(uint32_t*)(ohi + base + dt * 8) = H;
            *(uint32_t*)(olo + base + dt * 8) = L;
        }
    }
}

// ---------------------------------------------------------------------------
// Host side
// ---------------------------------------------------------------------------
typedef CUresult (CUDAAPI *EncodeTiledFn)(
    CUtensorMap*, CUtensorMapDataType, cuuint32_t, void*,
    const cuuint64_t*, const cuuint64_t*, const cuuint32_t*, const cuuint32_t*,
    CUtensorMapInterleave, CUtensorMapSwizzle, CUtensorMapL2promotion,
    CUtensorMapFloatOOBfill);

static void make_map_bf16(EncodeTiledFn enc, CUtensorMap* m, const void* p,
                          unsigned long long d0, unsigned long long d1,
                          unsigned b0, unsigned b1)
{
    cuuint64_t dims[2]    = {d0, d1};
    cuuint64_t strides[1] = {d0 * 2};
    cuuint32_t box[2]     = {b0, b1};
    cuuint32_t es[2]      = {1, 1};
    enc(m, CU_TENSOR_MAP_DATA_TYPE_BFLOAT16, 2, (void*)p, dims, strides, box, es,
        CU_TENSOR_MAP_INTERLEAVE_NONE, CU_TENSOR_MAP_SWIZZLE_128B,
        CU_TENSOR_MAP_L2_PROMOTION_L2_128B, CU_TENSOR_MAP_FLOAT_OOB_FILL_NONE);
}

extern "C" void kernel_launch(void* const* d_in, const int* in_sizes, int n_in,
                              void* d_out, int out_size)
{
    const float* X    = (const float*)d_in[0];
    const float* fcos = (const float*)d_in[1];
    const float* fsin = (const float*)d_in[2];
    const float* Wqkv = (const float*)d_in[3];
    const float* bqkv = (const float*)d_in[4];
    const float* gq   = (const float*)d_in[5];
    const float* gk   = (const float*)d_in[6];
    const float* Wout = (const float*)d_in[7];
    const float* bout = (const float*)d_in[8];
    float* out = (float*)d_out;

    float *qkvbuf;
    __nv_bfloat16 *xhi, *xlo, *ahi, *alo, *wqhi, *wqlo, *wohi, *wolo;
    __nv_bfloat16 *qh, *ql, *kh, *kl, *vh, *vl;
    cudaGetSymbolAddress((void**)&qkvbuf, g_qkv);
    cudaGetSymbolAddress((void**)&xhi, g_xhi);
    cudaGetSymbolAddress((void**)&xlo, g_xlo);
    cudaGetSymbolAddress((void**)&ahi, g_ahi);
    cudaGetSymbolAddress((void**)&alo, g_alo);
    cudaGetSymbolAddress((void**)&wqhi, g_wqhi);
    cudaGetSymbolAddress((void**)&wqlo, g_wqlo);
    cudaGetSymbolAddress((void**)&wohi, g_wohi);
    cudaGetSymbolAddress((void**)&wolo, g_wolo);
    cudaGetSymbolAddress((void**)&qh, g_qh);
    cudaGetSymbolAddress((void**)&ql, g_ql);
    cudaGetSymbolAddress((void**)&kh, g_kh);
    cudaGetSymbolAddress((void**)&kl, g_kl);
    cudaGetSymbolAddress((void**)&vh, g_vh);
    cudaGetSymbolAddress((void**)&vl, g_vl);

    EncodeTiledFn enc = nullptr;
    cudaDriverEntryPointQueryResult qr;
    cudaGetDriverEntryPoint("cuTensorMapEncodeTiled", (void**)&enc,
                            cudaEnableDefault, &qr);

    CUtensorMap tXh, tXl, tWqh, tWql, tAh, tAl, tWoh, tWol;
    make_map_bf16(enc, &tXh,  xhi,  DIMN, TOKENS,   GBK, GBM);
    make_map_bf16(enc, &tXl,  xlo,  DIMN, TOKENS,   GBK, GBM);
    make_map_bf16(enc, &tWqh, wqhi, DIMN, QKV_COLS, GBK, GBN);
    make_map_bf16(enc, &tWql, wqlo, DIMN, QKV_COLS, GBK, GBN);
    make_map_bf16(enc, &tAh,  ahi,  DIMN, TOKENS,   GBK, GBM);
    make_map_bf16(enc, &tAl,  alo,  DIMN, TOKENS,   GBK, GBM);
    make_map_bf16(enc, &tWoh, wohi, DIMN, DIMN,     GBK, GBN);
    make_map_bf16(enc, &tWol, wolo, DIMN, DIMN,     GBK, GBN);

    cudaFuncSetAttribute(gemm_tma, cudaFuncAttributeMaxDynamicSharedMemorySize, GSMEM);
    cudaFuncSetAttribute(flash_mma, cudaFuncAttributeMaxDynamicSharedMemorySize, FSMEM);

    // 0) precision-split operands
    split_bf16<<<(TOKENS * DIMN / 4 + 255) / 256, 256>>>(
        (const float4*)X, (uint2*)xhi, (uint2*)xlo, TOKENS * DIMN / 4);
    transpose_split<<<dim3(QKV_COLS / 32, DIMN / 32), dim3(32, 8)>>>(
        Wqkv, wqhi, wqlo, DIMN, QKV_COLS);
    transpose_split<<<dim3(DIMN / 32, DIMN / 32), dim3(32, 8)>>>(
        Wout, wohi, wolo, DIMN, DIMN);

    // 1) qkv = X @ W_qkv + b_qkv
    gemm_tma<<<dim3(TOKENS / GBM, QKV_COLS / GBN), 256, GSMEM>>>(
        tXh, tXl, tWqh, tWql, bqkv, qkvbuf, QKV_COLS);

    // 2) RMSNorm + RoPE -> split planes
    rms_rope_split<<<TOKENS, 256>>>(qkvbuf, gq, gk, fcos, fsin,
                                    qh, ql, kh, kl, vh, vl);

    // 3) tensor-core flash attention -> bf16 hi/lo planes
    flash_mma<<<dim3(SEQ / FBR, BATCH * NHEADS), 256, FSMEM>>>(
        qh, ql, kh, kl, vh, vl, ahi, alo);

    // 4) out = attn @ W_out + b_out
    gemm_tma<<<dim3(TOKENS / GBM, DIMN / GBN), 256, GSMEM>>>(
        tAh, tAl, tWoh, tWol, bout, out, DIMN);
}

// round 13
// speedup vs baseline: 4.1166x; 1.0047x over previous
#include <cuda.h>
#include <cuda_runtime.h>
#include <cuda_bf16.h>
#include <math.h>
#include <stdint.h>

// Problem constants
#define DIMN     5120
#define NHEADS   40
#define HDIM     128
#define BATCH    2
#define SEQ      1024
#define TOKENS   (BATCH * SEQ)        // 2048
#define QKV_COLS (3 * DIMN)           // 15360
#define EPSV     1e-6f
#define SCALEV   0.08838834764831845f // 128^-0.5

// GEMM tiling: CTA 64x128, 8 warps of 32x32, BK=64, 2-stage TMA, 2 CTAs/SM
#define GBM 64
#define GBN 128
#define GBK 64
#define A_PL (GBM * GBK * 2)              // 8192 B per plane
#define B_PL (GBN * GBK * 2)              // 16384 B
#define STB  (2 * A_PL + 2 * B_PL)        // 49152 per stage
#define GSMEM (1024 + 2 * STB)            // 99328
#define NCH (DIMN / GBK)                  // 80

// Flash tiling: Br=64 (4 warps x m16), Bc=32, D=128, 2-stage cp.async, 2 CTAs/SM
#define FBR 64
#define FBC 32
#define FROWB 272                          // 128 bf16 + 16B pad
#define FQ1  (FBR * FROWB)                 // 17408 (one Q plane)
#define FKPL (FBC * FROWB)                 // 8704 (one KV plane)
#define FSTG (4 * FKPL)                    // 34816 (khi,klo,vhi,vlo)
#define FSMEM (2 * FQ1 + 2 * FSTG)         // 104448 -> 2 CTAs/SM

// Scratch (no allocations allowed)
__device__ float          g_qkv[(size_t)TOKENS * QKV_COLS];
__device__ __nv_bfloat16  g_xhi[(size_t)TOKENS * DIMN];
__device__ __nv_bfloat16  g_xlo[(size_t)TOKENS * DIMN];
__device__ __nv_bfloat16  g_ahi[(size_t)TOKENS * DIMN];
__device__ __nv_bfloat16  g_alo[(size_t)TOKENS * DIMN];
__device__ __nv_bfloat16  g_wqhi[(size_t)QKV_COLS * DIMN];
__device__ __nv_bfloat16  g_wqlo[(size_t)QKV_COLS * DIMN];
__device__ __nv_bfloat16  g_wohi[(size_t)DIMN * DIMN];
__device__ __nv_bfloat16  g_wolo[(size_t)DIMN * DIMN];
__device__ __nv_bfloat16  g_qh[(size_t)TOKENS * DIMN];
__device__ __nv_bfloat16  g_ql[(size_t)TOKENS * DIMN];
__device__ __nv_bfloat16  g_kh[(size_t)TOKENS * DIMN];
__device__ __nv_bfloat16  g_kl[(size_t)TOKENS * DIMN];
__device__ __nv_bfloat16  g_vh[(size_t)TOKENS * DIMN];
__device__ __nv_bfloat16  g_vl[(size_t)TOKENS * DIMN];

// ---------------------------------------------------------------------------
__device__ __forceinline__ uint32_t smem_u32(const void* p) {
    uint32_t a;
    asm("{ .reg .u64 t; cvta.to.shared.u64 t, %1; cvt.u32.u64 %0, t; }" : "=r"(a) : "l"(p));
    return a;
}
__device__ __forceinline__ void cp16(uint32_t s, const void* g) {
    asm volatile("cp.async.cg.shared.global [%0], [%1], 16;" :: "r"(s), "l"(g));
}
__device__ __forceinline__ void cp_commit() {
    asm volatile("cp.async.commit_group;" ::: "memory");
}
__device__ __forceinline__ void cp_wait1() {
    asm volatile("cp.async.wait_group 1;" ::: "memory");
}
#define MBARRIER_INIT(addr, cnt) \
    asm volatile("mbarrier.init.shared.b64 [%0], %1;" :: "r"(addr), "r"(cnt) : "memory")
#define MBARRIER_EXPECT_TX(addr, bytes) \
    asm volatile("mbarrier.arrive.expect_tx.shared.b64 _, [%0], %1;" :: "r"(addr), "r"(bytes) : "memory")
#define MBARRIER_WAIT_PARITY(addr, parity) do { \
    uint32_t _m = (addr); uint32_t _p = (parity); uint32_t _d; \
    asm volatile("{\n\t.reg .pred p;\n\t" \
        "mbarrier.try_wait.parity.acquire.cta.shared::cta.b64 p, [%1], %2;\n\t" \
        "selp.b32 %0, 1, 0, p;\n\t}" : "=r"(_d) : "r"(_m), "r"(_p) : "memory"); \
    if (!_d) { \
        asm volatile("{\n\t.reg .pred P1;\n\t" \
            "WL_%=:\n\t" \
            "mbarrier.try_wait.parity.acquire.cta.shared::cta.b64 P1, [%0], %1, 0x989680;\n\t" \
            "@P1 bra.uni WD_%=;\n\t" \
            "bra.uni WL_%=;\n\t" \
            "WD_%=:\n\t}" :: "r"(_m), "r"(_p) : "memory"); \
    } \
} while (0)
#define TMA_LOAD_2D(saddr, tmap, cx, cy, mbar) \
    asm volatile("cp.async.bulk.tensor.2d.shared::cta.global.tile.mbarrier::complete_tx::bytes " \
                 "[%0], [%1, {%2, %3}], [%4];" \
                 :: "r"(saddr), "l"(tmap), "r"(cx), "r"(cy), "r"(mbar) : "memory")

__device__ __forceinline__ void mma_bf16(float* c, const uint32_t* a, const uint32_t* b) {
    asm volatile("mma.sync.aligned.m16n8k16.row.col.f32.bf16.bf16.f32 "
        "{%0,%1,%2,%3}, {%4,%5,%6,%7}, {%8,%9}, {%0,%1,%2,%3};"
        : "+f"(c[0]), "+f"(c[1]), "+f"(c[2]), "+f"(c[3])
        : "r"(a[0]), "r"(a[1]), "r"(a[2]), "r"(a[3]), "r"(b[0]), "r"(b[1]));
}
__device__ __forceinline__ void ldsm_x4(uint32_t* r, uint32_t a) {
    asm volatile("ldmatrix.sync.aligned.m8n8.x4.shared.b16 {%0,%1,%2,%3}, [%4];"
        : "=r"(r[0]), "=r"(r[1]), "=r"(r[2]), "=r"(r[3]) : "r"(a));
}
__device__ __forceinline__ void ldsm_x2(uint32_t* r, uint32_t a) {
    asm volatile("ldmatrix.sync.aligned.m8n8.x2.shared.b16 {%0,%1}, [%2];"
        : "=r"(r[0]), "=r"(r[1]) : "r"(a));
}
__device__ __forceinline__ void ldsm_x2t(uint32_t* r, uint32_t a) {
    asm volatile("ldmatrix.sync.aligned.m8n8.x2.trans.shared.b16 {%0,%1}, [%2];"
        : "=r"(r[0]), "=r"(r[1]) : "r"(a));
}
__device__ __forceinline__ void bsplit2(float x, float y, uint32_t& hi, uint32_t& lo) {
    __nv_bfloat16 hx = __float2bfloat16_rn(x), hy = __float2bfloat16_rn(y);
    __nv_bfloat16 lx = __float2bfloat16_rn(x - __bfloat162float(hx));
    __nv_bfloat16 ly = __float2bfloat16_rn(y - __bfloat162float(hy));
    hi = ((uint32_t)__bfloat16_as_ushort(hy) << 16) | __bfloat16_as_ushort(hx);
    lo = ((uint32_t)__bfloat16_as_ushort(ly) << 16) | __bfloat16_as_ushort(lx);
}

// ---------------------------------------------------------------------------
// GEMM (R12): TMA tiles (SW128), ldmatrix with per-lane swizzled addresses.
// CTA 64x128, warptile 32x32, 2 CTAs/SM.
// ---------------------------------------------------------------------------
__global__ __launch_bounds__(256, 2) void gemm_tma(
    const __grid_constant__ CUtensorMap tAh, const __grid_constant__ CUtensorMap tAl,
    const __grid_constant__ CUtensorMap tBh, const __grid_constant__ CUtensorMap tBl,
    const float* __restrict__ bias, float* __restrict__ C, int Ntot)
{
    extern __shared__ __align__(1024) char gsm[];
    const uint32_t sb0  = smem_u32(gsm);
    const uint32_t ctrl = sb0;
    const uint32_t tile = sb0 + 1024;

    const int tid = threadIdx.x;
    const int m0  = blockIdx.x * GBM;
    const int n0  = blockIdx.y * GBN;

    const int wid  = tid >> 5, lane = tid & 31;
    const int wm   = wid & 1;
    const int wn   = wid >> 1;
    const int gid  = lane >> 2;
    const int tig  = lane & 3;
    const int l15  = lane & 15;

    const uint32_t a_row  = (uint32_t)(wm * 32 + l15);
    const uint32_t a_colh = (uint32_t)((lane >> 4) << 4);
    const uint32_t b_row  = (uint32_t)(wn * 32 + (lane & 7));
    const uint32_t b_colh = (uint32_t)(((lane >> 3) & 1) << 4);

    if (tid == 0) { MBARRIER_INIT(ctrl, 1); MBARRIER_INIT(ctrl + 8, 1); }
    __syncthreads();

    auto issue = [&](int s, int k0) {
        const uint32_t st = tile + s * STB;
        MBARRIER_EXPECT_TX(ctrl + s * 8, STB);
        TMA_LOAD_2D(st,                   &tAh, k0, m0, ctrl + s * 8);
        TMA_LOAD_2D(st + A_PL,            &tAl, k0, m0, ctrl + s * 8);
        TMA_LOAD_2D(st + 2 * A_PL,        &tBh, k0, n0, ctrl + s * 8);
        TMA_LOAD_2D(st + 2 * A_PL + B_PL, &tBl, k0, n0, ctrl + s * 8);
    };

    float acc[2][4][4];
#pragma unroll
    for (int a = 0; a < 2; ++a)
#pragma unroll
        for (int b = 0; b < 4; ++b)
#pragma unroll
            for (int c = 0; c < 4; ++c) acc[a][b][c] = 0.0f;

    if (tid == 0) { issue(0, 0); issue(1, GBK); }

    for (int it = 0; it < NCH; ++it) {
        const int s = it & 1;
        MBARRIER_WAIT_PARITY(ctrl + s * 8, (it >> 1) & 1);
        const uint32_t ss = tile + s * STB;

#pragma unroll
        for (int ks = 0; ks < 4; ++ks) {
            const uint32_t kofs = (uint32_t)(ks * 32);

            uint32_t ah[2][4], al[2][4];
#pragma unroll
            for (int mt = 0; mt < 2; ++mt) {
                const uint32_t r  = a_row + mt * 16;
                const uint32_t c  = (kofs + a_colh) ^ ((r & 7) * 16);
                const uint32_t ad = ss + r * 128 + c;
                ldsm_x4(ah[mt], ad);
                ldsm_x4(al[mt], ad + A_PL);
            }
            uint32_t bh[4][2], bl[4][2];
#pragma unroll
            for (int nt = 0; nt < 4; ++nt) {
                const uint32_t r  = b_row + nt * 8;
                const uint32_t c  = (kofs + b_colh) ^ ((r & 7) * 16);
                const uint32_t bd = ss + 2 * A_PL + r * 128 + c;
                ldsm_x2(bh[nt], bd);
                ldsm_x2(bl[nt], bd + B_PL);
            }
#pragma unroll
            for (int mt = 0; mt < 2; ++mt)
#pragma unroll
                for (int nt = 0; nt < 4; ++nt)
                    mma_bf16(acc[mt][nt], ah[mt], bh[nt]);
#pragma unroll
            for (int mt = 0; mt < 2; ++mt)
#pragma unroll
                for (int nt = 0; nt < 4; ++nt)
                    mma_bf16(acc[mt][nt], ah[mt], bl[nt]);
#pragma unroll
            for (int mt = 0; mt < 2; ++mt)
#pragma unroll
                for (int nt = 0; nt < 4; ++nt)
                    mma_bf16(acc[mt][nt], al[mt], bh[nt]);
        }
        __syncthreads();
        if (tid == 0 && it + 2 < NCH) issue(s, (it + 2) * GBK);
    }

#pragma unroll
    for (int mt = 0; mt < 2; ++mt) {
#pragma unroll
        for (int nt = 0; nt < 4; ++nt) {
            const int row = m0 + wm * 32 + mt * 16 + gid;
            const int col = n0 + wn * 32 + nt * 8 + tig * 2;
            const float b0 = bias[col], b1 = bias[col + 1];
            float2 v0 = {acc[mt][nt][0] + b0, acc[mt][nt][1] + b1};
            float2 v1 = {acc[mt][nt][2] + b0, acc[mt][nt][3] + b1};
            *(float2*)(C + (size_t)row * Ntot + col)       = v0;
            *(float2*)(C + (size_t)(row + 8) * Ntot + col) = v1;
        }
    }
}

// ---------------------------------------------------------------------------
__global__ __launch_bounds__(256) void split_bf16(
    const float4* __restrict__ in, uint2* __restrict__ hi, uint2* __restrict__ lo, int n4)
{
    const int i = blockIdx.x * 256 + threadIdx.x;
    if (i >= n4) return;
    float4 v = in[i];
    uint32_t H0, L0, H1, L1;
    bsplit2(v.x, v.y, H0, L0);
    bsplit2(v.z, v.w, H1, L1);
    hi[i] = make_uint2(H0, H1);
    lo[i] = make_uint2(L0, L1);
}

__global__ __launch_bounds__(256) void transpose_split(
    const float* __restrict__ W,
    __nv_bfloat16* __restrict__ Whi, __nv_bfloat16* __restrict__ Wlo, int K, int N)
{
    __shared__ float t[32][33];
    const int n0 = blockIdx.x * 32, k0 = blockIdx.y * 32;
    const int tx = threadIdx.x, ty = threadIdx.y;
#pragma unroll
    for (int i = 0; i < 32; i += 8)
        t[ty + i][tx] = W[(size_t)(k0 + ty + i) * N + n0 + tx];
    __syncthreads();
#pragma unroll
    for (int i = 0; i < 32; i += 8) {
        float x = t[tx][ty + i];
        __nv_bfloat16 h = __float2bfloat16_rn(x);
        __nv_bfloat16 l = __float2bfloat16_rn(x - __bfloat162float(h));
        const size_t idx = (size_t)(n0 + ty + i) * K + k0 + tx;
        Whi[idx] = h;
        Wlo[idx] = l;
    }
}

// ---------------------------------------------------------------------------
// RMSNorm + rotary; emits split-bf16 q (pre-scaled), k, and v planes.
// ---------------------------------------------------------------------------
__global__ __launch_bounds__(256) void rms_rope_split(
    const float* __restrict__ qkv,
    const float* __restrict__ gq, const float* __restrict__ gk,
    const float* __restrict__ fcos, const float* __restrict__ fsin,
    __nv_bfloat16* __restrict__ qh, __nv_bfloat16* __restrict__ ql,
    __nv_bfloat16* __restrict__ kh, __nv_bfloat16* __restrict__ kl,
    __nv_bfloat16* __restrict__ vh, __nv_bfloat16* __restrict__ vl)
{
    const int t   = blockIdx.x;
    const int l   = t & (SEQ - 1);
    const int tid = threadIdx.x;

    const float* qrow = qkv + (size_t)t * QKV_COLS;
    const float* krow = qrow + DIMN;
    const float* vrow = qrow + 2 * DIMN;

    float sq = 0.0f, sk = 0.0f;
    for (int i = tid; i < DIMN; i += 256) {
        float a = qrow[i]; sq = fmaf(a, a, sq);
        float b = krow[i]; sk = fmaf(b, b, sk);
    }
#pragma unroll
    for (int off = 16; off; off >>= 1) {
        sq += __shfl_xor_sync(0xffffffffu, sq, off);
        sk += __shfl_xor_sync(0xffffffffu, sk, off);
    }
    __shared__ float redq[8], redk[8];
    __shared__ float bq, bk;
    const int warp = tid >> 5, lane = tid & 31;
    if (lane == 0) { redq[warp] = sq; redk[warp] = sk; }
    __syncthreads();
    if (tid == 0) {
        float a = 0.0f, b = 0.0f;
#pragma unroll
        for (int w = 0; w < 8; ++w) { a += redq[w]; b += redk[w]; }
        bq = a; bk = b;
    }
    __syncthreads();
    const float rq = rsqrtf(bq * (1.0f / DIMN) + EPSV);
    const float rk = rsqrtf(bk * (1.0f / DIMN) + EPSV);

    const size_t ob = (size_t)t * DIMN;
    for (int p = tid; p < DIMN / 2; p += 256) {
        const int head = p >> 6;
        const int i2   = (p & 63) * 2;
        const int ce   = head * HDIM + i2;
        const int co   = ce + 1;
        const float ccos = fcos[l * HDIM + i2];
        const float csin = fsin[l * HDIM + i2 + 1];

        float xe = qrow[ce] * rq * gq[ce];
        float xo = qrow[co] * rq * gq[co];
        float qe = (xe * ccos - xo * csin) * SCALEV;
        float qo = (xe * csin + xo * ccos) * SCALEV;
        uint32_t H, L;
        bsplit2(qe, qo, H, L);
        *(uint32_t*)(qh + ob + ce) = H;
        *(uint32_t*)(ql + ob + ce) = L;

        xe = krow[ce] * rk * gk[ce];
        xo = krow[co] * rk * gk[co];
        float ke = xe * ccos - xo * csin;
        float ko = xe * csin + xo * ccos;
        bsplit2(ke, ko, H, L);
        *(uint32_t*)(kh + ob + ce) = H;
        *(uint32_t*)(kl + ob + ce) = L;

        float v0 = vrow[ce], v1 = vrow[co];
        bsplit2(v0, v1, H, L);
        *(uint32_t*)(vh + ob + ce) = H;
        *(uint32_t*)(vl + ob + ce) = L;
    }
}

// ---------------------------------------------------------------------------
// Tensor-core flash attention. Br=64, Bc=32, D=128, 128 threads, 2 CTAs/SM.
// ---------------------------------------------------------------------------
__global__ __launch_bounds__(128, 2) void flash_mma(
    const __nv_bfloat16* __restrict__ qhp, const __nv_bfloat16* __restrict__ qlp,
    const __nv_bfloat16* __restrict__ khp, const __nv_bfloat16* __restrict__ klp,
    const __nv_bfloat16* __restrict__ vhp, const __nv_bfloat16* __restrict__ vlp,
    __nv_bfloat16* __restrict__ ohi, __nv_bfloat16* __restrict__ olo)
{
    extern __shared__ char fsm[];
    const uint32_t sb = smem_u32(fsm);

    const int qb = blockIdx.x, bh = blockIdx.y;
    const int b  = bh / NHEADS, h = bh % NHEADS;
    const int tid = threadIdx.x, wid = tid >> 5, lane = tid & 31;
    const int gid = lane >> 2, tig = lane & 3;
    const int l15 = lane & 15;
    const int hofs = h * HDIM;
    const size_t qrow0 = (size_t)(b * SEQ + qb * FBR);
    const size_t krow0 = (size_t)(b * SEQ);

    // Q load: 2 planes x 64 rows x 16 chunks = 2048 cp16 (joins group 0)
    for (int i = 0; i < 16; ++i) {
        const int idx = tid + 128 * i;        // 0..2047
        const int pl  = idx >> 10;
        const int r   = (idx >> 4) & 63;
        const int c   = idx & 15;
        const __nv_bfloat16* src = (pl ? qlp : qhp) + (qrow0 + r) * DIMN + hofs + c * 8;
        cp16(sb + pl * FQ1 + r * FROWB + c * 16, src);
    }
    auto loadkv = [&](int s, int kb) {
        const uint32_t st = sb + 2 * FQ1 + s * FSTG;
        const size_t kr = krow0 + (size_t)kb * FBC;
        for (int i = 0; i < 16; ++i) {
            const int idx = tid + 128 * i;    // 0..2047
            const int pl  = idx >> 9;         // 0..3
            const int r   = (idx >> 4) & 31;
            const int c   = idx & 15;
            const __nv_bfloat16* base = (pl == 0) ? khp : (pl == 1) ? klp
                                      : (pl == 2) ? vhp : vlp;
            cp16(st + pl * FKPL + r * FROWB + c * 16, base + (kr + r) * DIMN + hofs + c * 8);
        }
        cp_commit();
    };
    loadkv(0, 0);
    loadkv(1, 1);

    float oacc[16][4];
#pragma unroll
    for (int d = 0; d < 16; ++d)
#pragma unroll
        for (int c = 0; c < 4; ++c) oacc[d][c] = 0.0f;
    float mrow[2] = {-1e30f, -1e30f};
    float lrow[2] = {0.0f, 0.0f};

    const int qrow = wid * 16 + l15;              // 0..63
    const uint32_t qcol = ((lane >> 4) & 1) * 16;
    const int krw  = l15 & 7;
    const uint32_t kcadd = ((l15 >> 3) & 1) * 16;

    for (int kb = 0; kb < SEQ / FBC; ++kb) {      // 32 steps
        cp_wait1();
        __syncthreads();
        const uint32_t st = sb + 2 * FQ1 + (kb & 1) * FSTG;
        const uint32_t kh = st, kl = st + FKPL, vh = st + 2 * FKPL, vl = st + 3 * FKPL;

        // ---- S = Q K^T (3-pass split), 4 n-tiles over Bc=32 ----
        float sacc[4][4];
#pragma unroll
        for (int nt = 0; nt < 4; ++nt)
#pragma unroll
            for (int c = 0; c < 4; ++c) sacc[nt][c] = 0.0f;

#pragma unroll
        for (int kc = 0; kc < 8; ++kc) {
            uint32_t aqh[4], aql[4];
            ldsm_x4(aqh, sb + qrow * FROWB + kc * 32 + qcol);
            ldsm_x4(aql, sb + FQ1 + qrow * FROWB + kc * 32 + qcol);
            const uint32_t kcol = kc * 32 + kcadd;
#pragma unroll
            for (int nt = 0; nt < 4; ++nt) {
                uint32_t bkh[2], bkl[2];
                ldsm_x2(bkh, kh + (nt * 8 + krw) * FROWB + kcol);
                ldsm_x2(bkl, kl + (nt * 8 + krw) * FROWB + kcol);
                mma_bf16(sacc[nt], aqh, bkh);
                mma_bf16(sacc[nt], aqh, bkl);
                mma_bf16(sacc[nt], aql, bkh);
            }
        }

        // ---- online softmax ----
        float mx0 = sacc[0][0], mx1 = sacc[0][2];
#pragma unroll
        for (int nt = 0; nt < 4; ++nt) {
            mx0 = fmaxf(mx0, fmaxf(sacc[nt][0], sacc[nt][1]));
            mx1 = fmaxf(mx1, fmaxf(sacc[nt][2], sacc[nt][3]));
        }
        mx0 = fmaxf(mx0, __shfl_xor_sync(0xffffffffu, mx0, 1));
        mx0 = fmaxf(mx0, __shfl_xor_sync(0xffffffffu, mx0, 2));
        mx1 = fmaxf(mx1, __shfl_xor_sync(0xffffffffu, mx1, 1));
        mx1 = fmaxf(mx1, __shfl_xor_sync(0xffffffffu, mx1, 2));
        const float mn0 = fmaxf(mrow[0], mx0);
        const float mn1 = fmaxf(mrow[1], mx1);
        const float al0 = __expf(mrow[0] - mn0);
        const float al1 = __expf(mrow[1] - mn1);
        mrow[0] = mn0; mrow[1] = mn1;

        float rs0 = 0.0f, rs1 = 0.0f;
#pragma unroll
        for (int nt = 0; nt < 4; ++nt) {
            sacc[nt][0] = __expf(sacc[nt][0] - mn0);
            sacc[nt][1] = __expf(sacc[nt][1] - mn0);
            sacc[nt][2] = __expf(sacc[nt][2] - mn1);
            sacc[nt][3] = __expf(sacc[nt][3] - mn1);
            rs0 += sacc[nt][0] + sacc[nt][1];
            rs1 += sacc[nt][2] + sacc[nt][3];
        }
        rs0 += __shfl_xor_sync(0xffffffffu, rs0, 1);
        rs0 += __shfl_xor_sync(0xffffffffu, rs0, 2);
        rs1 += __shfl_xor_sync(0xffffffffu, rs1, 1);
        rs1 += __shfl_xor_sync(0xffffffffu, rs1, 2);
        lrow[0] = lrow[0] * al0 + rs0;
        lrow[1] = lrow[1] * al1 + rs1;
#pragma unroll
        for (int d = 0; d < 16; ++d) {
            oacc[d][0] *= al0; oacc[d][1] *= al0;
            oacc[d][2] *= al1; oacc[d][3] *= al1;
        }

        // ---- O += P V (3-pass split), 2 k-steps over Bc=32 ----
#pragma unroll
        for (int kc2 = 0; kc2 < 2; ++kc2) {
            uint32_t aph[4], apl[4];
            bsplit2(sacc[2 * kc2][0],     sacc[2 * kc2][1],     aph[0], apl[0]);
            bsplit2(sacc[2 * kc2][2],     sacc[2 * kc2][3],     aph[1], apl[1]);
            bsplit2(sacc[2 * kc2 + 1][0], sacc[2 * kc2 + 1][1], aph[2], apl[2]);
            bsplit2(sacc[2 * kc2 + 1][2], sacc[2 * kc2 + 1][3], aph[3], apl[3]);
            const uint32_t vr = (kc2 * 16 + l15) * FROWB;
#pragma unroll
            for (int dt = 0; dt < 16; ++dt) {
                uint32_t bvh[2], bvl[2];
                ldsm_x2t(bvh, vh + vr + dt * 16);
                ldsm_x2t(bvl, vl + vr + dt * 16);
                mma_bf16(oacc[dt], aph, bvh);
                mma_bf16(oacc[dt], aph, bvl);
                mma_bf16(oacc[dt], apl, bvh);
            }
        }
        __syncthreads();
        if (kb + 2 < SEQ / FBC) loadkv(kb & 1, kb + 2);
    }

    // ---- epilogue ----
#pragma unroll
    for (int i = 0; i < 2; ++i) {
        const float inv = 1.0f / lrow[i];
        const size_t base =
            (qrow0 + (size_t)(wid * 16 + gid + i * 8)) * DIMN + hofs + tig * 2;
#pragma unroll
        for (int dt = 0; dt < 16; ++dt) {
            uint32_t H, L;
            bsplit2(oacc[dt][2 * i] * inv, oacc[dt][2 * i + 1] * inv, H, L);
            *(uint32_t*)(ohi + base + dt * 8) = H;
            *(uint32_t*)(olo + base + dt * 8) = L;
        }
    }
}

// ---------------------------------------------------------------------------
// Host side
// ---------------------------------------------------------------------------
typedef CUresult (CUDAAPI *EncodeTiledFn)(
    CUtensorMap*, CUtensorMapDataType, cuuint32_t, void*,
    const cuuint64_t*, const cuuint64_t*, const cuuint32_t*, const cuuint32_t*,
    CUtensorMapInterleave, CUtensorMapSwizzle, CUtensorMapL2promotion,
    CUtensorMapFloatOOBfill);

static void make_map_bf16(EncodeTiledFn enc, CUtensorMap* m, const void* p,
                          unsigned long long d0, unsigned long long d1,
                          unsigned b0, unsigned b1)
{
    cuuint64_t dims[2]    = {d0, d1};
    cuuint64_t strides[1] = {d0 * 2};
    cuuint32_t box[2]     = {b0, b1};
    cuuint32_t es[2]      = {1, 1};
    enc(m, CU_TENSOR_MAP_DATA_TYPE_BFLOAT16, 2, (void*)p, dims, strides, box, es,
        CU_TENSOR_MAP_INTERLEAVE_NONE, CU_TENSOR_MAP_SWIZZLE_128B,
        CU_TENSOR_MAP_L2_PROMOTION_L2_128B, CU_TENSOR_MAP_FLOAT_OOB_FILL_NONE);
}

extern "C" void kernel_launch(void* const* d_in, const int* in_sizes, int n_in,
                              void* d_out, int out_size)
{
    const float* X    = (const float*)d_in[0];
    const float* fcos = (const float*)d_in[1];
    const float* fsin = (const float*)d_in[2];
    const float* Wqkv = (const float*)d_in[3];
    const float* bqkv = (const float*)d_in[4];
    const float* gq   = (const float*)d_in[5];
    const float* gk   = (const float*)d_in[6];
    const float* Wout = (const float*)d_in[7];
    const float* bout = (const float*)d_in[8];
    float* out = (float*)d_out;

    float *qkvbuf;
    __nv_bfloat16 *xhi, *xlo, *ahi, *alo, *wqhi, *wqlo, *wohi, *wolo;
    __nv_bfloat16 *qh, *ql, *kh, *kl, *vh, *vl;
    cudaGetSymbolAddress((void**)&qkvbuf, g_qkv);
    cudaGetSymbolAddress((void**)&xhi, g_xhi);
    cudaGetSymbolAddress((void**)&xlo, g_xlo);
    cudaGetSymbolAddress((void**)&ahi, g_ahi);
    cudaGetSymbolAddress((void**)&alo, g_alo);
    cudaGetSymbolAddress((void**)&wqhi, g_wqhi);
    cudaGetSymbolAddress((void**)&wqlo, g_wqlo);
    cudaGetSymbolAddress((void**)&wohi, g_wohi);
    cudaGetSymbolAddress((void**)&wolo, g_wolo);
    cudaGetSymbolAddress((void**)&qh, g_qh);
    cudaGetSymbolAddress((void**)&ql, g_ql);
    cudaGetSymbolAddress((void**)&kh, g_kh);
    cudaGetSymbolAddress((void**)&kl, g_kl);
    cudaGetSymbolAddress((void**)&vh, g_vh);
    cudaGetSymbolAddress((void**)&vl, g_vl);

    EncodeTiledFn enc = nullptr;
    cudaDriverEntryPointQueryResult qr;
    cudaGetDriverEntryPoint("cuTensorMapEncodeTiled", (void**)&enc,
                            cudaEnableDefault, &qr);

    CUtensorMap tXh, tXl, tWqh, tWql, tAh, tAl, tWoh, tWol;
    make_map_bf16(enc, &tXh,  xhi,  DIMN, TOKENS,   GBK, GBM);
    make_map_bf16(enc, &tXl,  xlo,  DIMN, TOKENS,   GBK, GBM);
    make_map_bf16(enc, &tWqh, wqhi, DIMN, QKV_COLS, GBK, GBN);
    make_map_bf16(enc, &tWql, wqlo, DIMN, QKV_COLS, GBK, GBN);
    make_map_bf16(enc, &tAh,  ahi,  DIMN, TOKENS,   GBK, GBM);
    make_map_bf16(enc, &tAl,  alo,  DIMN, TOKENS,   GBK, GBM);
    make_map_bf16(enc, &tWoh, wohi, DIMN, DIMN,     GBK, GBN);
    make_map_bf16(enc, &tWol, wolo, DIMN, DIMN,     GBK, GBN);

    cudaFuncSetAttribute(gemm_tma, cudaFuncAttributeMaxDynamicSharedMemorySize, GSMEM);
    cudaFuncSetAttribute(flash_mma, cudaFuncAttributeMaxDynamicSharedMemorySize, FSMEM);

    // 0) precision-split operands
    split_bf16<<<(TOKENS * DIMN / 4 + 255) / 256, 256>>>(
        (const float4*)X, (uint2*)xhi, (uint2*)xlo, TOKENS * DIMN / 4);
    transpose_split<<<dim3(QKV_COLS / 32, DIMN / 32), dim3(32, 8)>>>(
        Wqkv, wqhi, wqlo, DIMN, QKV_COLS);
    transpose_split<<<dim3(DIMN / 32, DIMN / 32), dim3(32, 8)>>>(
        Wout, wohi, wolo, DIMN, DIMN);

    // 1) qkv = X @ W_qkv + b_qkv
    gemm_tma<<<dim3(TOKENS / GBM, QKV_COLS / GBN), 256, GSMEM>>>(
        tXh, tXl, tWqh, tWql, bqkv, qkvbuf, QKV_COLS);

    // 2) RMSNorm + RoPE -> split planes
    rms_rope_split<<<TOKENS, 256>>>(qkvbuf, gq, gk, fcos, fsin,
                                    qh, ql, kh, kl, vh, vl);

    // 3) tensor-core flash attention (Br=64, 2 CTAs/SM) -> bf16 hi/lo planes
    flash_mma<<<dim3(SEQ / FBR, BATCH * NHEADS), 128, FSMEM>>>(
        qh, ql, kh, kl, vh, vl, ahi, alo);

    // 4) out = attn @ W_out + b_out
    gemm_tma<<<dim3(TOKENS / GBM, DIMN / GBN), 256, GSMEM>>>(
        tAh, tAl, tWoh, tWol, bout, out, DIMN);
}

// round 14
// speedup vs baseline: 9.9196x; 2.4097x over previous
#include <cuda.h>
#include <cuda_runtime.h>
#include <cuda_bf16.h>
#include <cuda_fp16.h>
#include <math.h>
#include <stdint.h>

// Problem constants
#define DIMN     5120
#define NHEADS   40
#define HDIM     128
#define BATCH    2
#define SEQ      1024
#define TOKENS   (BATCH * SEQ)        // 2048
#define QKV_COLS (3 * DIMN)           // 15360
#define EPSV     1e-6f
#define SCALEV   0.08838834764831845f // 128^-0.5
#define LOG2E    1.4426950408889634f

// GEMM tiling: CTA 128x128, 8 warps of 32x64, BK=64, 2-stage TMA, 2 CTAs/SM
#define GBM 128
#define GBN 128
#define GBK 64
#define A_PL (GBM * GBK * 2)              // 16384 B
#define B_PL (GBN * GBK * 2)              // 16384 B
#define STB  (A_PL + B_PL)                // 32768 per stage
#define GSMEM (1024 + 2 * STB)            // 66560 -> 2 CTAs/SM
#define NCH (DIMN / GBK)                  // 80

// Flash tiling: Br=64 (4 warps x m16), Bc=32, D=128, single fp16 planes
#define FBR 64
#define FBC 32
#define FROWB 272                          // 128 fp16 + 16B pad
#define FQ1  (FBR * FROWB)                 // 17408
#define FKPL (FBC * FROWB)                 // 8704
#define FSTG (2 * FKPL)                    // 17408 (k, v)
#define FSMEM (FQ1 + 2 * FSTG)             // 52224 -> 3 CTAs/SM

// Scratch (no allocations allowed)
__device__ float   g_qkv[(size_t)TOKENS * QKV_COLS];
__device__ __half  g_xh[(size_t)TOKENS * DIMN];
__device__ __half  g_a[(size_t)TOKENS * DIMN];
__device__ __half  g_wq[(size_t)QKV_COLS * DIMN];
__device__ __half  g_wo[(size_t)DIMN * DIMN];
__device__ __half  g_q[(size_t)TOKENS * DIMN];
__device__ __half  g_k[(size_t)TOKENS * DIMN];
__device__ __half  g_v[(size_t)TOKENS * DIMN];

// ---------------------------------------------------------------------------
__device__ __forceinline__ uint32_t smem_u32(const void* p) {
    uint32_t a;
    asm("{ .reg .u64 t; cvta.to.shared.u64 t, %1; cvt.u32.u64 %0, t; }" : "=r"(a) : "l"(p));
    return a;
}
__device__ __forceinline__ void cp16(uint32_t s, const void* g) {
    asm volatile("cp.async.cg.shared.global [%0], [%1], 16;" :: "r"(s), "l"(g));
}
__device__ __forceinline__ void cp_commit() {
    asm volatile("cp.async.commit_group;" ::: "memory");
}
__device__ __forceinline__ void cp_wait1() {
    asm volatile("cp.async.wait_group 1;" ::: "memory");
}
#define MBARRIER_INIT(addr, cnt) \
    asm volatile("mbarrier.init.shared.b64 [%0], %1;" :: "r"(addr), "r"(cnt) : "memory")
#define MBARRIER_EXPECT_TX(addr, bytes) \
    asm volatile("mbarrier.arrive.expect_tx.shared.b64 _, [%0], %1;" :: "r"(addr), "r"(bytes) : "memory")
#define MBARRIER_WAIT_PARITY(addr, parity) do { \
    uint32_t _m = (addr); uint32_t _p = (parity); uint32_t _d; \
    asm volatile("{\n\t.reg .pred p;\n\t" \
        "mbarrier.try_wait.parity.acquire.cta.shared::cta.b64 p, [%1], %2;\n\t" \
        "selp.b32 %0, 1, 0, p;\n\t}" : "=r"(_d) : "r"(_m), "r"(_p) : "memory"); \
    if (!_d) { \
        asm volatile("{\n\t.reg .pred P1;\n\t" \
            "WL_%=:\n\t" \
            "mbarrier.try_wait.parity.acquire.cta.shared::cta.b64 P1, [%0], %1, 0x989680;\n\t" \
            "@P1 bra.uni WD_%=;\n\t" \
            "bra.uni WL_%=;\n\t" \
            "WD_%=:\n\t}" :: "r"(_m), "r"(_p) : "memory"); \
    } \
} while (0)
#define TMA_LOAD_2D(saddr, tmap, cx, cy, mbar) \
    asm volatile("cp.async.bulk.tensor.2d.shared::cta.global.tile.mbarrier::complete_tx::bytes " \
                 "[%0], [%1, {%2, %3}], [%4];" \
                 :: "r"(saddr), "l"(tmap), "r"(cx), "r"(cy), "r"(mbar) : "memory")

__device__ __forceinline__ void mma_f16(float* c, const uint32_t* a, const uint32_t* b) {
    asm volatile("mma.sync.aligned.m16n8k16.row.col.f32.f16.f16.f32 "
        "{%0,%1,%2,%3}, {%4,%5,%6,%7}, {%8,%9}, {%0,%1,%2,%3};"
        : "+f"(c[0]), "+f"(c[1]), "+f"(c[2]), "+f"(c[3])
        : "r"(a[0]), "r"(a[1]), "r"(a[2]), "r"(a[3]), "r"(b[0]), "r"(b[1]));
}
__device__ __forceinline__ void ldsm_x4(uint32_t* r, uint32_t a) {
    asm volatile("ldmatrix.sync.aligned.m8n8.x4.shared.b16 {%0,%1,%2,%3}, [%4];"
        : "=r"(r[0]), "=r"(r[1]), "=r"(r[2]), "=r"(r[3]) : "r"(a));
}
__device__ __forceinline__ void ldsm_x2(uint32_t* r, uint32_t a) {
    asm volatile("ldmatrix.sync.aligned.m8n8.x2.shared.b16 {%0,%1}, [%2];"
        : "=r"(r[0]), "=r"(r[1]) : "r"(a));
}
__device__ __forceinline__ void ldsm_x2t(uint32_t* r, uint32_t a) {
    asm volatile("ldmatrix.sync.aligned.m8n8.x2.trans.shared.b16 {%0,%1}, [%2];"
        : "=r"(r[0]), "=r"(r[1]) : "r"(a));
}
__device__ __forceinline__ uint32_t hpack2(float x, float y) {
    __half hx = __float2half_rn(x), hy = __float2half_rn(y);
    return ((uint32_t)__half_as_ushort(hy) << 16) | __half_as_ushort(hx);
}

// ---------------------------------------------------------------------------
// GEMM: C[M, Ntot] = A @ B^T + bias, single-pass fp16, fp32 accum.
// TMA tiles (SW128, 128B rows), ldmatrix with per-lane swizzled addresses.
// CTA 128x128, warptile 32x64, 2 CTAs/SM.
// ---------------------------------------------------------------------------
__global__ __launch_bounds__(256, 2) void gemm_f16(
    const __grid_constant__ CUtensorMap tA, const __grid_constant__ CUtensorMap tB,
    const float* __restrict__ bias, float* __restrict__ C, int Ntot)
{
    extern __shared__ __align__(1024) char gsm[];
    const uint32_t sb0  = smem_u32(gsm);
    const uint32_t ctrl = sb0;
    const uint32_t tile = sb0 + 1024;

    const int tid = threadIdx.x;
    const int m0  = blockIdx.x * GBM;
    const int n0  = blockIdx.y * GBN;

    const int wid  = tid >> 5, lane = tid & 31;
    const int wm   = wid & 3;        // 4 groups of 32 rows
    const int wn   = wid >> 2;       // 2 groups of 64 cols
    const int gid  = lane >> 2;
    const int tig  = lane & 3;
    const int l15  = lane & 15;

    const uint32_t a_row  = (uint32_t)(wm * 32 + l15);
    const uint32_t a_colh = (uint32_t)((lane >> 4) << 4);
    const uint32_t b_row  = (uint32_t)(wn * 64 + (lane & 7));
    const uint32_t b_colh = (uint32_t)(((lane >> 3) & 1) << 4);

    if (tid == 0) { MBARRIER_INIT(ctrl, 1); MBARRIER_INIT(ctrl + 8, 1); }
    __syncthreads();

    auto issue = [&](int s, int k0) {
        const uint32_t st = tile + s * STB;
        MBARRIER_EXPECT_TX(ctrl + s * 8, STB);
        TMA_LOAD_2D(st,        &tA, k0, m0, ctrl + s * 8);
        TMA_LOAD_2D(st + A_PL, &tB, k0, n0, ctrl + s * 8);
    };

    float acc[2][8][4];
#pragma unroll
    for (int a = 0; a < 2; ++a)
#pragma unroll
        for (int b = 0; b < 8; ++b)
#pragma unroll
            for (int c = 0; c < 4; ++c) acc[a][b][c] = 0.0f;

    if (tid == 0) { issue(0, 0); issue(1, GBK); }

    for (int it = 0; it < NCH; ++it) {
        const int s = it & 1;
        MBARRIER_WAIT_PARITY(ctrl + s * 8, (it >> 1) & 1);
        const uint32_t ss = tile + s * STB;

#pragma unroll
        for (int ks = 0; ks < 4; ++ks) {
            const uint32_t kofs = (uint32_t)(ks * 32);

            uint32_t af[2][4];
#pragma unroll
            for (int mt = 0; mt < 2; ++mt) {
                const uint32_t r = a_row + mt * 16;
                const uint32_t c = (kofs + a_colh) ^ ((r & 7) * 16);
                ldsm_x4(af[mt], ss + r * 128 + c);
            }
            uint32_t bf[8][2];
#pragma unroll
            for (int nt = 0; nt < 8; ++nt) {
                const uint32_t r = b_row + nt * 8;
                const uint32_t c = (kofs + b_colh) ^ ((r & 7) * 16);
                ldsm_x2(bf[nt], ss + A_PL + r * 128 + c);
            }
#pragma unroll
            for (int mt = 0; mt < 2; ++mt)
#pragma unroll
                for (int nt = 0; nt < 8; ++nt)
                    mma_f16(acc[mt][nt], af[mt], bf[nt]);
        }
        __syncthreads();
        if (tid == 0 && it + 2 < NCH) issue(s, (it + 2) * GBK);
    }

#pragma unroll
    for (int mt = 0; mt < 2; ++mt) {
#pragma unroll
        for (int nt = 0; nt < 8; ++nt) {
            const int row = m0 + wm * 32 + mt * 16 + gid;
            const int col = n0 + wn * 64 + nt * 8 + tig * 2;
            const float b0 = bias[col], b1 = bias[col + 1];
            float2 v0 = {acc[mt][nt][0] + b0, acc[mt][nt][1] + b1};
            float2 v1 = {acc[mt][nt][2] + b0, acc[mt][nt][3] + b1};
            *(float2*)(C + (size_t)row * Ntot + col)       = v0;
            *(float2*)(C + (size_t)(row + 8) * Ntot + col) = v1;
        }
    }
}

// ---------------------------------------------------------------------------
__global__ __launch_bounds__(256) void cvt_f16(
    const float4* __restrict__ in, uint2* __restrict__ out, int n4)
{
    const int i = blockIdx.x * 256 + threadIdx.x;
    if (i >= n4) return;
    float4 v = in[i];
    out[i] = make_uint2(hpack2(v.x, v.y), hpack2(v.z, v.w));
}

__global__ __launch_bounds__(256) void transpose_f16(
    const float* __restrict__ W, __half* __restrict__ Wt, int K, int N)
{
    __shared__ float t[32][33];
    const int n0 = blockIdx.x * 32, k0 = blockIdx.y * 32;
    const int tx = threadIdx.x, ty = threadIdx.y;
#pragma unroll
    for (int i = 0; i < 32; i += 8)
        t[ty + i][tx] = W[(size_t)(k0 + ty + i) * N + n0 + tx];
    __syncthreads();
#pragma unroll
    for (int i = 0; i < 32; i += 8)
        Wt[(size_t)(n0 + ty + i) * K + k0 + tx] = __float2half_rn(t[tx][ty + i]);
}

// ---------------------------------------------------------------------------
// RMSNorm + rotary; emits fp16 q (scaled by SCALEV*LOG2E), k, v planes.
// ---------------------------------------------------------------------------
__global__ __launch_bounds__(256) void rms_rope_h(
    const float* __restrict__ qkv,
    const float* __restrict__ gq, const float* __restrict__ gk,
    const float* __restrict__ fcos, const float* __restrict__ fsin,
    __half* __restrict__ qp, __half* __restrict__ kp, __half* __restrict__ vp)
{
    const int t   = blockIdx.x;
    const int l   = t & (SEQ - 1);
    const int tid = threadIdx.x;

    const float* qrow = qkv + (size_t)t * QKV_COLS;
    const float* krow = qrow + DIMN;
    const float* vrow = qrow + 2 * DIMN;

    float sq = 0.0f, sk = 0.0f;
    for (int i = tid; i < DIMN; i += 256) {
        float a = qrow[i]; sq = fmaf(a, a, sq);
        float b = krow[i]; sk = fmaf(b, b, sk);
    }
#pragma unroll
    for (int off = 16; off; off >>= 1) {
        sq += __shfl_xor_sync(0xffffffffu, sq, off);
        sk += __shfl_xor_sync(0xffffffffu, sk, off);
    }
    __shared__ float redq[8], redk[8];
    __shared__ float bq, bk;
    const int warp = tid >> 5, lane = tid & 31;
    if (lane == 0) { redq[warp] = sq; redk[warp] = sk; }
    __syncthreads();
    if (tid == 0) {
        float a = 0.0f, b = 0.0f;
#pragma unroll
        for (int w = 0; w < 8; ++w) { a += redq[w]; b += redk[w]; }
        bq = a; bk = b;
    }
    __syncthreads();
    const float rq = rsqrtf(bq * (1.0f / DIMN) + EPSV);
    const float rk = rsqrtf(bk * (1.0f / DIMN) + EPSV);
    const float qs = SCALEV * LOG2E;

    const size_t ob = (size_t)t * DIMN;
    for (int p = tid; p < DIMN / 2; p += 256) {
        const int head = p >> 6;
        const int i2   = (p & 63) * 2;
        const int ce   = head * HDIM + i2;
        const int co   = ce + 1;
        const float ccos = fcos[l * HDIM + i2];
        const float csin = fsin[l * HDIM + i2 + 1];

        float xe = qrow[ce] * rq * gq[ce];
        float xo = qrow[co] * rq * gq[co];
        *(uint32_t*)(qp + ob + ce) =
            hpack2((xe * ccos - xo * csin) * qs, (xe * csin + xo * ccos) * qs);

        xe = krow[ce] * rk * gk[ce];
        xo = krow[co] * rk * gk[co];
        *(uint32_t*)(kp + ob + ce) =
            hpack2(xe * ccos - xo * csin, xe * csin + xo * ccos);

        *(uint32_t*)(vp + ob + ce) = hpack2(vrow[ce], vrow[co]);
    }
}

// ---------------------------------------------------------------------------
// Flash attention, single-pass fp16. Br=64, Bc=32, D=128, 128 thr, 3 CTAs/SM.
// Softmax in base-2 (q pre-scaled by log2e). Q fragments hoisted to registers.
// ---------------------------------------------------------------------------
__global__ __launch_bounds__(128, 3) void flash_f16(
    const __half* __restrict__ qp, const __half* __restrict__ kp,
    const __half* __restrict__ vp, __half* __restrict__ op)
{
    extern __shared__ char fsm[];
    const uint32_t sb = smem_u32(fsm);

    const int qb = blockIdx.x, bh = blockIdx.y;
    const int b  = bh / NHEADS, h = bh % NHEADS;
    const int tid = threadIdx.x, wid = tid >> 5, lane = tid & 31;
    const int gid = lane >> 2, tig = lane & 3;
    const int l15 = lane & 15;
    const int hofs = h * HDIM;
    const size_t qrow0 = (size_t)(b * SEQ + qb * FBR);
    const size_t krow0 = (size_t)(b * SEQ);

    // Q: 64 rows x 16 chunks = 1024 cp16 (joins group 0)
    for (int i = 0; i < 8; ++i) {
        const int idx = tid + 128 * i;
        const int r   = idx >> 4;
        const int c   = idx & 15;
        cp16(sb + r * FROWB + c * 16, qp + (qrow0 + r) * DIMN + hofs + c * 8);
    }
    auto loadkv = [&](int s, int kb) {
        const uint32_t st = sb + FQ1 + s * FSTG;
        const size_t kr = krow0 + (size_t)kb * FBC;
        for (int i = 0; i < 8; ++i) {
            const int idx = tid + 128 * i;     // 0..1023
            const int pl  = idx >> 9;          // 0: K, 1: V
            const int r   = (idx >> 4) & 31;
            const int c   = idx & 15;
            const __half* base = pl ? vp : kp;
            cp16(st + pl * FKPL + r * FROWB + c * 16, base + (kr + r) * DIMN + hofs + c * 8);
        }
        cp_commit();
    };
    loadkv(0, 0);
    loadkv(1, 1);

    float oacc[16][4];
#pragma unroll
    for (int d = 0; d < 16; ++d)
#pragma unroll
        for (int c = 0; c < 4; ++c) oacc[d][c] = 0.0f;
    float mrow[2] = {-1e30f, -1e30f};
    float lrow[2] = {0.0f, 0.0f};

    const int qrow = wid * 16 + l15;
    const uint32_t qcol = ((lane >> 4) & 1) * 16;
    const int krw  = l15 & 7;
    const uint32_t kcadd = ((l15 >> 3) & 1) * 16;

    // Hoist Q fragments to registers (Q resident after first wait+sync)
    cp_wait1();
    __syncthreads();
    uint32_t qf[8][4];
#pragma unroll
    for (int kc = 0; kc < 8; ++kc)
        ldsm_x4(qf[kc], sb + qrow * FROWB + kc * 32 + qcol);

    for (int kb = 0; kb < SEQ / FBC; ++kb) {
        if (kb) { cp_wait1(); __syncthreads(); }
        const uint32_t st = sb + FQ1 + (kb & 1) * FSTG;
        const uint32_t kh = st, vh = st + FKPL;

        // ---- S = Q K^T ----
        float sacc[4][4];
#pragma unroll
        for (int nt = 0; nt < 4; ++nt)
#pragma unroll
            for (int c = 0; c < 4; ++c) sacc[nt][c] = 0.0f;

#pragma unroll
        for (int kc = 0; kc < 8; ++kc) {
            const uint32_t kcol = kc * 32 + kcadd;
#pragma unroll
            for (int nt = 0; nt < 4; ++nt) {
                uint32_t bk[2];
                ldsm_x2(bk, kh + (nt * 8 + krw) * FROWB + kcol);
                mma_f16(sacc[nt], qf[kc], bk);
            }
        }

        // ---- online softmax (base-2) ----
        float mx0 = sacc[0][0], mx1 = sacc[0][2];
#pragma unroll
        for (int nt = 0; nt < 4; ++nt) {
            mx0 = fmaxf(mx0, fmaxf(sacc[nt][0], sacc[nt][1]));
            mx1 = fmaxf(mx1, fmaxf(sacc[nt][2], sacc[nt][3]));
        }
        mx0 = fmaxf(mx0, __shfl_xor_sync(0xffffffffu, mx0, 1));
        mx0 = fmaxf(mx0, __shfl_xor_sync(0xffffffffu, mx0, 2));
        mx1 = fmaxf(mx1, __shfl_xor_sync(0xffffffffu, mx1, 1));
        mx1 = fmaxf(mx1, __shfl_xor_sync(0xffffffffu, mx1, 2));
        const float mn0 = fmaxf(mrow[0], mx0);
        const float mn1 = fmaxf(mrow[1], mx1);
        const float al0 = exp2f(mrow[0] - mn0);
        const float al1 = exp2f(mrow[1] - mn1);
        mrow[0] = mn0; mrow[1] = mn1;

        float rs0 = 0.0f, rs1 = 0.0f;
#pragma unroll
        for (int nt = 0; nt < 4; ++nt) {
            sacc[nt][0] = exp2f(sacc[nt][0] - mn0);
            sacc[nt][1] = exp2f(sacc[nt][1] - mn0);
            sacc[nt][2] = exp2f(sacc[nt][2] - mn1);
            sacc[nt][3] = exp2f(sacc[nt][3] - mn1);
            rs0 += sacc[nt][0] + sacc[nt][1];
            rs1 += sacc[nt][2] + sacc[nt][3];
        }
        rs0 += __shfl_xor_sync(0xffffffffu, rs0, 1);
        rs0 += __shfl_xor_sync(0xffffffffu, rs0, 2);
        rs1 += __shfl_xor_sync(0xffffffffu, rs1, 1);
        rs1 += __shfl_xor_sync(0xffffffffu, rs1, 2);
        lrow[0] = lrow[0] * al0 + rs0;
        lrow[1] = lrow[1] * al1 + rs1;
#pragma unroll
        for (int d = 0; d < 16; ++d) {
            oacc[d][0] *= al0; oacc[d][1] *= al0;
            oacc[d][2] *= al1; oacc[d][3] *= al1;
        }

        // ---- O += P V ----
#pragma unroll
        for (int kc2 = 0; kc2 < 2; ++kc2) {
            uint32_t ap[4];
            ap[0] = hpack2(sacc[2 * kc2][0],     sacc[2 * kc2][1]);
            ap[1] = hpack2(sacc[2 * kc2][2],     sacc[2 * kc2][3]);
            ap[2] = hpack2(sacc[2 * kc2 + 1][0], sacc[2 * kc2 + 1][1]);
            ap[3] = hpack2(sacc[2 * kc2 + 1][2], sacc[2 * kc2 + 1][3]);
            const uint32_t vr = (kc2 * 16 + l15) * FROWB;
#pragma unroll
            for (int dt = 0; dt < 16; ++dt) {
                uint32_t bv[2];
                ldsm_x2t(bv, vh + vr + dt * 16);
                mma_f16(oacc[dt], ap, bv);
            }
        }
        __syncthreads();
        if (kb + 2 < SEQ / FBC) loadkv(kb & 1, kb + 2);
    }

    // ---- epilogue ----
#pragma unroll
    for (int i = 0; i < 2; ++i) {
        const float inv = 1.0f / lrow[i];
        const size_t base =
            (qrow0 + (size_t)(wid * 16 + gid + i * 8)) * DIMN + hofs + tig * 2;
#pragma unroll
        for (int dt = 0; dt < 16; ++dt)
            *(uint32_t*)(op + base + dt * 8) =
                hpack2(oacc[dt][2 * i] * inv, oacc[dt][2 * i + 1] * inv);
    }
}

// ---------------------------------------------------------------------------
// Host side
// ---------------------------------------------------------------------------
typedef CUresult (CUDAAPI *EncodeTiledFn)(
    CUtensorMap*, CUtensorMapDataType, cuuint32_t, void*,
    const cuuint64_t*, const cuuint64_t*, const cuuint32_t*, const cuuint32_t*,
    CUtensorMapInterleave, CUtensorMapSwizzle, CUtensorMapL2promotion,
    CUtensorMapFloatOOBfill);

static void make_map_f16(EncodeTiledFn enc, CUtensorMap* m, const void* p,
                         unsigned long long d0, unsigned long long d1,
                         unsigned b0, unsigned b1)
{
    cuuint64_t dims[2]    = {d0, d1};
    cuuint64_t strides[1] = {d0 * 2};
    cuuint32_t box[2]     = {b0, b1};
    cuuint32_t es[2]      = {1, 1};
    enc(m, CU_TENSOR_MAP_DATA_TYPE_FLOAT16, 2, (void*)p, dims, strides, box, es,
        CU_TENSOR_MAP_INTERLEAVE_NONE, CU_TENSOR_MAP_SWIZZLE_128B,
        CU_TENSOR_MAP_L2_PROMOTION_L2_128B, CU_TENSOR_MAP_FLOAT_OOB_FILL_NONE);
}

extern "C" void kernel_launch(void* const* d_in, const int* in_sizes, int n_in,
                              void* d_out, int out_size)
{
    const float* X    = (const float*)d_in[0];
    const float* fcos = (const float*)d_in[1];
    const float* fsin = (const float*)d_in[2];
    const float* Wqkv = (const float*)d_in[3];
    const float* bqkv = (const float*)d_in[4];
    const float* gq   = (const float*)d_in[5];
    const float* gk   = (const float*)d_in[6];
    const float* Wout = (const float*)d_in[7];
    const float* bout = (const float*)d_in[8];
    float* out = (float*)d_out;

    float *qkvbuf;
    __half *xh, *ap, *wq, *wo, *qp, *kp, *vp;
    cudaGetSymbolAddress((void**)&qkvbuf, g_qkv);
    cudaGetSymbolAddress((void**)&xh, g_xh);
    cudaGetSymbolAddress((void**)&ap, g_a);
    cudaGetSymbolAddress((void**)&wq, g_wq);
    cudaGetSymbolAddress((void**)&wo, g_wo);
    cudaGetSymbolAddress((void**)&qp, g_q);
    cudaGetSymbolAddress((void**)&kp, g_k);
    cudaGetSymbolAddress((void**)&vp, g_v);

    EncodeTiledFn enc = nullptr;
    cudaDriverEntryPointQueryResult qr;
    cudaGetDriverEntryPoint("cuTensorMapEncodeTiled", (void**)&enc,
                            cudaEnableDefault, &qr);

    CUtensorMap tX, tWq, tA, tWo;
    make_map_f16(enc, &tX,  xh, DIMN, TOKENS,   GBK, GBM);
    make_map_f16(enc, &tWq, wq, DIMN, QKV_COLS, GBK, GBN);
    make_map_f16(enc, &tA,  ap, DIMN, TOKENS,   GBK, GBM);
    make_map_f16(enc, &tWo, wo, DIMN, DIMN,     GBK, GBN);

    cudaFuncSetAttribute(gemm_f16, cudaFuncAttributeMaxDynamicSharedMemorySize, GSMEM);
    cudaFuncSetAttribute(flash_f16, cudaFuncAttributeMaxDynamicSharedMemorySize, FSMEM);

    // 0) fp16 operands
    cvt_f16<<<(TOKENS * DIMN / 4 + 255) / 256, 256>>>(
        (const float4*)X, (uint2*)xh, TOKENS * DIMN / 4);
    transpose_f16<<<dim3(QKV_COLS / 32, DIMN / 32), dim3(32, 8)>>>(
        Wqkv, wq, DIMN, QKV_COLS);
    transpose_f16<<<dim3(DIMN / 32, DIMN / 32), dim3(32, 8)>>>(
        Wout, wo, DIMN, DIMN);

    // 1) qkv = X @ W_qkv + b_qkv
    gemm_f16<<<dim3(TOKENS / GBM, QKV_COLS / GBN), 256, GSMEM>>>(
        tX, tWq, bqkv, qkvbuf, QKV_COLS);

    // 2) RMSNorm + RoPE -> fp16 planes
    rms_rope_h<<<TOKENS, 256>>>(qkvbuf, gq, gk, fcos, fsin, qp, kp, vp);

    // 3) flash attention -> fp16 plane
    flash_f16<<<dim3(SEQ / FBR, BATCH * NHEADS), 128, FSMEM>>>(qp, kp, vp, ap);

    // 4) out = attn @ W_out + b_out
    gemm_f16<<<dim3(TOKENS / GBM, DIMN / GBN), 256, GSMEM>>>(
        tA, tWo, bout, out, DIMN);
}

// round 16
// speedup vs baseline: 10.5536x; 1.0639x over previous
#include <cuda.h>
#include <cuda_runtime.h>
#include <cuda_bf16.h>
#include <cuda_fp16.h>
#include <math.h>
#include <stdint.h>

// Problem constants
#define DIMN     5120
#define NHEADS   40
#define HDIM     128
#define BATCH    2
#define SEQ      1024
#define TOKENS   (BATCH * SEQ)        // 2048
#define QKV_COLS (3 * DIMN)           // 15360
#define EPSV     1e-6f
#define SCALEV   0.08838834764831845f // 128^-0.5
#define LOG2E    1.4426950408889634f

// GEMM tiling: CTA 128x128, 8 warps of 32x64, BK=64, 3-stage TMA, 2 CTAs/SM
#define GBM 128
#define GBN 128
#define GBK 64
#define A_PL (GBM * GBK * 2)              // 16384 B
#define B_PL (GBN * GBK * 2)              // 16384 B
#define STB  (A_PL + B_PL)                // 32768 per stage
#define GSTG 3
#define GSMEM (1024 + GSTG * STB)         // 99328 -> 2 CTAs/SM
#define NCH (DIMN / GBK)                  // 80

// Flash tiling: Br=64 (4 warps x m16), Bc=64, D=128, fp16, 2 CTAs/SM
#define FBR 64
#define FBC 64
#define FROWB 272                          // 128 fp16 + 16B pad
#define FQ1  (FBR * FROWB)                 // 17408
#define FKPL (FBC * FROWB)                 // 17408
#define FSTG (2 * FKPL)                    // 34816 (k, v)
#define FSMEM (FQ1 + 2 * FSTG)             // 87040 -> 2 CTAs/SM

// Scratch (no allocations allowed)
__device__ float   g_qkv[(size_t)TOKENS * QKV_COLS];
__device__ __half  g_xh[(size_t)TOKENS * DIMN];
__device__ __half  g_a[(size_t)TOKENS * DIMN];
__device__ __half  g_wq[(size_t)QKV_COLS * DIMN];
__device__ __half  g_wo[(size_t)DIMN * DIMN];
__device__ __half  g_q[(size_t)TOKENS * DIMN];
__device__ __half  g_k[(size_t)TOKENS * DIMN];
__device__ __half  g_v[(size_t)TOKENS * DIMN];

// ---------------------------------------------------------------------------
__device__ __forceinline__ uint32_t smem_u32(const void* p) {
    uint32_t a;
    asm("{ .reg .u64 t; cvta.to.shared.u64 t, %1; cvt.u32.u64 %0, t; }" : "=r"(a) : "l"(p));
    return a;
}
__device__ __forceinline__ void cp16(uint32_t s, const void* g) {
    asm volatile("cp.async.cg.shared.global [%0], [%1], 16;" :: "r"(s), "l"(g));
}
__device__ __forceinline__ void cp_commit() {
    asm volatile("cp.async.commit_group;" ::: "memory");
}
__device__ __forceinline__ void cp_wait1() {
    asm volatile("cp.async.wait_group 1;" ::: "memory");
}
#define MBARRIER_INIT(addr, cnt) \
    asm volatile("mbarrier.init.shared.b64 [%0], %1;" :: "r"(addr), "r"(cnt) : "memory")
#define MBARRIER_EXPECT_TX(addr, bytes) \
    asm volatile("mbarrier.arrive.expect_tx.shared.b64 _, [%0], %1;" :: "r"(addr), "r"(bytes) : "memory")
#define MBARRIER_WAIT_PARITY(addr, parity) do { \
    uint32_t _m = (addr); uint32_t _p = (parity); uint32_t _d; \
    asm volatile("{\n\t.reg .pred p;\n\t" \
        "mbarrier.try_wait.parity.acquire.cta.shared::cta.b64 p, [%1], %2;\n\t" \
        "selp.b32 %0, 1, 0, p;\n\t}" : "=r"(_d) : "r"(_m), "r"(_p) : "memory"); \
    if (!_d) { \
        asm volatile("{\n\t.reg .pred P1;\n\t" \
            "WL_%=:\n\t" \
            "mbarrier.try_wait.parity.acquire.cta.shared::cta.b64 P1, [%0], %1, 0x989680;\n\t" \
            "@P1 bra.uni WD_%=;\n\t" \
            "bra.uni WL_%=;\n\t" \
            "WD_%=:\n\t}" :: "r"(_m), "r"(_p) : "memory"); \
    } \
} while (0)
#define TMA_LOAD_2D(saddr, tmap, cx, cy, mbar) \
    asm volatile("cp.async.bulk.tensor.2d.shared::cta.global.tile.mbarrier::complete_tx::bytes " \
                 "[%0], [%1, {%2, %3}], [%4];" \
                 :: "r"(saddr), "l"(tmap), "r"(cx), "r"(cy), "r"(mbar) : "memory")

__device__ __forceinline__ void mma_f16(float* c, const uint32_t* a, const uint32_t* b) {
    asm volatile("mma.sync.aligned.m16n8k16.row.col.f32.f16.f16.f32 "
        "{%0,%1,%2,%3}, {%4,%5,%6,%7}, {%8,%9}, {%0,%1,%2,%3};"
        : "+f"(c[0]), "+f"(c[1]), "+f"(c[2]), "+f"(c[3])
        : "r"(a[0]), "r"(a[1]), "r"(a[2]), "r"(a[3]), "r"(b[0]), "r"(b[1]));
}
__device__ __forceinline__ void ldsm_x4(uint32_t* r, uint32_t a) {
    asm volatile("ldmatrix.sync.aligned.m8n8.x4.shared.b16 {%0,%1,%2,%3}, [%4];"
        : "=r"(r[0]), "=r"(r[1]), "=r"(r[2]), "=r"(r[3]) : "r"(a));
}
__device__ __forceinline__ void ldsm_x2(uint32_t* r, uint32_t a) {
    asm volatile("ldmatrix.sync.aligned.m8n8.x2.shared.b16 {%0,%1}, [%2];"
        : "=r"(r[0]), "=r"(r[1]) : "r"(a));
}
__device__ __forceinline__ void ldsm_x2t(uint32_t* r, uint32_t a) {
    asm volatile("ldmatrix.sync.aligned.m8n8.x2.trans.shared.b16 {%0,%1}, [%2];"
        : "=r"(r[0]), "=r"(r[1]) : "r"(a));
}
__device__ __forceinline__ uint32_t hpack2(float x, float y) {
    __half hx = __float2half_rn(x), hy = __float2half_rn(y);
    return ((uint32_t)__half_as_ushort(hy) << 16) | __half_as_ushort(hx);
}

// ---------------------------------------------------------------------------
// GEMM: C[M, Ntot] = A @ B^T + bias, single-pass fp16, fp32 accum.
// 3-stage TMA pipeline; B fragments via paired ldsm_x4 (2 n-tiles per instr).
// CTA 128x128, warptile 32x64, 2 CTAs/SM.
// ---------------------------------------------------------------------------
__global__ __launch_bounds__(256, 2) void gemm_f16(
    const __grid_constant__ CUtensorMap tA, const __grid_constant__ CUtensorMap tB,
    const float* __restrict__ bias, float* __restrict__ C, int Ntot)
{
    extern __shared__ __align__(1024) char gsm[];
    const uint32_t sb0  = smem_u32(gsm);
    const uint32_t ctrl = sb0;
    const uint32_t tile = sb0 + 1024;

    const int tid = threadIdx.x;
    const int m0  = blockIdx.x * GBM;
    const int n0  = blockIdx.y * GBN;

    const int wid  = tid >> 5, lane = tid & 31;
    const int wm   = wid & 3;        // 4 groups of 32 rows
    const int wn   = wid >> 2;       // 2 groups of 64 cols
    const int gid  = lane >> 2;
    const int tig  = lane & 3;
    const int l15  = lane & 15;

    const uint32_t a_row  = (uint32_t)(wm * 32 + l15);
    const uint32_t a_colh = (uint32_t)((lane >> 4) << 4);
    // B x4 lane mapping: groups 0..3 -> {nt,k0},{nt,k1},{nt+1,k0},{nt+1,k1}
    const uint32_t b_row4 = (uint32_t)(wn * 64 + (lane & 7) + ((lane >> 4) << 3));
    const uint32_t b_kh4  = (uint32_t)(((lane >> 3) & 1) << 4);

    if (tid == 0) {
        MBARRIER_INIT(ctrl, 1);
        MBARRIER_INIT(ctrl + 8, 1);
        MBARRIER_INIT(ctrl + 16, 1);
    }
    __syncthreads();

    auto issue = [&](int s, int k0) {
        const uint32_t st = tile + s * STB;
        MBARRIER_EXPECT_TX(ctrl + s * 8, STB);
        TMA_LOAD_2D(st,        &tA, k0, m0, ctrl + s * 8);
        TMA_LOAD_2D(st + A_PL, &tB, k0, n0, ctrl + s * 8);
    };

    float acc[2][8][4];
#pragma unroll
    for (int a = 0; a < 2; ++a)
#pragma unroll
        for (int b = 0; b < 8; ++b)
#pragma unroll
            for (int c = 0; c < 4; ++c) acc[a][b][c] = 0.0f;

    if (tid == 0) { issue(0, 0); issue(1, GBK); issue(2, 2 * GBK); }

    int s = 0, phase = 0;
    for (int it = 0; it < NCH; ++it) {
        MBARRIER_WAIT_PARITY(ctrl + s * 8, phase);
        const uint32_t ss = tile + s * STB;

#pragma unroll
        for (int ks = 0; ks < 4; ++ks) {
            const uint32_t kofs = (uint32_t)(ks * 32);

            uint32_t af[2][4];
#pragma unroll
            for (int mt = 0; mt < 2; ++mt) {
                const uint32_t r = a_row + mt * 16;
                const uint32_t c = (kofs + a_colh) ^ ((r & 7) * 16);
                ldsm_x4(af[mt], ss + r * 128 + c);
            }
            uint32_t bf[8][2];
#pragma unroll
            for (int p = 0; p < 4; ++p) {
                const uint32_t r = b_row4 + p * 16;
                const uint32_t c = (kofs + b_kh4) ^ ((r & 7) * 16);
                uint32_t q[4];
                ldsm_x4(q, ss + A_PL + r * 128 + c);
                bf[2 * p][0]     = q[0];
                bf[2 * p][1]     = q[1];
                bf[2 * p + 1][0] = q[2];
                bf[2 * p + 1][1] = q[3];
            }
#pragma unroll
            for (int mt = 0; mt < 2; ++mt)
#pragma unroll
                for (int nt = 0; nt < 8; ++nt)
                    mma_f16(acc[mt][nt], af[mt], bf[nt]);
        }
        __syncthreads();
        if (tid == 0 && it + 3 < NCH) issue(s, (it + 3) * GBK);
        if (++s == GSTG) { s = 0; phase ^= 1; }
    }

#pragma unroll
    for (int mt = 0; mt < 2; ++mt) {
#pragma unroll
        for (int nt = 0; nt < 8; ++nt) {
            const int row = m0 + wm * 32 + mt * 16 + gid;
            const int col = n0 + wn * 64 + nt * 8 + tig * 2;
            const float b0 = bias[col], b1 = bias[col + 1];
            float2 v0 = {acc[mt][nt][0] + b0, acc[mt][nt][1] + b1};
            float2 v1 = {acc[mt][nt][2] + b0, acc[mt][nt][3] + b1};
            *(float2*)(C + (size_t)row * Ntot + col)       = v0;
            *(float2*)(C + (size_t)(row + 8) * Ntot + col) = v1;
        }
    }
}

// ---------------------------------------------------------------------------
__global__ __launch_bounds__(256) void cvt_f16(
    const float4* __restrict__ in, uint2* __restrict__ out, int n4)
{
    const int i = blockIdx.x * 256 + threadIdx.x;
    if (i >= n4) return;
    float4 v = in[i];
    out[i] = make_uint2(hpack2(v.x, v.y), hpack2(v.z, v.w));
}

__global__ __launch_bounds__(256) void transpose_f16(
    const float* __restrict__ W, __half* __restrict__ Wt, int K, int N)
{
    __shared__ float t[32][33];
    const int n0 = blockIdx.x * 32, k0 = blockIdx.y * 32;
    const int tx = threadIdx.x, ty = threadIdx.y;
#pragma unroll
    for (int i = 0; i < 32; i += 8)
        t[ty + i][tx] = W[(size_t)(k0 + ty + i) * N + n0 + tx];
    __syncthreads();
#pragma unroll
    for (int i = 0; i < 32; i += 8)
        Wt[(size_t)(n0 + ty + i) * K + k0 + tx] = __float2half_rn(t[tx][ty + i]);
}

// ---------------------------------------------------------------------------
// RMSNorm + rotary; emits fp16 q (scaled by SCALEV*LOG2E), k, v planes.
// ---------------------------------------------------------------------------
__global__ __launch_bounds__(256) void rms_rope_h(
    const float* __restrict__ qkv,
    const float* __restrict__ gq, const float* __restrict__ gk,
    const float* __restrict__ fcos, const float* __restrict__ fsin,
    __half* __restrict__ qp, __half* __restrict__ kp, __half* __restrict__ vp)
{
    const int t   = blockIdx.x;
    const int l   = t & (SEQ - 1);
    const int tid = threadIdx.x;

    const float* qrow = qkv + (size_t)t * QKV_COLS;
    const float* krow = qrow + DIMN;
    const float* vrow = qrow + 2 * DIMN;

    float sq = 0.0f, sk = 0.0f;
    for (int i = tid; i < DIMN; i += 256) {
        float a = qrow[i]; sq = fmaf(a, a, sq);
        float b = krow[i]; sk = fmaf(b, b, sk);
    }
#pragma unroll
    for (int off = 16; off; off >>= 1) {
        sq += __shfl_xor_sync(0xffffffffu, sq, off);
        sk += __shfl_xor_sync(0xffffffffu, sk, off);
    }
    __shared__ float redq[8], redk[8];
    __shared__ float bq, bk;
    const int warp = tid >> 5, lane = tid & 31;
    if (lane == 0) { redq[warp] = sq; redk[warp] = sk; }
    __syncthreads();
    if (tid == 0) {
        float a = 0.0f, b = 0.0f;
#pragma unroll
        for (int w = 0; w < 8; ++w) { a += redq[w]; b += redk[w]; }
        bq = a; bk = b;
    }
    __syncthreads();
    const float rq = rsqrtf(bq * (1.0f / DIMN) + EPSV);
    const float rk = rsqrtf(bk * (1.0f / DIMN) + EPSV);
    const float qs = SCALEV * LOG2E;

    const size_t ob = (size_t)t * DIMN;
    for (int p = tid; p < DIMN / 2; p += 256) {
        const int head = p >> 6;
        const int i2   = (p & 63) * 2;
        const int ce   = head * HDIM + i2;
        const int co   = ce + 1;
        const float ccos = fcos[l * HDIM + i2];
        const float csin = fsin[l * HDIM + i2 + 1];

        float xe = qrow[ce] * rq * gq[ce];
        float xo = qrow[co] * rq * gq[co];
        *(uint32_t*)(qp + ob + ce) =
            hpack2((xe * ccos - xo * csin) * qs, (xe * csin + xo * ccos) * qs);

        xe = krow[ce] * rk * gk[ce];
        xo = krow[co] * rk * gk[co];
        *(uint32_t*)(kp + ob + ce) =
            hpack2(xe * ccos - xo * csin, xe * csin + xo * ccos);

        *(uint32_t*)(vp + ob + ce) = hpack2(vrow[ce], vrow[co]);
    }
}

// ---------------------------------------------------------------------------
// Flash attention, fp16. Br=64, Bc=64, D=128, 128 threads, 2 CTAs/SM.
// Softmax in base-2 (q pre-scaled by log2e). Q fragments in registers.
// ---------------------------------------------------------------------------
__global__ __launch_bounds__(128, 2) void flash_f16(
    const __half* __restrict__ qp, const __half* __restrict__ kp,
    const __half* __restrict__ vp, __half* __restrict__ op)
{
    extern __shared__ char fsm[];
    const uint32_t sb = smem_u32(fsm);

    const int qb = blockIdx.x, bh = blockIdx.y;
    const int b  = bh / NHEADS, h = bh % NHEADS;
    const int tid = threadIdx.x, wid = tid >> 5, lane = tid & 31;
    const int gid = lane >> 2, tig = lane & 3;
    const int l15 = lane & 15;
    const int hofs = h * HDIM;
    const size_t qrow0 = (size_t)(b * SEQ + qb * FBR);
    const size_t krow0 = (size_t)(b * SEQ);

    // Q: 64 rows x 16 chunks = 1024 cp16 (joins group 0)
    for (int i = 0; i < 8; ++i) {
        const int idx = tid + 128 * i;
        const int r   = idx >> 4;
        const int c   = idx & 15;
        cp16(sb + r * FROWB + c * 16, qp + (qrow0 + r) * DIMN + hofs + c * 8);
    }
    auto loadkv = [&](int s, int kb) {
        const uint32_t st = sb + FQ1 + s * FSTG;
        const size_t kr = krow0 + (size_t)kb * FBC;
        for (int i = 0; i < 16; ++i) {
            const int idx = tid + 128 * i;     // 0..2047
            const int pl  = idx >> 10;         // 0: K, 1: V
            const int r   = (idx >> 4) & 63;
            const int c   = idx & 15;
            const __half* base = pl ? vp : kp;
            cp16(st + pl * FKPL + r * FROWB + c * 16, base + (kr + r) * DIMN + hofs + c * 8);
        }
        cp_commit();
    };
    loadkv(0, 0);
    loadkv(1, 1);

    float oacc[16][4];
#pragma unroll
    for (int d = 0; d < 16; ++d)
#pragma unroll
        for (int c = 0; c < 4; ++c) oacc[d][c] = 0.0f;
    float mrow[2] = {-1e30f, -1e30f};
    float lrow[2] = {0.0f, 0.0f};

    const int qrow = wid * 16 + l15;
    const uint32_t qcol = ((lane >> 4) & 1) * 16;
    const int krw  = l15 & 7;
    const uint32_t kcadd = ((l15 >> 3) & 1) * 16;

    cp_wait1();
    __syncthreads();
    uint32_t qf[8][4];
#pragma unroll
    for (int kc = 0; kc < 8; ++kc)
        ldsm_x4(qf[kc], sb + qrow * FROWB + kc * 32 + qcol);

    for (int kb = 0; kb < SEQ / FBC; ++kb) {     // 16 steps
        if (kb) { cp_wait1(); __syncthreads(); }
        const uint32_t st = sb + FQ1 + (kb & 1) * FSTG;
        const uint32_t kh = st, vh = st + FKPL;

        // ---- S = Q K^T (8 n-tiles over Bc=64) ----
        float sacc[8][4];
#pragma unroll
        for (int nt = 0; nt < 8; ++nt)
#pragma unroll
            for (int c = 0; c < 4; ++c) sacc[nt][c] = 0.0f;

#pragma unroll
        for (int kc = 0; kc < 8; ++kc) {
            const uint32_t kcol = kc * 32 + kcadd;
#pragma unroll
            for (int nt = 0; nt < 8; ++nt) {
                uint32_t bk[2];
                ldsm_x2(bk, kh + (nt * 8 + krw) * FROWB + kcol);
                mma_f16(sacc[nt], qf[kc], bk);
            }
        }

        // ---- online softmax (base-2) ----
        float mx0 = sacc[0][0], mx1 = sacc[0][2];
#pragma unroll
        for (int nt = 0; nt < 8; ++nt) {
            mx0 = fmaxf(mx0, fmaxf(sacc[nt][0], sacc[nt][1]));
            mx1 = fmaxf(mx1, fmaxf(sacc[nt][2], sacc[nt][3]));
        }
        mx0 = fmaxf(mx0, __shfl_xor_sync(0xffffffffu, mx0, 1));
        mx0 = fmaxf(mx0, __shfl_xor_sync(0xffffffffu, mx0, 2));
        mx1 = fmaxf(mx1, __shfl_xor_sync(0xffffffffu, mx1, 1));
        mx1 = fmaxf(mx1, __shfl_xor_sync(0xffffffffu, mx1, 2));
        const float mn0 = fmaxf(mrow[0], mx0);
        const float mn1 = fmaxf(mrow[1], mx1);
        const float al0 = exp2f(mrow[0] - mn0);
        const float al1 = exp2f(mrow[1] - mn1);
        mrow[0] = mn0; mrow[1] = mn1;

        float rs0 = 0.0f, rs1 = 0.0f;
#pragma unroll
        for (int nt = 0; nt < 8; ++nt) {
            sacc[nt][0] = exp2f(sacc[nt][0] - mn0);
            sacc[nt][1] = exp2f(sacc[nt][1] - mn0);
            sacc[nt][2] = exp2f(sacc[nt][2] - mn1);
            sacc[nt][3] = exp2f(sacc[nt][3] - mn1);
            rs0 += sacc[nt][0] + sacc[nt][1];
            rs1 += sacc[nt][2] + sacc[nt][3];
        }
        rs0 += __shfl_xor_sync(0xffffffffu, rs0, 1);
        rs0 += __shfl_xor_sync(0xffffffffu, rs0, 2);
        rs1 += __shfl_xor_sync(0xffffffffu, rs1, 1);
        rs1 += __shfl_xor_sync(0xffffffffu, rs1, 2);
        lrow[0] = lrow[0] * al0 + rs0;
        lrow[1] = lrow[1] * al1 + rs1;
#pragma unroll
        for (int d = 0; d < 16; ++d) {
            oacc[d][0] *= al0; oacc[d][1] *= al0;
            oacc[d][2] *= al1; oacc[d][3] *= al1;
        }

        // ---- O += P V (4 k-steps over Bc=64) ----
#pragma unroll
        for (int kc2 = 0; kc2 < 4; ++kc2) {
            uint32_t ap[4];
            ap[0] = hpack2(sacc[2 * kc2][0],     sacc[2 * kc2][1]);
            ap[1] = hpack2(sacc[2 * kc2][2],     sacc[2 * kc2][3]);
            ap[2] = hpack2(sacc[2 * kc2 + 1][0], sacc[2 * kc2 + 1][1]);
            ap[3] = hpack2(sacc[2 * kc2 + 1][2], sacc[2 * kc2 + 1][3]);
            const uint32_t vr = (kc2 * 16 + l15) * FROWB;
#pragma unroll
            for (int dt = 0; dt < 16; ++dt) {
                uint32_t bv[2];
                ldsm_x2t(bv, vh + vr + dt * 16);
                mma_f16(oacc[dt], ap, bv);
            }
        }
        __syncthreads();
        if (kb + 2 < SEQ / FBC) loadkv(kb & 1, kb + 2);
    }

    // ---- epilogue ----
#pragma unroll
    for (int i = 0; i < 2; ++i) {
        const float inv = 1.0f / lrow[i];
        const size_t base =
            (qrow0 + (size_t)(wid * 16 + gid + i * 8)) * DIMN + hofs + tig * 2;
#pragma unroll
        for (int dt = 0; dt < 16; ++dt)
            *(uint32_t*)(op + base + dt * 8) =
                hpack2(oacc[dt][2 * i] * inv, oacc[dt][2 * i + 1] * inv);
    }
}

// ---------------------------------------------------------------------------
// Host side
// ---------------------------------------------------------------------------
typedef CUresult (CUDAAPI *EncodeTiledFn)(
    CUtensorMap*, CUtensorMapDataType, cuuint32_t, void*,
    const cuuint64_t*, const cuuint64_t*, const cuuint32_t*, const cuuint32_t*,
    CUtensorMapInterleave, CUtensorMapSwizzle, CUtensorMapL2promotion,
    CUtensorMapFloatOOBfill);

static void make_map_f16(EncodeTiledFn enc, CUtensorMap* m, const void* p,
                         unsigned long long d0, unsigned long long d1,
                         unsigned b0, unsigned b1)
{
    cuuint64_t dims[2]    = {d0, d1};
    cuuint64_t strides[1] = {d0 * 2};
    cuuint32_t box[2]     = {b0, b1};
    cuuint32_t es[2]      = {1, 1};
    enc(m, CU_TENSOR_MAP_DATA_TYPE_FLOAT16, 2, (void*)p, dims, strides, box, es,
        CU_TENSOR_MAP_INTERLEAVE_NONE, CU_TENSOR_MAP_SWIZZLE_128B,
        CU_TENSOR_MAP_L2_PROMOTION_L2_128B, CU_TENSOR_MAP_FLOAT_OOB_FILL_NONE);
}

extern "C" void kernel_launch(void* const* d_in, const int* in_sizes, int n_in,
                              void* d_out, int out_size)
{
    const float* X    = (const float*)d_in[0];
    const float* fcos = (const float*)d_in[1];
    const float* fsin = (const float*)d_in[2];
    const float* Wqkv = (const float*)d_in[3];
    const float* bqkv = (const float*)d_in[4];
    const float* gq   = (const float*)d_in[5];
    const float* gk   = (const float*)d_in[6];
    const float* Wout = (const float*)d_in[7];
    const float* bout = (const float*)d_in[8];
    float* out = (float*)d_out;

    float *qkvbuf;
    __half *xh, *ap, *wq, *wo, *qp, *kp, *vp;
    cudaGetSymbolAddress((void**)&qkvbuf, g_qkv);
    cudaGetSymbolAddress((void**)&xh, g_xh);
    cudaGetSymbolAddress((void**)&ap, g_a);
    cudaGetSymbolAddress((void**)&wq, g_wq);
    cudaGetSymbolAddress((void**)&wo, g_wo);
    cudaGetSymbolAddress((void**)&qp, g_q);
    cudaGetSymbolAddress((void**)&kp, g_k);
    cudaGetSymbolAddress((void**)&vp, g_v);

    EncodeTiledFn enc = nullptr;
    cudaDriverEntryPointQueryResult qr;
    cudaGetDriverEntryPoint("cuTensorMapEncodeTiled", (void**)&enc,
                            cudaEnableDefault, &qr);

    CUtensorMap tX, tWq, tA, tWo;
    make_map_f16(enc, &tX,  xh, DIMN, TOKENS,   GBK, GBM);
    make_map_f16(enc, &tWq, wq, DIMN, QKV_COLS, GBK, GBN);
    make_map_f16(enc, &tA,  ap, DIMN, TOKENS,   GBK, GBM);
    make_map_f16(enc, &tWo, wo, DIMN, DIMN,     GBK, GBN);

    cudaFuncSetAttribute(gemm_f16, cudaFuncAttributeMaxDynamicSharedMemorySize, GSMEM);
    cudaFuncSetAttribute(flash_f16, cudaFuncAttributeMaxDynamicSharedMemorySize, FSMEM);

    // 0) fp16 operands
    cvt_f16<<<(TOKENS * DIMN / 4 + 255) / 256, 256>>>(
        (const float4*)X, (uint2*)xh, TOKENS * DIMN / 4);
    transpose_f16<<<dim3(QKV_COLS / 32, DIMN / 32), dim3(32, 8)>>>(
        Wqkv, wq, DIMN, QKV_COLS);
    transpose_f16<<<dim3(DIMN / 32, DIMN / 32), dim3(32, 8)>>>(
        Wout, wo, DIMN, DIMN);

    // 1) qkv = X @ W_qkv + b_qkv
    gemm_f16<<<dim3(TOKENS / GBM, QKV_COLS / GBN), 256, GSMEM>>>(
        tX, tWq, bqkv, qkvbuf, QKV_COLS);

    // 2) RMSNorm + RoPE -> fp16 planes
    rms_rope_h<<<TOKENS, 256>>>(qkvbuf, gq, gk, fcos, fsin, qp, kp, vp);

    // 3) flash attention -> fp16 plane
    flash_f16<<<dim3(SEQ / FBR, BATCH * NHEADS), 128, FSMEM>>>(qp, kp, vp, ap);

    // 4) out = attn @ W_out + b_out
    gemm_f16<<<dim3(TOKENS / GBM, DIMN / GBN), 256, GSMEM>>>(
        tA, tWo, bout, out, DIMN);
}

// round 17
// speedup vs baseline: 10.6088x; 1.0052x over previous
#include <cuda.h>
#include <cuda_runtime.h>
#include <cuda_bf16.h>
#include <cuda_fp16.h>
#include <math.h>
#include <stdint.h>

// Problem constants
#define DIMN     5120
#define NHEADS   40
#define HDIM     128
#define BATCH    2
#define SEQ      1024
#define TOKENS   (BATCH * SEQ)        // 2048
#define QKV_COLS (3 * DIMN)           // 15360
#define EPSV     1e-6f
#define SCALEV   0.08838834764831845f // 128^-0.5
#define LOG2E    1.4426950408889634f

// GEMM tiling: CTA 128x128, 8 warps of 32x64, BK=64, 3-stage TMA, 2 CTAs/SM
// B loaded from natural [K,N] layout (two 64-col halves), fragments via ldsm.trans
#define GBM 128
#define GBN 128
#define GBK 64
#define A_PL (GBM * GBK * 2)              // 16384 B
#define B_HP (64 * GBK * 2)               // 8192 B per B half
#define STB  (A_PL + 2 * B_HP)            // 32768 per stage
#define GSTG 3
#define GSMEM (1024 + GSTG * STB)         // 99328 -> 2 CTAs/SM
#define NCH (DIMN / GBK)                  // 80

// Flash tiling: Br=64 (4 warps x m16), Bc=64, D=128, fp16, 2 CTAs/SM
#define FBR 64
#define FBC 64
#define FROWB 272                          // 128 fp16 + 16B pad
#define FQ1  (FBR * FROWB)                 // 17408
#define FKPL (FBC * FROWB)                 // 17408
#define FSTG (2 * FKPL)                    // 34816 (k, v)
#define FSMEM (FQ1 + 2 * FSTG)             // 87040 -> 2 CTAs/SM

// Scratch (no allocations allowed)
__device__ float   g_qkv[(size_t)TOKENS * QKV_COLS];
__device__ __half  g_xh[(size_t)TOKENS * DIMN];
__device__ __half  g_a[(size_t)TOKENS * DIMN];
__device__ __half  g_wq[(size_t)DIMN * QKV_COLS];   // fp16 copy of W_qkv [K,N]
__device__ __half  g_wo[(size_t)DIMN * DIMN];       // fp16 copy of W_out [K,N]
__device__ __half  g_q[(size_t)TOKENS * DIMN];
__device__ __half  g_k[(size_t)TOKENS * DIMN];
__device__ __half  g_v[(size_t)TOKENS * DIMN];

// ---------------------------------------------------------------------------
__device__ __forceinline__ uint32_t smem_u32(const void* p) {
    uint32_t a;
    asm("{ .reg .u64 t; cvta.to.shared.u64 t, %1; cvt.u32.u64 %0, t; }" : "=r"(a) : "l"(p));
    return a;
}
__device__ __forceinline__ void cp16(uint32_t s, const void* g) {
    asm volatile("cp.async.cg.shared.global [%0], [%1], 16;" :: "r"(s), "l"(g));
}
__device__ __forceinline__ void cp_commit() {
    asm volatile("cp.async.commit_group;" ::: "memory");
}
__device__ __forceinline__ void cp_wait1() {
    asm volatile("cp.async.wait_group 1;" ::: "memory");
}
#define MBARRIER_INIT(addr, cnt) \
    asm volatile("mbarrier.init.shared.b64 [%0], %1;" :: "r"(addr), "r"(cnt) : "memory")
#define MBARRIER_EXPECT_TX(addr, bytes) \
    asm volatile("mbarrier.arrive.expect_tx.shared.b64 _, [%0], %1;" :: "r"(addr), "r"(bytes) : "memory")
#define MBARRIER_WAIT_PARITY(addr, parity) do { \
    uint32_t _m = (addr); uint32_t _p = (parity); uint32_t _d; \
    asm volatile("{\n\t.reg .pred p;\n\t" \
        "mbarrier.try_wait.parity.acquire.cta.shared::cta.b64 p, [%1], %2;\n\t" \
        "selp.b32 %0, 1, 0, p;\n\t}" : "=r"(_d) : "r"(_m), "r"(_p) : "memory"); \
    if (!_d) { \
        asm volatile("{\n\t.reg .pred P1;\n\t" \
            "WL_%=:\n\t" \
            "mbarrier.try_wait.parity.acquire.cta.shared::cta.b64 P1, [%0], %1, 0x989680;\n\t" \
            "@P1 bra.uni WD_%=;\n\t" \
            "bra.uni WL_%=;\n\t" \
            "WD_%=:\n\t}" :: "r"(_m), "r"(_p) : "memory"); \
    } \
} while (0)
#define TMA_LOAD_2D(saddr, tmap, cx, cy, mbar) \
    asm volatile("cp.async.bulk.tensor.2d.shared::cta.global.tile.mbarrier::complete_tx::bytes " \
                 "[%0], [%1, {%2, %3}], [%4];" \
                 :: "r"(saddr), "l"(tmap), "r"(cx), "r"(cy), "r"(mbar) : "memory")

__device__ __forceinline__ void mma_f16(float* c, const uint32_t* a, const uint32_t* b) {
    asm volatile("mma.sync.aligned.m16n8k16.row.col.f32.f16.f16.f32 "
        "{%0,%1,%2,%3}, {%4,%5,%6,%7}, {%8,%9}, {%0,%1,%2,%3};"
        : "+f"(c[0]), "+f"(c[1]), "+f"(c[2]), "+f"(c[3])
        : "r"(a[0]), "r"(a[1]), "r"(a[2]), "r"(a[3]), "r"(b[0]), "r"(b[1]));
}
__device__ __forceinline__ void ldsm_x4(uint32_t* r, uint32_t a) {
    asm volatile("ldmatrix.sync.aligned.m8n8.x4.shared.b16 {%0,%1,%2,%3}, [%4];"
        : "=r"(r[0]), "=r"(r[1]), "=r"(r[2]), "=r"(r[3]) : "r"(a));
}
__device__ __forceinline__ void ldsm_x4t(uint32_t* r, uint32_t a) {
    asm volatile("ldmatrix.sync.aligned.m8n8.x4.trans.shared.b16 {%0,%1,%2,%3}, [%4];"
        : "=r"(r[0]), "=r"(r[1]), "=r"(r[2]), "=r"(r[3]) : "r"(a));
}
__device__ __forceinline__ uint32_t hpack2(float x, float y) {
    __half hx = __float2half_rn(x), hy = __float2half_rn(y);
    return ((uint32_t)__half_as_ushort(hy) << 16) | __half_as_ushort(hx);
}

// ---------------------------------------------------------------------------
// GEMM: C[M, Ntot] = A @ B + bias.  A: [M,K] K-major.  B: [K,Ntot] N-major.
// A fragments: ldsm_x4 (row).  B fragments: paired ldsm_x4.trans.
// CTA 128x128, warptile 32x64, 3-stage TMA, 2 CTAs/SM.
// ---------------------------------------------------------------------------
__global__ __launch_bounds__(256, 2) void gemm_f16(
    const __grid_constant__ CUtensorMap tA, const __grid_constant__ CUtensorMap tB,
    const float* __restrict__ bias, float* __restrict__ C, int Ntot)
{
    extern __shared__ __align__(1024) char gsm[];
    const uint32_t sb0  = smem_u32(gsm);
    const uint32_t ctrl = sb0;
    const uint32_t tile = sb0 + 1024;

    const int tid = threadIdx.x;
    const int m0  = blockIdx.x * GBM;
    const int n0  = blockIdx.y * GBN;

    const int wid  = tid >> 5, lane = tid & 31;
    const int wm   = wid & 3;        // 4 groups of 32 rows
    const int wn   = wid >> 2;       // 2 groups of 64 cols (one B half each)
    const int gid  = lane >> 2;
    const int tig  = lane & 3;
    const int l15  = lane & 15;

    const uint32_t a_row  = (uint32_t)(wm * 32 + l15);
    const uint32_t a_colh = (uint32_t)((lane >> 4) << 4);
    // B trans x4: lanes 0-15 -> 16 k-rows at n-tile 2p, lanes 16-31 -> 2p+1
    const uint32_t b_krow = (uint32_t)l15;            // + ks*16
    const uint32_t b_nadd = (uint32_t)((lane >> 4) << 4);  // +16B for second n-tile

    if (tid == 0) {
        MBARRIER_INIT(ctrl, 1);
        MBARRIER_INIT(ctrl + 8, 1);
        MBARRIER_INIT(ctrl + 16, 1);
    }
    __syncthreads();

    auto issue = [&](int s, int k0) {
        const uint32_t st = tile + s * STB;
        MBARRIER_EXPECT_TX(ctrl + s * 8, STB);
        TMA_LOAD_2D(st,               &tA, k0, m0,      ctrl + s * 8);
        TMA_LOAD_2D(st + A_PL,        &tB, n0,      k0, ctrl + s * 8);
        TMA_LOAD_2D(st + A_PL + B_HP, &tB, n0 + 64, k0, ctrl + s * 8);
    };

    float acc[2][8][4];
#pragma unroll
    for (int a = 0; a < 2; ++a)
#pragma unroll
        for (int b = 0; b < 8; ++b)
#pragma unroll
            for (int c = 0; c < 4; ++c) acc[a][b][c] = 0.0f;

    if (tid == 0) { issue(0, 0); issue(1, GBK); issue(2, 2 * GBK); }

    const uint32_t bhalf_ofs = A_PL + (uint32_t)wn * B_HP;   // this warp's B half

    int s = 0, phase = 0;
    for (int it = 0; it < NCH; ++it) {
        MBARRIER_WAIT_PARITY(ctrl + s * 8, phase);
        const uint32_t ss = tile + s * STB;

#pragma unroll
        for (int ks = 0; ks < 4; ++ks) {
            const uint32_t kofs = (uint32_t)(ks * 32);

            uint32_t af[2][4];
#pragma unroll
            for (int mt = 0; mt < 2; ++mt) {
                const uint32_t r = a_row + mt * 16;
                const uint32_t c = (kofs + a_colh) ^ ((r & 7) * 16);
                ldsm_x4(af[mt], ss + r * 128 + c);
            }
            // B: 4 paired trans loads cover 8 n-tiles for this ks (k=ks*16..+16)
            uint32_t bf[8][2];
#pragma unroll
            for (int p = 0; p < 4; ++p) {
                const uint32_t r = ks * 16 + b_krow;           // k row in half-tile
                const uint32_t c = (p * 32 + b_nadd) ^ ((r & 7) * 16);
                uint32_t q[4];
                ldsm_x4t(q, ss + bhalf_ofs + r * 128 + c);
                bf[2 * p][0]     = q[0];
                bf[2 * p][1]     = q[1];
                bf[2 * p + 1][0] = q[2];
                bf[2 * p + 1][1] = q[3];
            }
#pragma unroll
            for (int mt = 0; mt < 2; ++mt)
#pragma unroll
                for (int nt = 0; nt < 8; ++nt)
                    mma_f16(acc[mt][nt], af[mt], bf[nt]);
        }
        __syncthreads();
        if (tid == 0 && it + 3 < NCH) issue(s, (it + 3) * GBK);
        if (++s == GSTG) { s = 0; phase ^= 1; }
    }

#pragma unroll
    for (int mt = 0; mt < 2; ++mt) {
#pragma unroll
        for (int nt = 0; nt < 8; ++nt) {
            const int row = m0 + wm * 32 + mt * 16 + gid;
            const int col = n0 + wn * 64 + nt * 8 + tig * 2;
            const float b0 = bias[col], b1 = bias[col + 1];
            float2 v0 = {acc[mt][nt][0] + b0, acc[mt][nt][1] + b1};
            float2 v1 = {acc[mt][nt][2] + b0, acc[mt][nt][3] + b1};
            *(float2*)(C + (size_t)row * Ntot + col)       = v0;
            *(float2*)(C + (size_t)(row + 8) * Ntot + col) = v1;
        }
    }
}

// ---------------------------------------------------------------------------
__global__ __launch_bounds__(256) void cvt_f16(
    const float4* __restrict__ in, uint2* __restrict__ out, int n4)
{
    const int i = blockIdx.x * 256 + threadIdx.x;
    if (i >= n4) return;
    float4 v = in[i];
    out[i] = make_uint2(hpack2(v.x, v.y), hpack2(v.z, v.w));
}

// ---------------------------------------------------------------------------
// RMSNorm + rotary; emits fp16 q (scaled by SCALEV*LOG2E), k, v planes.
// ---------------------------------------------------------------------------
__global__ __launch_bounds__(256) void rms_rope_h(
    const float* __restrict__ qkv,
    const float* __restrict__ gq, const float* __restrict__ gk,
    const float* __restrict__ fcos, const float* __restrict__ fsin,
    __half* __restrict__ qp, __half* __restrict__ kp, __half* __restrict__ vp)
{
    const int t   = blockIdx.x;
    const int l   = t & (SEQ - 1);
    const int tid = threadIdx.x;

    const float* qrow = qkv + (size_t)t * QKV_COLS;
    const float* krow = qrow + DIMN;
    const float* vrow = qrow + 2 * DIMN;

    float sq = 0.0f, sk = 0.0f;
    for (int i = tid; i < DIMN; i += 256) {
        float a = qrow[i]; sq = fmaf(a, a, sq);
        float b = krow[i]; sk = fmaf(b, b, sk);
    }
#pragma unroll
    for (int off = 16; off; off >>= 1) {
        sq += __shfl_xor_sync(0xffffffffu, sq, off);
        sk += __shfl_xor_sync(0xffffffffu, sk, off);
    }
    __shared__ float redq[8], redk[8];
    __shared__ float bq, bk;
    const int warp = tid >> 5, lane = tid & 31;
    if (lane == 0) { redq[warp] = sq; redk[warp] = sk; }
    __syncthreads();
    if (tid == 0) {
        float a = 0.0f, b = 0.0f;
#pragma unroll
        for (int w = 0; w < 8; ++w) { a += redq[w]; b += redk[w]; }
        bq = a; bk = b;
    }
    __syncthreads();
    const float rq = rsqrtf(bq * (1.0f / DIMN) + EPSV);
    const float rk = rsqrtf(bk * (1.0f / DIMN) + EPSV);
    const float qs = SCALEV * LOG2E;

    const size_t ob = (size_t)t * DIMN;
    for (int p = tid; p < DIMN / 2; p += 256) {
        const int head = p >> 6;
        const int i2   = (p & 63) * 2;
        const int ce   = head * HDIM + i2;
        const int co   = ce + 1;
        const float ccos = fcos[l * HDIM + i2];
        const float csin = fsin[l * HDIM + i2 + 1];

        float xe = qrow[ce] * rq * gq[ce];
        float xo = qrow[co] * rq * gq[co];
        *(uint32_t*)(qp + ob + ce) =
            hpack2((xe * ccos - xo * csin) * qs, (xe * csin + xo * ccos) * qs);

        xe = krow[ce] * rk * gk[ce];
        xo = krow[co] * rk * gk[co];
        *(uint32_t*)(kp + ob + ce) =
            hpack2(xe * ccos - xo * csin, xe * csin + xo * ccos);

        *(uint32_t*)(vp + ob + ce) = hpack2(vrow[ce], vrow[co]);
    }
}

// ---------------------------------------------------------------------------
// Flash attention, fp16. Br=64, Bc=64, D=128, 128 threads, 2 CTAs/SM.
// K and V fragment loads paired into ldsm_x4 / ldsm_x4.trans.
// ---------------------------------------------------------------------------
__global__ __launch_bounds__(128, 2) void flash_f16(
    const __half* __restrict__ qp, const __half* __restrict__ kp,
    const __half* __restrict__ vp, __half* __restrict__ op)
{
    extern __shared__ char fsm[];
    const uint32_t sb = smem_u32(fsm);

    const int qb = blockIdx.x, bh = blockIdx.y;
    const int b  = bh / NHEADS, h = bh % NHEADS;
    const int tid = threadIdx.x, wid = tid >> 5, lane = tid & 31;
    const int gid = lane >> 2, tig = lane & 3;
    const int l15 = lane & 15;
    const int hofs = h * HDIM;
    const size_t qrow0 = (size_t)(b * SEQ + qb * FBR);
    const size_t krow0 = (size_t)(b * SEQ);

    for (int i = 0; i < 8; ++i) {
        const int idx = tid + 128 * i;
        const int r   = idx >> 4;
        const int c   = idx & 15;
        cp16(sb + r * FROWB + c * 16, qp + (qrow0 + r) * DIMN + hofs + c * 8);
    }
    auto loadkv = [&](int s, int kb) {
        const uint32_t st = sb + FQ1 + s * FSTG;
        const size_t kr = krow0 + (size_t)kb * FBC;
        for (int i = 0; i < 16; ++i) {
            const int idx = tid + 128 * i;
            const int pl  = idx >> 10;
            const int r   = (idx >> 4) & 63;
            const int c   = idx & 15;
            const __half* base = pl ? vp : kp;
            cp16(st + pl * FKPL + r * FROWB + c * 16, base + (kr + r) * DIMN + hofs + c * 8);
        }
        cp_commit();
    };
    loadkv(0, 0);
    loadkv(1, 1);

    float oacc[16][4];
#pragma unroll
    for (int d = 0; d < 16; ++d)
#pragma unroll
        for (int c = 0; c < 4; ++c) oacc[d][c] = 0.0f;
    float mrow[2] = {-1e30f, -1e30f};
    float lrow[2] = {0.0f, 0.0f};

    const int qrow = wid * 16 + l15;
    const uint32_t qcol = ((lane >> 4) & 1) * 16;
    // K x4 pairing (non-trans): lanes 0-15 -> n-tile 2p, 16-31 -> 2p+1
    const uint32_t k_row4 = (uint32_t)((lane & 7) + ((lane >> 4) << 3));
    const uint32_t k_kh   = (uint32_t)(((lane >> 3) & 1) << 4);
    // V x4 pairing (trans): lanes 0-15 -> 16 k-rows at dt=2p, 16-31 -> 2p+1
    const uint32_t v_nadd = (uint32_t)((lane >> 4) << 4);

    cp_wait1();
    __syncthreads();
    uint32_t qf[8][4];
#pragma unroll
    for (int kc = 0; kc < 8; ++kc)
        ldsm_x4(qf[kc], sb + qrow * FROWB + kc * 32 + qcol);

    for (int kb = 0; kb < SEQ / FBC; ++kb) {
        if (kb) { cp_wait1(); __syncthreads(); }
        const uint32_t st = sb + FQ1 + (kb & 1) * FSTG;
        const uint32_t kh = st, vh = st + FKPL;

        // ---- S = Q K^T (8 n-tiles, paired K loads) ----
        float sacc[8][4];
#pragma unroll
        for (int nt = 0; nt < 8; ++nt)
#pragma unroll
            for (int c = 0; c < 4; ++c) sacc[nt][c] = 0.0f;

#pragma unroll
        for (int kc = 0; kc < 8; ++kc) {
            const uint32_t kcol = kc * 32 + k_kh;
#pragma unroll
            for (int p = 0; p < 4; ++p) {
                uint32_t q[4];
                ldsm_x4(q, kh + (p * 16 + k_row4) * FROWB + kcol);
                uint32_t bk0[2] = {q[0], q[1]};
                uint32_t bk1[2] = {q[2], q[3]};
                mma_f16(sacc[2 * p],     qf[kc], bk0);
                mma_f16(sacc[2 * p + 1], qf[kc], bk1);
            }
        }

        // ---- online softmax (base-2) ----
        float mx0 = sacc[0][0], mx1 = sacc[0][2];
#pragma unroll
        for (int nt = 0; nt < 8; ++nt) {
            mx0 = fmaxf(mx0, fmaxf(sacc[nt][0], sacc[nt][1]));
            mx1 = fmaxf(mx1, fmaxf(sacc[nt][2], sacc[nt][3]));
        }
        mx0 = fmaxf(mx0, __shfl_xor_sync(0xffffffffu, mx0, 1));
        mx0 = fmaxf(mx0, __shfl_xor_sync(0xffffffffu, mx0, 2));
        mx1 = fmaxf(mx1, __shfl_xor_sync(0xffffffffu, mx1, 1));
        mx1 = fmaxf(mx1, __shfl_xor_sync(0xffffffffu, mx1, 2));
        const float mn0 = fmaxf(mrow[0], mx0);
        const float mn1 = fmaxf(mrow[1], mx1);
        const float al0 = exp2f(mrow[0] - mn0);
        const float al1 = exp2f(mrow[1] - mn1);
        mrow[0] = mn0; mrow[1] = mn1;

        float rs0 = 0.0f, rs1 = 0.0f;
#pragma unroll
        for (int nt = 0; nt < 8; ++nt) {
            sacc[nt][0] = exp2f(sacc[nt][0] - mn0);
            sacc[nt][1] = exp2f(sacc[nt][1] - mn0);
            sacc[nt][2] = exp2f(sacc[nt][2] - mn1);
            sacc[nt][3] = exp2f(sacc[nt][3] - mn1);
            rs0 += sacc[nt][0] + sacc[nt][1];
            rs1 += sacc[nt][2] + sacc[nt][3];
        }
        rs0 += __shfl_xor_sync(0xffffffffu, rs0, 1);
        rs0 += __shfl_xor_sync(0xffffffffu, rs0, 2);
        rs1 += __shfl_xor_sync(0xffffffffu, rs1, 1);
        rs1 += __shfl_xor_sync(0xffffffffu, rs1, 2);
        lrow[0] = lrow[0] * al0 + rs0;
        lrow[1] = lrow[1] * al1 + rs1;
#pragma unroll
        for (int d = 0; d < 16; ++d) {
            oacc[d][0] *= al0; oacc[d][1] *= al0;
            oacc[d][2] *= al1; oacc[d][3] *= al1;
        }

        // ---- O += P V (paired trans V loads) ----
#pragma unroll
        for (int kc2 = 0; kc2 < 4; ++kc2) {
            uint32_t ap[4];
            ap[0] = hpack2(sacc[2 * kc2][0],     sacc[2 * kc2][1]);
            ap[1] = hpack2(sacc[2 * kc2][2],     sacc[2 * kc2][3]);
            ap[2] = hpack2(sacc[2 * kc2 + 1][0], sacc[2 * kc2 + 1][1]);
            ap[3] = hpack2(sacc[2 * kc2 + 1][2], sacc[2 * kc2 + 1][3]);
            const uint32_t vr = (kc2 * 16 + l15) * FROWB;
#pragma unroll
            for (int p = 0; p < 8; ++p) {
                uint32_t q[4];
                ldsm_x4t(q, vh + vr + p * 32 + v_nadd);
                uint32_t bv0[2] = {q[0], q[1]};
                uint32_t bv1[2] = {q[2], q[3]};
                mma_f16(oacc[2 * p],     ap, bv0);
                mma_f16(oacc[2 * p + 1], ap, bv1);
            }
        }
        __syncthreads();
        if (kb + 2 < SEQ / FBC) loadkv(kb & 1, kb + 2);
    }

    // ---- epilogue ----
#pragma unroll
    for (int i = 0; i < 2; ++i) {
        const float inv = 1.0f / lrow[i];
        const size_t base =
            (qrow0 + (size_t)(wid * 16 + gid + i * 8)) * DIMN + hofs + tig * 2;
#pragma unroll
        for (int dt = 0; dt < 16; ++dt)
            *(uint32_t*)(op + base + dt * 8) =
                hpack2(oacc[dt][2 * i] * inv, oacc[dt][2 * i + 1] * inv);
    }
}

// ---------------------------------------------------------------------------
// Host side
// ---------------------------------------------------------------------------
typedef CUresult (CUDAAPI *EncodeTiledFn)(
    CUtensorMap*, CUtensorMapDataType, cuuint32_t, void*,
    const cuuint64_t*, const cuuint64_t*, const cuuint32_t*, const cuuint32_t*,
    CUtensorMapInterleave, CUtensorMapSwizzle, CUtensorMapL2promotion,
    CUtensorMapFloatOOBfill);

static void make_map_f16(EncodeTiledFn enc, CUtensorMap* m, const void* p,
                         unsigned long long d0, unsigned long long d1,
                         unsigned b0, unsigned b1)
{
    cuuint64_t dims[2]    = {d0, d1};
    cuuint64_t strides[1] = {d0 * 2};
    cuuint32_t box[2]     = {b0, b1};
    cuuint32_t es[2]      = {1, 1};
    enc(m, CU_TENSOR_MAP_DATA_TYPE_FLOAT16, 2, (void*)p, dims, strides, box, es,
        CU_TENSOR_MAP_INTERLEAVE_NONE, CU_TENSOR_MAP_SWIZZLE_128B,
        CU_TENSOR_MAP_L2_PROMOTION_L2_128B, CU_TENSOR_MAP_FLOAT_OOB_FILL_NONE);
}

extern "C" void kernel_launch(void* const* d_in, const int* in_sizes, int n_in,
                              void* d_out, int out_size)
{
    const float* X    = (const float*)d_in[0];
    const float* fcos = (const float*)d_in[1];
    const float* fsin = (const float*)d_in[2];
    const float* Wqkv = (const float*)d_in[3];
    const float* bqkv = (const float*)d_in[4];
    const float* gq   = (const float*)d_in[5];
    const float* gk   = (const float*)d_in[6];
    const float* Wout = (const float*)d_in[7];
    const float* bout = (const float*)d_in[8];
    float* out = (float*)d_out;

    float *qkvbuf;
    __half *xh, *ap, *wq, *wo, *qp, *kp, *vp;
    cudaGetSymbolAddress((void**)&qkvbuf, g_qkv);
    cudaGetSymbolAddress((void**)&xh, g_xh);
    cudaGetSymbolAddress((void**)&ap, g_a);
    cudaGetSymbolAddress((void**)&wq, g_wq);
    cudaGetSymbolAddress((void**)&wo, g_wo);
    cudaGetSymbolAddress((void**)&qp, g_q);
    cudaGetSymbolAddress((void**)&kp, g_k);
    cudaGetSymbolAddress((void**)&vp, g_v);

    EncodeTiledFn enc = nullptr;
    cudaDriverEntryPointQueryResult qr;
    cudaGetDriverEntryPoint("cuTensorMapEncodeTiled", (void**)&enc,
                            cudaEnableDefault, &qr);

    CUtensorMap tX, tWq, tA, tWo;
    // A maps: [K contig, M rows], box {GBK, GBM}
    make_map_f16(enc, &tX, xh, DIMN, TOKENS, GBK, GBM);
    make_map_f16(enc, &tA, ap, DIMN, TOKENS, GBK, GBM);
    // B maps: natural [N contig, K rows], box {64, GBK}
    make_map_f16(enc, &tWq, wq, QKV_COLS, DIMN, 64, GBK);
    make_map_f16(enc, &tWo, wo, DIMN,     DIMN, 64, GBK);

    cudaFuncSetAttribute(gemm_f16, cudaFuncAttributeMaxDynamicSharedMemorySize, GSMEM);
    cudaFuncSetAttribute(flash_f16, cudaFuncAttributeMaxDynamicSharedMemorySize, FSMEM);

    // 0) fp16 operands (elementwise, no transpose)
    cvt_f16<<<(TOKENS * DIMN / 4 + 255) / 256, 256>>>(
        (const float4*)X, (uint2*)xh, TOKENS * DIMN / 4);
    cvt_f16<<<((int)((size_t)DIMN * QKV_COLS / 4) + 255) / 256, 256>>>(
        (const float4*)Wqkv, (uint2*)wq, (int)((size_t)DIMN * QKV_COLS / 4));
    cvt_f16<<<(DIMN * DIMN / 4 + 255) / 256, 256>>>(
        (const float4*)Wout, (uint2*)wo, DIMN * DIMN / 4);

    // 1) qkv = X @ W_qkv + b_qkv
    gemm_f16<<<dim3(TOKENS / GBM, QKV_COLS / GBN), 256, GSMEM>>>(
        tX, tWq, bqkv, qkvbuf, QKV_COLS);

    // 2) RMSNorm + RoPE -> fp16 planes
    rms_rope_h<<<TOKENS, 256>>>(qkvbuf, gq, gk, fcos, fsin, qp, kp, vp);

    // 3) flash attention -> fp16 plane
    flash_f16<<<dim3(SEQ / FBR, BATCH * NHEADS), 128, FSMEM>>>(qp, kp, vp, ap);

    // 4) out = attn @ W_out + b_out
    gemm_f16<<<dim3(TOKENS / GBM, DIMN / GBN), 256, GSMEM>>>(
        tA, tWo, bout, out, DIMN);
}